// round 11
// baseline (speedup 1.0000x reference)
#include <cuda_runtime.h>
#include <cuda_bf16.h>
#include <math.h>
#include <stdint.h>
#include <cstdint>

#define CB 2
#define CS 1024
#define CD 1024
#define CH 16
#define CHD 64
#define CKD 256
#define CTOPK 10
#define CM 2048
#define CBH 32

__device__ float g_v[2097152];
__device__ float g_scores[33554432];
__device__ float g_attn[2097152];
__device__ float g_merge[2097152];
__device__ float g_eo[2097152];
__device__ float g_t1[4194304];
__device__ float g_qphi[8388608];
__device__ float g_kpsi[8388608];
__device__ float g_kv[524288];
__device__ float g_ksum[8192];
__device__ float g_h1[1048576];
__device__ float g_h2[524288];
__device__ float g_p1[8192];
__device__ float g_p2[4096];
__device__ float g_imp[2048];
__device__ float g_mask[2048];

__device__ __nv_bfloat16 qkvb_h[6291456], qkvb_l[6291456];
__device__ __nv_bfloat16 xb_h[2097152], xb_l[2097152];
__device__ __nv_bfloat16 cv_h[2097152], cv_l[2097152];
__device__ __nv_bfloat16 xc_h[2097152], xc_l[2097152];
__device__ __nv_bfloat16 ao_h[2097152], ao_l[2097152];
__device__ __nv_bfloat16 mg_h[2097152], mg_l[2097152];
__device__ __nv_bfloat16 eo_h[2097152], eo_l[2097152];
__device__ __nv_bfloat16 t1_h[4194304], t1_l[4194304];
__device__ __nv_bfloat16 wq_h[16777216], wq_l[16777216];
__device__ __nv_bfloat16 s1_h[8388608], s1_l[8388608];
__device__ __nv_bfloat16 s2_h[8388608], s2_l[8388608];
__device__ __nv_bfloat16 fw_h[2097152], fw_l[2097152];
__device__ __nv_bfloat16 cw_h[1048576], cw_l[1048576];
__device__ __nv_bfloat16 r1_h[524288], r1_l[524288];
__device__ __nv_bfloat16 r2_h[1048576], r2_l[1048576];
__device__ __nv_bfloat16 ph_h[16384], ph_l[16384];
__device__ __nv_bfloat16 ps_h[16384], ps_l[16384];
__device__ __nv_bfloat16 vt_h[2097152], vt_l[2097152];
__device__ __nv_bfloat16 pb_h[33554432], pb_l[33554432];

__device__ __forceinline__ float gelu_f(float v) {
    float c = 0.7978845608028654f * (v + 0.044715f * v * v * v);
    return 0.5f * v * (1.f + tanhf(c));
}

__device__ __forceinline__ float brs(float v) {
    __shared__ float sh[32];
    __syncthreads();
    int lane = threadIdx.x & 31;
    int wd = threadIdx.x >> 5;
#pragma unroll
    for (int o = 16; o > 0; o >>= 1) v += __shfl_xor_sync(0xffffffffu, v, o);
    if (lane == 0) sh[wd] = v;
    __syncthreads();
    int nw = (blockDim.x + 31) >> 5;
    v = (threadIdx.x < nw) ? sh[threadIdx.x] : 0.f;
    if (wd == 0) {
#pragma unroll
        for (int o = 16; o > 0; o >>= 1) v += __shfl_xor_sync(0xffffffffu, v, o);
        if (lane == 0) sh[0] = v;
    }
    __syncthreads();
    return sh[0];
}

__device__ __forceinline__ float brm(float v) {
    __shared__ float sh[32];
    __syncthreads();
    int lane = threadIdx.x & 31;
    int wd = threadIdx.x >> 5;
#pragma unroll
    for (int o = 16; o > 0; o >>= 1) v = fmaxf(v, __shfl_xor_sync(0xffffffffu, v, o));
    if (lane == 0) sh[wd] = v;
    __syncthreads();
    int nw = (blockDim.x + 31) >> 5;
    v = (threadIdx.x < nw) ? sh[threadIdx.x] : -3.4e38f;
    if (wd == 0) {
#pragma unroll
        for (int o = 16; o > 0; o >>= 1) v = fmaxf(v, __shfl_xor_sync(0xffffffffu, v, o));
        if (lane == 0) sh[0] = v;
    }
    __syncthreads();
    return sh[0];
}

__device__ __forceinline__ void mma16816(float* d, const uint32_t* a, const uint32_t* b) {
    asm volatile(
        "mma.sync.aligned.m16n8k16.row.col.f32.bf16.bf16.f32 "
        "{%0, %1, %2, %3}, {%4, %5, %6, %7}, {%8, %9}, {%0, %1, %2, %3};"
        : "+f"(d[0]), "+f"(d[1]), "+f"(d[2]), "+f"(d[3])
        : "r"(a[0]), "r"(a[1]), "r"(a[2]), "r"(a[3]), "r"(b[0]), "r"(b[1]));
}

__device__ __forceinline__ uint32_t s2u(const void* p) {
    uint32_t a;
    asm("{ .reg .u64 t; cvta.to.shared.u64 t, %1; cvt.u32.u64 %0, t; }" : "=r"(a) : "l"(p));
    return a;
}

__device__ __forceinline__ void split_st(__nv_bfloat16* h, __nv_bfloat16* l, size_t idx,
                                         float v) {
    __nv_bfloat16 a = __float2bfloat16(v);
    h[idx] = a;
    l[idx] = __float2bfloat16(v - __bfloat162float(a));
}

#define SROW 56
#define TILE_B 14336
#define BUF_B 57344
#define TG_SMEM 114688

__device__ __forceinline__ void tg_issue(const __nv_bfloat16* A0, const __nv_bfloat16* A1,
                                         const __nv_bfloat16* B0, const __nv_bfloat16* B1,
                                         int m0, int n0, int K, int M, int N, int ch,
                                         uint32_t sbase, int tid) {
    const __nv_bfloat16* srcs[4] = {A0, A1, B0, B1};
    uint32_t dbase = sbase + (uint32_t)(ch & 1) * BUF_B;
#pragma unroll
    for (int t = 0; t < 4; t++) {
        const __nv_bfloat16* src = srcs[t];
        int r0 = (t < 2) ? m0 : n0;
        int lim = (t < 2) ? M : N;
#pragma unroll
        for (int it = 0; it < 2; it++) {
            int u = tid + it * 256;
            int row = u >> 2;
            int c = u & 3;
            int gr = r0 + row;
            if (gr >= lim) gr = lim - 1;
            const void* gp = src + (size_t)gr * K + ch * 32 + c * 8;
            uint32_t dst = dbase + (uint32_t)(t * TILE_B + row * 112 + c * 16);
            asm volatile("cp.async.cg.shared.global [%0], [%1], 16;"
                         :: "r"(dst), "l"(gp) : "memory");
        }
    }
    asm volatile("cp.async.commit_group;" ::: "memory");
}

// tensor GEMM via mma.sync, cp.async double-buffered.
// C[M,N] = epi(alpha*(Ah+Al)@(Bh+Bl)^T + bias). A:[M,K] rm, B:[N,K] rm.
// epi: 0 none, 1 elu+1, 2 gelu.
// outm: 0 fp32 store, 1 fp32 heads, 2 fp32 +=, 3 rowscale-accum,
//       4 bf16-split heads, 6 bf16-split merged, 8 bf16-split flat.
__global__ void __launch_bounds__(256, 1) tg_k(
    int epi, int outm,
    const __nv_bfloat16* __restrict__ Ah, const __nv_bfloat16* __restrict__ Al,
    const __nv_bfloat16* __restrict__ Bh, const __nv_bfloat16* __restrict__ Bl,
    const float* __restrict__ bias, float* __restrict__ C,
    __nv_bfloat16* __restrict__ Ch, __nv_bfloat16* __restrict__ Cl,
    int M, int N, int K, int bsA, int bsB, int bsC, int bsBias, float alpha,
    const float* __restrict__ p1, const float* __restrict__ p2, int i1, int j2) {
    extern __shared__ char sm[];
    uint32_t sbase = s2u(sm);

    const int tid = threadIdx.x;
    const int lane = tid & 31;
    const int w = tid >> 5;
    const int g = lane >> 2;
    const int tc = lane & 3;
    const int wm = w >> 2;
    const int wn = w & 3;
    const int bz = blockIdx.z;
    const int m0 = blockIdx.y * 128;
    const int n0 = blockIdx.x * 128;

    const __nv_bfloat16* A0 = Ah + (size_t)bz * bsA;
    const __nv_bfloat16* A1 = Al + (size_t)bz * bsA;
    const __nv_bfloat16* B0 = Bh + (size_t)bz * bsB;
    const __nv_bfloat16* B1 = Bl + (size_t)bz * bsB;
    const float* bp = bias;
    if (bp) bp += (size_t)bz * bsBias;
    float* Cp = C ? C + (size_t)bz * bsC : (float*)0;
    __nv_bfloat16* Chp = Ch ? Ch + (size_t)bz * bsC : (__nv_bfloat16*)0;
    __nv_bfloat16* Clp = Cl ? Cl + (size_t)bz * bsC : (__nv_bfloat16*)0;

    float acc[4][4][4];
#pragma unroll
    for (int a = 0; a < 4; a++)
#pragma unroll
        for (int b = 0; b < 4; b++)
#pragma unroll
            for (int e = 0; e < 4; e++) acc[a][b][e] = 0.f;

    const int nch = K >> 5;
    tg_issue(A0, A1, B0, B1, m0, n0, K, M, N, 0, sbase, tid);

    for (int ch = 0; ch < nch; ch++) {
        if (ch + 1 < nch) {
            tg_issue(A0, A1, B0, B1, m0, n0, K, M, N, ch + 1, sbase, tid);
            asm volatile("cp.async.wait_group 1;" ::: "memory");
        } else {
            asm volatile("cp.async.wait_group 0;" ::: "memory");
        }
        __syncthreads();

        const __nv_bfloat16* s0 = (const __nv_bfloat16*)(sm + (ch & 1) * BUF_B);
        const __nv_bfloat16* s1 = s0 + 7168;
        const __nv_bfloat16* s2 = s0 + 14336;
        const __nv_bfloat16* s3 = s0 + 21504;

#pragma unroll
        for (int ks = 0; ks < 2; ks++) {
            int kb = ks * 16 + tc * 2;
            uint32_t fAh[4][4], fAl[4][4], fBh[4][2], fBl[4][2];
#pragma unroll
            for (int mt = 0; mt < 4; mt++) {
                const __nv_bfloat16* pa = s0 + (wm * 64 + mt * 16 + g) * SROW + kb;
                fAh[mt][0] = *(const uint32_t*)pa;
                fAh[mt][1] = *(const uint32_t*)(pa + 8 * SROW);
                fAh[mt][2] = *(const uint32_t*)(pa + 8);
                fAh[mt][3] = *(const uint32_t*)(pa + 8 * SROW + 8);
                const __nv_bfloat16* pl = s1 + (wm * 64 + mt * 16 + g) * SROW + kb;
                fAl[mt][0] = *(const uint32_t*)pl;
                fAl[mt][1] = *(const uint32_t*)(pl + 8 * SROW);
                fAl[mt][2] = *(const uint32_t*)(pl + 8);
                fAl[mt][3] = *(const uint32_t*)(pl + 8 * SROW + 8);
            }
#pragma unroll
            for (int nt = 0; nt < 4; nt++) {
                const __nv_bfloat16* pb = s2 + (wn * 32 + nt * 8 + g) * SROW + kb;
                fBh[nt][0] = *(const uint32_t*)pb;
                fBh[nt][1] = *(const uint32_t*)(pb + 8);
                const __nv_bfloat16* pq = s3 + (wn * 32 + nt * 8 + g) * SROW + kb;
                fBl[nt][0] = *(const uint32_t*)pq;
                fBl[nt][1] = *(const uint32_t*)(pq + 8);
            }
#pragma unroll
            for (int mt = 0; mt < 4; mt++)
#pragma unroll
                for (int nt = 0; nt < 4; nt++) {
                    mma16816(acc[mt][nt], fAh[mt], fBh[nt]);
                    mma16816(acc[mt][nt], fAh[mt], fBl[nt]);
                    mma16816(acc[mt][nt], fAl[mt], fBh[nt]);
                }
        }
        __syncthreads();
    }

#pragma unroll
    for (int mt = 0; mt < 4; mt++) {
#pragma unroll
        for (int eh = 0; eh < 2; eh++) {
            int row = m0 + wm * 64 + mt * 16 + g + eh * 8;
            float rs = 1.f;
            if (outm == 3) rs = p1[row * 4 + i1] * p2[row * 2 + j2];
#pragma unroll
            for (int nt = 0; nt < 4; nt++) {
#pragma unroll
                for (int ec = 0; ec < 2; ec++) {
                    int col = n0 + wn * 32 + nt * 8 + tc * 2 + ec;
                    if (col >= N) continue;
                    float v = acc[mt][nt][eh * 2 + ec] * alpha;
                    if (bp) v += bp[col];
                    if (epi == 1) v = (v > 0.f) ? (v + 1.f) : expf(v);
                    else if (epi == 2) v = gelu_f(v);
                    if (outm == 1 || outm == 4) {
                        size_t idx = (((size_t)((row >> 10) * CH + (col >> 6))) << 16) +
                                     ((row & 1023) << 6) + (col & 63);
                        if (outm == 1) Cp[idx] = v;
                        else split_st(Chp, Clp, idx, v);
                    } else if (outm == 6) {
                        size_t idx = ((size_t)((bz >> 4) * 1024 + row)) * 1024 +
                                     (size_t)((bz & 15) * 64 + col);
                        split_st(Ch, Cl, idx, v);
                    } else if (outm == 8) {
                        split_st(Chp, Clp, (size_t)row * N + col, v);
                    } else {
                        size_t ci = (size_t)row * N + col;
                        if (outm == 0) Cp[ci] = v;
                        else if (outm == 2) Cp[ci] += v;
                        else Cp[ci] += rs * v;
                    }
                }
            }
        }
    }
}

// FFMA GEMM (performer only)
template <int BM, int BN, int BK, int TM, int TN>
__global__ void __launch_bounds__((BM / TM) * (BN / TN))
gemm_k(const float* __restrict__ A, const float* __restrict__ Bm, float* __restrict__ C,
       int M, int N, int K, int sam, int sak, int sbk, int sbn,
       int bsA, int bsB, int bsC, float alpha) {
    constexpr int RM = BM / TM, RN = BN / TN, NT = RM * RN;
    const int bz = blockIdx.z;
    A += (size_t)bz * bsA;
    Bm += (size_t)bz * bsB;
    C += (size_t)bz * bsC;
    const int m0 = blockIdx.y * BM, n0 = blockIdx.x * BN;
    __shared__ float As[BK][BM + 4];
    __shared__ float Bs[BK][BN + 4];
    const int tid = threadIdx.x, tx = tid % RN, ty = tid / RN;
    float acc[TM][TN];
#pragma unroll
    for (int i = 0; i < TM; i++)
#pragma unroll
        for (int j = 0; j < TN; j++) acc[i][j] = 0.f;
    for (int k0 = 0; k0 < K; k0 += BK) {
#pragma unroll
        for (int idx = tid; idx < BM * BK; idx += NT) {
            int mm = idx / BK, kk = idx % BK;
            As[kk][mm] = A[(size_t)(m0 + mm) * sam + (size_t)(k0 + kk) * sak];
        }
#pragma unroll
        for (int idx = tid; idx < BK * BN; idx += NT) {
            int kk = idx / BN, nn = idx % BN;
            Bs[kk][nn] = Bm[(size_t)(k0 + kk) * sbk + (size_t)(n0 + nn) * sbn];
        }
        __syncthreads();
#pragma unroll
        for (int kk = 0; kk < BK; ++kk) {
            float ra[TM], rb[TN];
#pragma unroll
            for (int i = 0; i < TM; i++) ra[i] = As[kk][ty + i * RM];
#pragma unroll
            for (int j = 0; j < TN; j++) rb[j] = Bs[kk][tx + j * RN];
#pragma unroll
            for (int i = 0; i < TM; i++)
#pragma unroll
                for (int j = 0; j < TN; j++) acc[i][j] = fmaf(ra[i], rb[j], acc[i][j]);
        }
        __syncthreads();
    }
#pragma unroll
    for (int i = 0; i < TM; i++)
#pragma unroll
        for (int j = 0; j < TN; j++)
            C[(size_t)(m0 + ty + i * RM) * N + n0 + tx + j * RN] = acc[i][j] * alpha;
}

__global__ void zero_k(float* p, int n) {
    int i = blockIdx.x * blockDim.x + threadIdx.x;
    if (i < n) p[i] = 0.f;
}

// layernorm (+act); if oh != null, write bf16 hi/lo split instead of fp32 writeback
template <int ACT>
__global__ void ln_k(float* __restrict__ y, const float* __restrict__ g,
                     const float* __restrict__ be, int N, int rpg, int pstride,
                     __nv_bfloat16* __restrict__ oh, __nv_bfloat16* __restrict__ ol) {
    int row = blockIdx.x;
    int grp = row / rpg;
    const float* gp = g + (size_t)grp * pstride;
    const float* bpp = be + (size_t)grp * pstride;
    float* yr = y + (size_t)row * N;
    float s = 0.f, q = 0.f;
    for (int c = threadIdx.x; c < N; c += blockDim.x) {
        float v = yr[c];
        s += v;
        q += v * v;
    }
    s = brs(s);
    q = brs(q);
    float mean = s / N;
    float inv = rsqrtf(q / N - mean * mean + 1e-5f);
    for (int c = threadIdx.x; c < N; c += blockDim.x) {
        float v = (yr[c] - mean) * inv * gp[c] + bpp[c];
        if (ACT == 1) v = fmaxf(v, 0.f);
        if (ACT == 2) v = gelu_f(v);
        if (oh) split_st(oh, ol, (size_t)row * N + c, v);
        else yr[c] = v;
    }
}

// softmax over S cols; writes P as bf16 hi/lo
__global__ void softmax_k(const float* __restrict__ sc, const float* __restrict__ mask,
                          __nv_bfloat16* __restrict__ ph, __nv_bfloat16* __restrict__ pl) {
    int row = blockIdx.x;
    int b = row / (CH * CS);
    const float* r = sc + (size_t)row * CS;
    int t = threadIdx.x;
    float v[4];
    float mx = -3.4e38f;
#pragma unroll
    for (int i = 0; i < 4; i++) {
        int c = t + i * 256;
        float xv = r[c];
        if (mask) xv *= mask[b * CS + c];
        v[i] = xv;
        mx = fmaxf(mx, xv);
    }
    mx = brm(mx);
    float s = 0.f;
#pragma unroll
    for (int i = 0; i < 4; i++) {
        v[i] = __expf(v[i] - mx);
        s += v[i];
    }
    s = brs(s);
    float inv = 1.f / s;
#pragma unroll
    for (int i = 0; i < 4; i++) {
        size_t idx = (size_t)row * CS + t + i * 256;
        split_st(ph, pl, idx, v[i] * inv);
    }
}

__global__ void router_k(const float* __restrict__ h, const float* __restrict__ w,
                         const float* __restrict__ bias, float* __restrict__ probs,
                         int K, int NOUT) {
    __shared__ float red[512];
    int row = blockIdx.x, t = threadIdx.x;
    const float* hr = h + (size_t)row * K;
    float part[4] = {0.f, 0.f, 0.f, 0.f};
    for (int k = t; k < K; k += 128) {
        float hv = hr[k];
        for (int o = 0; o < NOUT; o++) part[o] += hv * w[k * NOUT + o];
    }
    for (int o = 0; o < 4; o++) red[t * 4 + o] = part[o];
    __syncthreads();
    for (int s = 64; s > 0; s >>= 1) {
        if (t < s)
            for (int o = 0; o < 4; o++) red[t * 4 + o] += red[(t + s) * 4 + o];
        __syncthreads();
    }
    if (t == 0) {
        float lg[4];
        float mx = -3.4e38f;
        for (int o = 0; o < NOUT; o++) {
            lg[o] = red[o] + bias[o];
            mx = fmaxf(mx, lg[o]);
        }
        float s = 0.f;
        for (int o = 0; o < NOUT; o++) {
            lg[o] = expf(lg[o] - mx);
            s += lg[o];
        }
        for (int o = 0; o < NOUT; o++) probs[row * NOUT + o] = lg[o] / s;
    }
}

__global__ void gemv_k(const float* __restrict__ x, const float* __restrict__ w,
                       const float* __restrict__ b, float* __restrict__ out) {
    int row = blockIdx.x;
    const float* xr = x + (size_t)row * CD;
    float s = 0.f;
    for (int k = threadIdx.x; k < CD; k += blockDim.x) s += xr[k] * w[k];
    s = brs(s);
    if (threadIdx.x == 0) out[row] = s + b[0];
}

__global__ void topk_mask_k(const float* __restrict__ imp, float* __restrict__ mask) {
    __shared__ float vals[1024];
    __shared__ float rv[1024];
    __shared__ int ri[1024];
    int b = blockIdx.x, t = threadIdx.x;
    vals[t] = imp[b * CS + t];
    mask[b * CS + t] = 0.f;
    __syncthreads();
    for (int it = 0; it < CTOPK; it++) {
        rv[t] = vals[t];
        ri[t] = t;
        __syncthreads();
        for (int s = 512; s > 0; s >>= 1) {
            if (t < s) {
                if (rv[t + s] > rv[t] || (rv[t + s] == rv[t] && ri[t + s] < ri[t])) {
                    rv[t] = rv[t + s];
                    ri[t] = ri[t + s];
                }
            }
            __syncthreads();
        }
        if (t == 0) {
            mask[b * CS + ri[0]] = 1.f;
            vals[ri[0]] = -3.4e38f;
        }
        __syncthreads();
    }
}

// depthwise conv -> bf16 hi/lo
__global__ void dwconv_k(const float* __restrict__ x, const float* __restrict__ dw,
                         __nv_bfloat16* __restrict__ oh, __nv_bfloat16* __restrict__ ol) {
    int idx = blockIdx.x * blockDim.x + threadIdx.x;
    if (idx >= CM * CD) return;
    int d = idx & (CD - 1);
    int s = (idx >> 10) & (CS - 1);
    float acc = x[idx] * dw[CD + d];
    if (s > 0) acc += x[idx - CD] * dw[d];
    if (s < CS - 1) acc += x[idx + CD] * dw[2 * CD + d];
    split_st(oh, ol, idx, acc);
}

__global__ void merge_k(const float* __restrict__ hin, float* __restrict__ o) {
    int idx = blockIdx.x * blockDim.x + threadIdx.x;
    if (idx >= CM * CD) return;
    int n = idx & 1023;
    int m = idx >> 10;
    int b = m >> 10, s = m & 1023, h = n >> 6, hd = n & 63;
    o[idx] = hin[(((size_t)(b * CH + h)) << 16) + (s << 6) + hd];
}

__global__ void colsum_k(const float* __restrict__ kpsi, float* __restrict__ ksum) {
    int bz = blockIdx.x;
    int d = threadIdx.x;
    const float* base = kpsi + (size_t)bz * CS * CKD + d;
    float s = 0.f;
    for (int l = 0; l < CS; l++) s += base[(size_t)l * CKD];
    ksum[bz * CKD + d] = s;
}

__global__ void perf_norm_k(float* __restrict__ num, const float* __restrict__ qphi,
                            const float* __restrict__ ksum) {
    int row = blockIdx.x;
    int bz = row / CS;
    int t = threadIdx.x;
    float p = qphi[(size_t)row * CKD + t] * ksum[bz * CKD + t];
    float den = brs(p) + 1e-8f;
    float inv = 1.f / den;
    if (t < CHD) num[(size_t)row * CHD + t] *= inv;
}

__global__ void convA(const float* __restrict__ s, __nv_bfloat16* __restrict__ h,
                      __nv_bfloat16* __restrict__ l, int n, float scale) {
    int i = blockIdx.x * 256 + threadIdx.x;
    if (i < n) {
        float v = s[i] * scale;
        split_st(h, l, i, v);
    }
}

// merge split -> fp32 (performer V)
__global__ void vmerge_k(const __nv_bfloat16* __restrict__ h,
                         const __nv_bfloat16* __restrict__ l, float* __restrict__ o, int n) {
    int i = blockIdx.x * 256 + threadIdx.x;
    if (i < n) o[i] = __bfloat162float(h[i]) + __bfloat162float(l[i]);
}

// V split heads [bh][s][hd] -> V^T [bh][hd][s] bf16 hi/lo
__global__ void vtrans_k(const __nv_bfloat16* __restrict__ vh,
                         const __nv_bfloat16* __restrict__ vl,
                         __nv_bfloat16* __restrict__ th, __nv_bfloat16* __restrict__ tl) {
    __shared__ float tt[32][33];
    int bh = blockIdx.z;
    int s0 = blockIdx.x * 32;
    int d0 = blockIdx.y * 32;
    size_t base = (size_t)bh * 65536;
    for (int i = threadIdx.y; i < 32; i += 8) {
        size_t si = base + (size_t)(s0 + i) * 64 + d0 + threadIdx.x;
        tt[i][threadIdx.x] = __bfloat162float(vh[si]) + __bfloat162float(vl[si]);
    }
    __syncthreads();
    for (int i = threadIdx.y; i < 32; i += 8) {
        float val = tt[threadIdx.x][i];
        size_t idx = base + (size_t)(d0 + i) * 1024 + s0 + threadIdx.x;
        split_st(th, tl, idx, val);
    }
}

__global__ void convWT(const float* __restrict__ src, __nv_bfloat16* __restrict__ dh,
                       __nv_bfloat16* __restrict__ dl, int K, int N) {
    __shared__ float tt[32][33];
    int b = blockIdx.z;
    src += (size_t)b * K * N;
    dh += (size_t)b * K * N;
    dl += (size_t)b * K * N;
    int k0 = blockIdx.x * 32, n0 = blockIdx.y * 32;
    for (int i = threadIdx.y; i < 32; i += 8)
        tt[i][threadIdx.x] = src[(size_t)(k0 + i) * N + n0 + threadIdx.x];
    __syncthreads();
    for (int i = threadIdx.y; i < 32; i += 8) {
        float v = tt[threadIdx.x][i];
        size_t o = (size_t)(n0 + i) * K + k0 + threadIdx.x;
        split_st(dh, dl, o, v);
    }
}

static float* symaddr(const void* s) {
    void* p = 0;
    cudaGetSymbolAddress(&p, s);
    return (float*)p;
}
static __nv_bfloat16* symb(const void* s) {
    void* p = 0;
    cudaGetSymbolAddress(&p, s);
    return (__nv_bfloat16*)p;
}

static void tgl(int epi, int outm, const __nv_bfloat16* Ah, const __nv_bfloat16* Al,
                const __nv_bfloat16* Bh, const __nv_bfloat16* Bl, const float* bias,
                float* C, __nv_bfloat16* Ch, __nv_bfloat16* Cl,
                int M, int N, int K, int bsA, int bsB, int bsC, int bsBias, int batch,
                float alpha, const float* p1, const float* p2, int i1, int j2) {
    dim3 g((N + 127) / 128, M / 128, batch);
    tg_k<<<g, 256, TG_SMEM>>>(epi, outm, Ah, Al, Bh, Bl, bias, C, Ch, Cl, M, N, K,
                              bsA, bsB, bsC, bsBias, alpha, p1, p2, i1, j2);
}

extern "C" void kernel_launch(void* const* d_in, const int* in_sizes, int n_in,
                              void* d_out, int out_size) {
    const float* x = (const float*)d_in[0];
    const float* w_qkvo = (const float*)d_in[1];
    const float* b_qkvo = (const float*)d_in[2];
    const float* sp_w = (const float*)d_in[3];
    const float* sp_b = (const float*)d_in[4];
    const float* phi_w = (const float*)d_in[5];
    const float* phi_b = (const float*)d_in[6];
    const float* psi_w = (const float*)d_in[7];
    const float* psi_b = (const float*)d_in[8];
    const float* conv_dw = (const float*)d_in[9];
    const float* conv_pw = (const float*)d_in[10];
    const float* fus_w = (const float*)d_in[11];
    const float* fus_b = (const float*)d_in[12];
    const float* sub_w1 = (const float*)d_in[13];
    const float* sub_b1 = (const float*)d_in[14];
    const float* sub_g = (const float*)d_in[15];
    const float* sub_be = (const float*)d_in[16];
    const float* sub_w2 = (const float*)d_in[17];
    const float* sub_b2 = (const float*)d_in[18];
    const float* r1_w1 = (const float*)d_in[19];
    const float* r1_b1 = (const float*)d_in[20];
    const float* r1_g = (const float*)d_in[21];
    const float* r1_be = (const float*)d_in[22];
    const float* r1_w2 = (const float*)d_in[23];
    const float* r1_b2 = (const float*)d_in[24];
    const float* r2_w1 = (const float*)d_in[25];
    const float* r2_b1 = (const float*)d_in[26];
    const float* r2_g = (const float*)d_in[27];
    const float* r2_be = (const float*)d_in[28];
    const float* r2_w2 = (const float*)d_in[29];
    const float* r2_b2 = (const float*)d_in[30];
    float* out = (float*)d_out;

    cudaFuncSetAttribute(tg_k, cudaFuncAttributeMaxDynamicSharedMemorySize, TG_SMEM);

    float* v = symaddr(g_v);
    float* scores = symaddr(g_scores);
    float* attn = symaddr(g_attn);
    float* mrg = symaddr(g_merge);
    float* eo = symaddr(g_eo);
    float* t1 = symaddr(g_t1);
    float* qphi = symaddr(g_qphi);
    float* kpsi = symaddr(g_kpsi);
    float* kv = symaddr(g_kv);
    float* ksum = symaddr(g_ksum);
    float* h1 = symaddr(g_h1);
    float* h2 = symaddr(g_h2);
    float* p1 = symaddr(g_p1);
    float* p2 = symaddr(g_p2);
    float* imp = symaddr(g_imp);
    float* msk = symaddr(g_mask);
    __nv_bfloat16* qkvbh = symb(qkvb_h);
    __nv_bfloat16* qkvbl = symb(qkvb_l);
    __nv_bfloat16* xbh = symb(xb_h);
    __nv_bfloat16* xbl = symb(xb_l);
    __nv_bfloat16* cvh = symb(cv_h);
    __nv_bfloat16* cvl = symb(cv_l);
    __nv_bfloat16* xch = symb(xc_h);
    __nv_bfloat16* xcl = symb(xc_l);
    __nv_bfloat16* aoh = symb(ao_h);
    __nv_bfloat16* aol = symb(ao_l);
    __nv_bfloat16* mgh = symb(mg_h);
    __nv_bfloat16* mgl = symb(mg_l);
    __nv_bfloat16* eoh = symb(eo_h);
    __nv_bfloat16* eol = symb(eo_l);
    __nv_bfloat16* t1h = symb(t1_h);
    __nv_bfloat16* t1l = symb(t1_l);
    __nv_bfloat16* wqh = symb(wq_h);
    __nv_bfloat16* wql = symb(wq_l);
    __nv_bfloat16* s1h = symb(s1_h);
    __nv_bfloat16* s1l = symb(s1_l);
    __nv_bfloat16* s2h = symb(s2_h);
    __nv_bfloat16* s2l = symb(s2_l);
    __nv_bfloat16* fwh = symb(fw_h);
    __nv_bfloat16* fwl = symb(fw_l);
    __nv_bfloat16* cwh = symb(cw_h);
    __nv_bfloat16* cwl = symb(cw_l);
    __nv_bfloat16* r1h = symb(r1_h);
    __nv_bfloat16* r1l = symb(r1_l);
    __nv_bfloat16* r2h = symb(r2_h);
    __nv_bfloat16* r2l = symb(r2_l);
    __nv_bfloat16* phh = symb(ph_h);
    __nv_bfloat16* phl = symb(ph_l);
    __nv_bfloat16* psh = symb(ps_h);
    __nv_bfloat16* psl = symb(ps_l);
    __nv_bfloat16* vth = symb(vt_h);
    __nv_bfloat16* vtl = symb(vt_l);
    __nv_bfloat16* pbh = symb(pb_h);
    __nv_bfloat16* pbl = symb(pb_l);
    const float* NP = (const float*)0;
    float* NF = (float*)0;
    __nv_bfloat16* NB = (__nv_bfloat16*)0;

    dim3 tb(32, 8);
    convWT<<<dim3(32, 32, 16), tb>>>(w_qkvo, wqh, wql, 1024, 1024);
    convWT<<<dim3(32, 32, 8), tb>>>(sub_w1, s1h, s1l, 1024, 1024);
    convWT<<<dim3(32, 32, 8), tb>>>(sub_w2, s2h, s2l, 1024, 1024);
    convWT<<<dim3(32, 32, 2), tb>>>(fus_w, fwh, fwl, 1024, 1024);
    convWT<<<dim3(32, 32, 1), tb>>>(conv_pw, cwh, cwl, 1024, 1024);
    convWT<<<dim3(32, 16, 1), tb>>>(r1_w1, r1h, r1l, 1024, 512);
    convWT<<<dim3(32, 8, 4), tb>>>(r2_w1, r2h, r2l, 1024, 256);
    convWT<<<dim3(2, 8, 1), tb>>>(phi_w, phh, phl, 64, 256);
    convWT<<<dim3(2, 8, 1), tb>>>(psi_w, psh, psl, 64, 256);
    convA<<<8192, 256>>>(x, xbh, xbl, CM * CD, 1.f);

    zero_k<<<8192, 256>>>(out, CM * CD);

    tgl(0, 0, xbh, xbl, r1h, r1l, r1_b1, h1, NB, NB, CM, 512, CD, 0, 0, 0, 0, 1, 1.f,
        NP, NP, 0, 0);
    ln_k<1><<<CM, 256>>>(h1, r1_g, r1_be, 512, CM, 0, NB, NB);
    router_k<<<CM, 128>>>(h1, r1_w2, r1_b2, p1, 512, 4);

    gemv_k<<<CM, 256>>>(x, sp_w, sp_b, imp);
    topk_mask_k<<<CB, 1024>>>(imp, msk);

    for (int i = 0; i < 4; i++) {
        const float* bb = b_qkvo + (size_t)i * 4 * CD;
        // QKV -> bf16 split heads, batch 3 (Q @0, K @2097152, V @4194304)
        tgl(0, 4, xbh, xbl, wqh + (size_t)i * 4194304, wql + (size_t)i * 4194304, bb, NF,
            qkvbh, qkvbl, CM, CD, CD, 0, 1048576, 2097152, CD, 3, 1.f, NP, NP, 0, 0);
        const __nv_bfloat16* woh = wqh + (size_t)(i * 4 + 3) * 1048576;
        const __nv_bfloat16* wol = wql + (size_t)(i * 4 + 3) * 1048576;

        if (i == 1) {
            vmerge_k<<<8192, 256>>>(qkvbh + 4194304, qkvbl + 4194304, v, 2097152);
            tgl(1, 0, qkvbh, qkvbl, phh, phl, phi_b, qphi, NB, NB, CBH * CS, CKD, CHD,
                0, 0, 0, 0, 1, 1.f, NP, NP, 0, 0);
            tgl(1, 0, qkvbh + 2097152, qkvbl + 2097152, psh, psl, psi_b, kpsi, NB, NB,
                CBH * CS, CKD, CHD, 0, 0, 0, 0, 1, 1.f, NP, NP, 0, 0);
            gemm_k<64, 64, 16, 4, 4><<<dim3(1, 4, CBH), 256>>>(
                kpsi, v, kv, CKD, CHD, CS, 1, CKD, CHD, 1,
                CS * CKD, CS * CHD, CKD * CHD, 1.f);
            colsum_k<<<CBH, 256>>>(kpsi, ksum);
            gemm_k<64, 64, 16, 4, 4><<<dim3(1, 16, CBH), 256>>>(
                qphi, kv, attn, CS, CHD, CKD, CKD, 1, CHD, 1,
                CS * CKD, CKD * CHD, CS * CHD, 1.f);
            perf_norm_k<<<CBH * CS, 256>>>(attn, qphi, ksum);
            merge_k<<<8192, 256>>>(attn, mrg);
            convA<<<8192, 256>>>(mrg, mgh, mgl, CM * CD, 1.f);
            tgl(0, 8, mgh, mgl, woh, wol, bb + 3 * CD, NF, eoh, eol, CM, CD, CD,
                0, 0, 0, CD, 1, 1.f, NP, NP, 0, 0);
        } else {
            vtrans_k<<<dim3(32, 2, CBH), tb>>>(qkvbh + 4194304, qkvbl + 4194304, vth, vtl);
            tgl(0, 0, qkvbh, qkvbl, qkvbh + 2097152, qkvbl + 2097152, NP, scores, NB, NB,
                CS, CS, CHD, 65536, 65536, 1048576, 0, CBH, 0.125f, NP, NP, 0, 0);
            softmax_k<<<CBH * CS, 256>>>(scores, (i == 0) ? msk : NP, pbh, pbl);
            tgl(0, 6, pbh, pbl, vth, vtl, NP, NF, mgh, mgl, CS, CHD, CS,
                1048576, 65536, 0, 0, CBH, 1.f, NP, NP, 0, 0);
            if (i == 3) {
                dwconv_k<<<8192, 256>>>(x, conv_dw, cvh, cvl);
                tgl(2, 8, cvh, cvl, cwh, cwl, NP, NF, xch, xcl, CM, CD, CD,
                    0, 0, 0, 0, 1, 1.f, NP, NP, 0, 0);
                tgl(0, 8, mgh, mgl, woh, wol, bb + 3 * CD, NF, aoh, aol, CM, CD, CD,
                    0, 0, 0, CD, 1, 1.f, NP, NP, 0, 0);
                tgl(0, 0, aoh, aol, fwh, fwl, fus_b, eo, NB, NB, CM, CD, CD,
                    0, 0, 0, CD, 1, 1.f, NP, NP, 0, 0);
                tgl(0, 2, xch, xcl, fwh + 1048576, fwl + 1048576, NP, eo, NB, NB,
                    CM, CD, CD, 0, 0, 0, 0, 1, 1.f, NP, NP, 0, 0);
                convA<<<8192, 256>>>(eo, eoh, eol, CM * CD, 1.f);
            } else {
                tgl(0, 8, mgh, mgl, woh, wol, bb + 3 * CD, NF, eoh, eol, CM, CD, CD,
                    0, 0, 0, CD, 1, 1.f, NP, NP, 0, 0);
            }
        }

        tgl(0, 0, eoh, eol, r2h + (size_t)i * 262144, r2l + (size_t)i * 262144,
            r2_b1 + i * 256, h2, NB, NB, CM, 256, CD, 0, 0, 0, 0, 1, 1.f, NP, NP, 0, 0);
        ln_k<1><<<CM, 256>>>(h2, r2_g + i * 256, r2_be + i * 256, 256, CM, 0, NB, NB);
        router_k<<<CM, 128>>>(h2, r2_w2 + (size_t)i * 512, r2_b2 + i * 2, p2, 256, 2);

        tgl(0, 0, eoh, eol, s1h + (size_t)i * 2097152, s1l + (size_t)i * 2097152,
            sub_b1 + (size_t)i * 2 * CD, t1, NB, NB, CM, CD, CD, 0, 1048576, 2097152,
            CD, 2, 1.f, NP, NP, 0, 0);
        ln_k<2><<<2 * CM, 256>>>(t1, sub_g + (size_t)i * 2 * CD, sub_be + (size_t)i * 2 * CD,
                                 CD, CM, CD, t1h, t1l);
        for (int j = 0; j < 2; j++) {
            tgl(0, 3, t1h + (size_t)j * 2097152, t1l + (size_t)j * 2097152,
                s2h + (size_t)(i * 2 + j) * 1048576, s2l + (size_t)(i * 2 + j) * 1048576,
                sub_b2 + (size_t)(i * 2 + j) * CD, out, NB, NB, CM, CD, CD,
                0, 0, 0, 0, 1, 1.f, p1, p2, i, j);
        }
    }
}

// round 12
// speedup vs baseline: 1.2568x; 1.2568x over previous
#include <cuda_runtime.h>
#include <cuda_bf16.h>
#include <math.h>
#include <stdint.h>
#include <cstdint>

#define CB 2
#define CS 1024
#define CD 1024
#define CH 16
#define CHD 64
#define CKD 256
#define CTOPK 10
#define CM 2048
#define CBH 32

__device__ float g_qkv[6291456];
__device__ float g_scores[33554432];
__device__ float g_attn[2097152];
__device__ float g_merge[2097152];
__device__ float g_eo[2097152];
__device__ float g_ao[2097152];
__device__ float g_xc[2097152];
__device__ float g_conv[2097152];
__device__ float g_t1[4194304];
__device__ float g_qphi[8388608];
__device__ float g_kpsi[8388608];
__device__ float g_kv[524288];
__device__ float g_ksum[8192];
__device__ float g_h1[1048576];
__device__ float g_h2[524288];
__device__ float g_p1[8192];
__device__ float g_p2[4096];
__device__ float g_imp[2048];
__device__ float g_mask[2048];

__device__ __nv_bfloat16 xb_h[2097152], xb_l[2097152];
__device__ __nv_bfloat16 qh_h[2097152], qh_l[2097152];
__device__ __nv_bfloat16 kh_h[2097152], kh_l[2097152];
__device__ __nv_bfloat16 cv_h[2097152], cv_l[2097152];
__device__ __nv_bfloat16 xc_h[2097152], xc_l[2097152];
__device__ __nv_bfloat16 ao_h[2097152], ao_l[2097152];
__device__ __nv_bfloat16 mg_h[2097152], mg_l[2097152];
__device__ __nv_bfloat16 eo_h[2097152], eo_l[2097152];
__device__ __nv_bfloat16 t1_h[4194304], t1_l[4194304];
__device__ __nv_bfloat16 wq_h[16777216], wq_l[16777216];
__device__ __nv_bfloat16 s1_h[8388608], s1_l[8388608];
__device__ __nv_bfloat16 s2_h[8388608], s2_l[8388608];
__device__ __nv_bfloat16 fw_h[2097152], fw_l[2097152];
__device__ __nv_bfloat16 cw_h[1048576], cw_l[1048576];
__device__ __nv_bfloat16 r1_h[524288], r1_l[524288];
__device__ __nv_bfloat16 r2_h[1048576], r2_l[1048576];
__device__ __nv_bfloat16 ph_h[16384], ph_l[16384];
__device__ __nv_bfloat16 ps_h[16384], ps_l[16384];
__device__ __nv_bfloat16 vt_h[2097152], vt_l[2097152];
__device__ __nv_bfloat16 pb_h[33554432], pb_l[33554432];

__device__ __forceinline__ float gelu_f(float v) {
    float c = 0.7978845608028654f * (v + 0.044715f * v * v * v);
    return 0.5f * v * (1.f + tanhf(c));
}

__device__ __forceinline__ float brs(float v) {
    __shared__ float sh[32];
    __syncthreads();
    int lane = threadIdx.x & 31;
    int wd = threadIdx.x >> 5;
#pragma unroll
    for (int o = 16; o > 0; o >>= 1) v += __shfl_xor_sync(0xffffffffu, v, o);
    if (lane == 0) sh[wd] = v;
    __syncthreads();
    int nw = (blockDim.x + 31) >> 5;
    v = (threadIdx.x < nw) ? sh[threadIdx.x] : 0.f;
    if (wd == 0) {
#pragma unroll
        for (int o = 16; o > 0; o >>= 1) v += __shfl_xor_sync(0xffffffffu, v, o);
        if (lane == 0) sh[0] = v;
    }
    __syncthreads();
    return sh[0];
}

__device__ __forceinline__ float brm(float v) {
    __shared__ float sh[32];
    __syncthreads();
    int lane = threadIdx.x & 31;
    int wd = threadIdx.x >> 5;
#pragma unroll
    for (int o = 16; o > 0; o >>= 1) v = fmaxf(v, __shfl_xor_sync(0xffffffffu, v, o));
    if (lane == 0) sh[wd] = v;
    __syncthreads();
    int nw = (blockDim.x + 31) >> 5;
    v = (threadIdx.x < nw) ? sh[threadIdx.x] : -3.4e38f;
    if (wd == 0) {
#pragma unroll
        for (int o = 16; o > 0; o >>= 1) v = fmaxf(v, __shfl_xor_sync(0xffffffffu, v, o));
        if (lane == 0) sh[0] = v;
    }
    __syncthreads();
    return sh[0];
}

__device__ __forceinline__ void mma16816(float* d, const uint32_t* a, const uint32_t* b) {
    asm volatile(
        "mma.sync.aligned.m16n8k16.row.col.f32.bf16.bf16.f32 "
        "{%0, %1, %2, %3}, {%4, %5, %6, %7}, {%8, %9}, {%0, %1, %2, %3};"
        : "+f"(d[0]), "+f"(d[1]), "+f"(d[2]), "+f"(d[3])
        : "r"(a[0]), "r"(a[1]), "r"(a[2]), "r"(a[3]), "r"(b[0]), "r"(b[1]));
}

__device__ __forceinline__ uint32_t s2u(const void* p) {
    uint32_t a;
    asm("{ .reg .u64 t; cvta.to.shared.u64 t, %1; cvt.u32.u64 %0, t; }" : "=r"(a) : "l"(p));
    return a;
}

__device__ __forceinline__ void split_st(__nv_bfloat16* h, __nv_bfloat16* l, size_t idx,
                                         float v) {
    __nv_bfloat16 a = __float2bfloat16(v);
    h[idx] = a;
    l[idx] = __float2bfloat16(v - __bfloat162float(a));
}

#define SROW 56
#define TILE_B 14336
#define BUF_B 57344
#define TG_SMEM 172032  // 3-stage pipeline

__device__ __forceinline__ void tg_issue(const __nv_bfloat16* A0, const __nv_bfloat16* A1,
                                         const __nv_bfloat16* B0, const __nv_bfloat16* B1,
                                         int m0, int n0, int K, int M, int N, int ch,
                                         uint32_t sbase, int tid) {
    const __nv_bfloat16* srcs[4] = {A0, A1, B0, B1};
    int buf = ch % 3;
    uint32_t dbase = sbase + (uint32_t)buf * BUF_B;
#pragma unroll
    for (int t = 0; t < 4; t++) {
        const __nv_bfloat16* src = srcs[t];
        int r0 = (t < 2) ? m0 : n0;
        int lim = (t < 2) ? M : N;
#pragma unroll
        for (int it = 0; it < 2; it++) {
            int u = tid + it * 256;
            int row = u >> 2;
            int c = u & 3;
            int gr = r0 + row;
            if (gr >= lim) gr = lim - 1;
            const void* gp = src + (size_t)gr * K + ch * 32 + c * 8;
            uint32_t dst = dbase + (uint32_t)(t * TILE_B + row * 112 + c * 16);
            asm volatile("cp.async.cg.shared.global [%0], [%1], 16;"
                         :: "r"(dst), "l"(gp) : "memory");
        }
    }
    asm volatile("cp.async.commit_group;" ::: "memory");
}

// tensor GEMM via mma.sync, cp.async triple-buffered.
// C[M,N] = epi(alpha*(Ah+Al)@(Bh+Bl)^T + bias). A:[M,K] rm, B:[N,K] rm.
// epi: 0 none, 1 elu+1, 2 gelu.
// outm: 0 store, 1 heads-scatter, 2 +=, 3 rowscale-accum, 6 bf16-split merged.
__global__ void __launch_bounds__(256, 1) tg_k(
    int epi, int outm,
    const __nv_bfloat16* __restrict__ Ah, const __nv_bfloat16* __restrict__ Al,
    const __nv_bfloat16* __restrict__ Bh, const __nv_bfloat16* __restrict__ Bl,
    const float* __restrict__ bias, float* __restrict__ C,
    __nv_bfloat16* __restrict__ Ch, __nv_bfloat16* __restrict__ Cl,
    int M, int N, int K, int bsA, int bsB, int bsC, int bsBias, float alpha,
    const float* __restrict__ p1, const float* __restrict__ p2, int i1, int j2) {
    extern __shared__ char sm[];
    uint32_t sbase = s2u(sm);

    const int tid = threadIdx.x;
    const int lane = tid & 31;
    const int w = tid >> 5;
    const int g = lane >> 2;
    const int tc = lane & 3;
    const int wm = w >> 2;
    const int wn = w & 3;
    const int bz = blockIdx.z;
    const int m0 = blockIdx.y * 128;
    const int n0 = blockIdx.x * 128;

    const __nv_bfloat16* A0 = Ah + (size_t)bz * bsA;
    const __nv_bfloat16* A1 = Al + (size_t)bz * bsA;
    const __nv_bfloat16* B0 = Bh + (size_t)bz * bsB;
    const __nv_bfloat16* B1 = Bl + (size_t)bz * bsB;
    const float* bp = bias;
    if (bp) bp += (size_t)bz * bsBias;
    float* Cp = C ? C + (size_t)bz * bsC : (float*)0;

    float acc[4][4][4];
#pragma unroll
    for (int a = 0; a < 4; a++)
#pragma unroll
        for (int b = 0; b < 4; b++)
#pragma unroll
            for (int e = 0; e < 4; e++) acc[a][b][e] = 0.f;

    const int nch = K >> 5;
    tg_issue(A0, A1, B0, B1, m0, n0, K, M, N, 0, sbase, tid);
    if (nch > 1) tg_issue(A0, A1, B0, B1, m0, n0, K, M, N, 1, sbase, tid);

    for (int ch = 0; ch < nch; ch++) {
        if (ch + 2 < nch) {
            tg_issue(A0, A1, B0, B1, m0, n0, K, M, N, ch + 2, sbase, tid);
            asm volatile("cp.async.wait_group 2;" ::: "memory");
        } else if (ch + 1 < nch) {
            asm volatile("cp.async.wait_group 1;" ::: "memory");
        } else {
            asm volatile("cp.async.wait_group 0;" ::: "memory");
        }
        __syncthreads();

        const __nv_bfloat16* s0 = (const __nv_bfloat16*)(sm + (ch % 3) * BUF_B);
        const __nv_bfloat16* s1 = s0 + 7168;
        const __nv_bfloat16* s2 = s0 + 14336;
        const __nv_bfloat16* s3 = s0 + 21504;

#pragma unroll
        for (int ks = 0; ks < 2; ks++) {
            int kb = ks * 16 + tc * 2;
            uint32_t fAh[4][4], fAl[4][4], fBh[4][2], fBl[4][2];
#pragma unroll
            for (int mt = 0; mt < 4; mt++) {
                const __nv_bfloat16* pa = s0 + (wm * 64 + mt * 16 + g) * SROW + kb;
                fAh[mt][0] = *(const uint32_t*)pa;
                fAh[mt][1] = *(const uint32_t*)(pa + 8 * SROW);
                fAh[mt][2] = *(const uint32_t*)(pa + 8);
                fAh[mt][3] = *(const uint32_t*)(pa + 8 * SROW + 8);
                const __nv_bfloat16* pl = s1 + (wm * 64 + mt * 16 + g) * SROW + kb;
                fAl[mt][0] = *(const uint32_t*)pl;
                fAl[mt][1] = *(const uint32_t*)(pl + 8 * SROW);
                fAl[mt][2] = *(const uint32_t*)(pl + 8);
                fAl[mt][3] = *(const uint32_t*)(pl + 8 * SROW + 8);
            }
#pragma unroll
            for (int nt = 0; nt < 4; nt++) {
                const __nv_bfloat16* pb = s2 + (wn * 32 + nt * 8 + g) * SROW + kb;
                fBh[nt][0] = *(const uint32_t*)pb;
                fBh[nt][1] = *(const uint32_t*)(pb + 8);
                const __nv_bfloat16* pq = s3 + (wn * 32 + nt * 8 + g) * SROW + kb;
                fBl[nt][0] = *(const uint32_t*)pq;
                fBl[nt][1] = *(const uint32_t*)(pq + 8);
            }
#pragma unroll
            for (int mt = 0; mt < 4; mt++)
#pragma unroll
                for (int nt = 0; nt < 4; nt++) {
                    mma16816(acc[mt][nt], fAh[mt], fBh[nt]);
                    mma16816(acc[mt][nt], fAh[mt], fBl[nt]);
                    mma16816(acc[mt][nt], fAl[mt], fBh[nt]);
                }
        }
        __syncthreads();
    }

#pragma unroll
    for (int mt = 0; mt < 4; mt++) {
#pragma unroll
        for (int eh = 0; eh < 2; eh++) {
            int row = m0 + wm * 64 + mt * 16 + g + eh * 8;
            float rs = 1.f;
            if (outm == 3) rs = p1[row * 4 + i1] * p2[row * 2 + j2];
#pragma unroll
            for (int nt = 0; nt < 4; nt++) {
#pragma unroll
                for (int ec = 0; ec < 2; ec++) {
                    int col = n0 + wn * 32 + nt * 8 + tc * 2 + ec;
                    if (col >= N) continue;
                    float v = acc[mt][nt][eh * 2 + ec] * alpha;
                    if (bp) v += bp[col];
                    if (epi == 1) v = (v > 0.f) ? (v + 1.f) : expf(v);
                    else if (epi == 2) v = gelu_f(v);
                    if (outm == 1) {
                        int b = row >> 10;
                        int s = row & 1023;
                        int h = col >> 6;
                        int hd = col & 63;
                        Cp[(((size_t)(b * CH + h)) << 16) + (s << 6) + hd] = v;
                    } else if (outm == 6) {
                        size_t idx = ((size_t)((bz >> 4) * 1024 + row)) * 1024 +
                                     (size_t)((bz & 15) * 64 + col);
                        split_st(Ch, Cl, idx, v);
                    } else {
                        size_t ci = (size_t)row * N + col;
                        if (outm == 0) Cp[ci] = v;
                        else if (outm == 2) Cp[ci] += v;
                        else Cp[ci] += rs * v;
                    }
                }
            }
        }
    }
}

// FFMA GEMM (performer only)
template <int BM, int BN, int BK, int TM, int TN>
__global__ void __launch_bounds__((BM / TM) * (BN / TN))
gemm_k(const float* __restrict__ A, const float* __restrict__ Bm, float* __restrict__ C,
       int M, int N, int K, int sam, int sak, int sbk, int sbn,
       int bsA, int bsB, int bsC, float alpha) {
    constexpr int RM = BM / TM, RN = BN / TN, NT = RM * RN;
    const int bz = blockIdx.z;
    A += (size_t)bz * bsA;
    Bm += (size_t)bz * bsB;
    C += (size_t)bz * bsC;
    const int m0 = blockIdx.y * BM, n0 = blockIdx.x * BN;
    __shared__ float As[BK][BM + 4];
    __shared__ float Bs[BK][BN + 4];
    const int tid = threadIdx.x, tx = tid % RN, ty = tid / RN;
    float acc[TM][TN];
#pragma unroll
    for (int i = 0; i < TM; i++)
#pragma unroll
        for (int j = 0; j < TN; j++) acc[i][j] = 0.f;
    for (int k0 = 0; k0 < K; k0 += BK) {
#pragma unroll
        for (int idx = tid; idx < BM * BK; idx += NT) {
            int mm = idx / BK, kk = idx % BK;
            As[kk][mm] = A[(size_t)(m0 + mm) * sam + (size_t)(k0 + kk) * sak];
        }
#pragma unroll
        for (int idx = tid; idx < BK * BN; idx += NT) {
            int kk = idx / BN, nn = idx % BN;
            Bs[kk][nn] = Bm[(size_t)(k0 + kk) * sbk + (size_t)(n0 + nn) * sbn];
        }
        __syncthreads();
#pragma unroll
        for (int kk = 0; kk < BK; ++kk) {
            float ra[TM], rb[TN];
#pragma unroll
            for (int i = 0; i < TM; i++) ra[i] = As[kk][ty + i * RM];
#pragma unroll
            for (int j = 0; j < TN; j++) rb[j] = Bs[kk][tx + j * RN];
#pragma unroll
            for (int i = 0; i < TM; i++)
#pragma unroll
                for (int j = 0; j < TN; j++) acc[i][j] = fmaf(ra[i], rb[j], acc[i][j]);
        }
        __syncthreads();
    }
#pragma unroll
    for (int i = 0; i < TM; i++)
#pragma unroll
        for (int j = 0; j < TN; j++)
            C[(size_t)(m0 + ty + i * RM) * N + n0 + tx + j * RN] = acc[i][j] * alpha;
}

__global__ void zero_k(float* p, int n) {
    int i = blockIdx.x * blockDim.x + threadIdx.x;
    if (i < n) p[i] = 0.f;
}

template <int ACT>
__global__ void ln_k(float* __restrict__ y, const float* __restrict__ g,
                     const float* __restrict__ be, int N, int rpg, int pstride) {
    int row = blockIdx.x;
    int grp = row / rpg;
    const float* gp = g + (size_t)grp * pstride;
    const float* bpp = be + (size_t)grp * pstride;
    float* yr = y + (size_t)row * N;
    float s = 0.f, q = 0.f;
    for (int c = threadIdx.x; c < N; c += blockDim.x) {
        float v = yr[c];
        s += v;
        q += v * v;
    }
    s = brs(s);
    q = brs(q);
    float mean = s / N;
    float inv = rsqrtf(q / N - mean * mean + 1e-5f);
    for (int c = threadIdx.x; c < N; c += blockDim.x) {
        float v = (yr[c] - mean) * inv * gp[c] + bpp[c];
        if (ACT == 1) v = fmaxf(v, 0.f);
        if (ACT == 2) v = gelu_f(v);
        yr[c] = v;
    }
}

// softmax over S cols; writes P as bf16 hi/lo
__global__ void softmax_k(const float* __restrict__ sc, const float* __restrict__ mask,
                          __nv_bfloat16* __restrict__ ph, __nv_bfloat16* __restrict__ pl) {
    int row = blockIdx.x;
    int b = row / (CH * CS);
    const float* r = sc + (size_t)row * CS;
    int t = threadIdx.x;
    float v[4];
    float mx = -3.4e38f;
#pragma unroll
    for (int i = 0; i < 4; i++) {
        int c = t + i * 256;
        float xv = r[c];
        if (mask) xv *= mask[b * CS + c];
        v[i] = xv;
        mx = fmaxf(mx, xv);
    }
    mx = brm(mx);
    float s = 0.f;
#pragma unroll
    for (int i = 0; i < 4; i++) {
        v[i] = __expf(v[i] - mx);
        s += v[i];
    }
    s = brs(s);
    float inv = 1.f / s;
#pragma unroll
    for (int i = 0; i < 4; i++) {
        size_t idx = (size_t)row * CS + t + i * 256;
        split_st(ph, pl, idx, v[i] * inv);
    }
}

__global__ void router_k(const float* __restrict__ h, const float* __restrict__ w,
                         const float* __restrict__ bias, float* __restrict__ probs,
                         int K, int NOUT) {
    __shared__ float red[512];
    int row = blockIdx.x, t = threadIdx.x;
    const float* hr = h + (size_t)row * K;
    float part[4] = {0.f, 0.f, 0.f, 0.f};
    for (int k = t; k < K; k += 128) {
        float hv = hr[k];
        for (int o = 0; o < NOUT; o++) part[o] += hv * w[k * NOUT + o];
    }
    for (int o = 0; o < 4; o++) red[t * 4 + o] = part[o];
    __syncthreads();
    for (int s = 64; s > 0; s >>= 1) {
        if (t < s)
            for (int o = 0; o < 4; o++) red[t * 4 + o] += red[(t + s) * 4 + o];
        __syncthreads();
    }
    if (t == 0) {
        float lg[4];
        float mx = -3.4e38f;
        for (int o = 0; o < NOUT; o++) {
            lg[o] = red[o] + bias[o];
            mx = fmaxf(mx, lg[o]);
        }
        float s = 0.f;
        for (int o = 0; o < NOUT; o++) {
            lg[o] = expf(lg[o] - mx);
            s += lg[o];
        }
        for (int o = 0; o < NOUT; o++) probs[row * NOUT + o] = lg[o] / s;
    }
}

__global__ void gemv_k(const float* __restrict__ x, const float* __restrict__ w,
                       const float* __restrict__ b, float* __restrict__ out) {
    int row = blockIdx.x;
    const float* xr = x + (size_t)row * CD;
    float s = 0.f;
    for (int k = threadIdx.x; k < CD; k += blockDim.x) s += xr[k] * w[k];
    s = brs(s);
    if (threadIdx.x == 0) out[row] = s + b[0];
}

__global__ void topk_mask_k(const float* __restrict__ imp, float* __restrict__ mask) {
    __shared__ float vals[1024];
    __shared__ float rv[1024];
    __shared__ int ri[1024];
    int b = blockIdx.x, t = threadIdx.x;
    vals[t] = imp[b * CS + t];
    mask[b * CS + t] = 0.f;
    __syncthreads();
    for (int it = 0; it < CTOPK; it++) {
        rv[t] = vals[t];
        ri[t] = t;
        __syncthreads();
        for (int s = 512; s > 0; s >>= 1) {
            if (t < s) {
                if (rv[t + s] > rv[t] || (rv[t + s] == rv[t] && ri[t + s] < ri[t])) {
                    rv[t] = rv[t + s];
                    ri[t] = ri[t + s];
                }
            }
            __syncthreads();
        }
        if (t == 0) {
            mask[b * CS + ri[0]] = 1.f;
            vals[ri[0]] = -3.4e38f;
        }
        __syncthreads();
    }
}

__global__ void dwconv_k(const float* __restrict__ x, const float* __restrict__ dw,
                         float* __restrict__ o) {
    int idx = blockIdx.x * blockDim.x + threadIdx.x;
    if (idx >= CM * CD) return;
    int d = idx & (CD - 1);
    int s = (idx >> 10) & (CS - 1);
    float acc = x[idx] * dw[CD + d];
    if (s > 0) acc += x[idx - CD] * dw[d];
    if (s < CS - 1) acc += x[idx + CD] * dw[2 * CD + d];
    o[idx] = acc;
}

__global__ void merge_k(const float* __restrict__ hin, float* __restrict__ o) {
    int idx = blockIdx.x * blockDim.x + threadIdx.x;
    if (idx >= CM * CD) return;
    int n = idx & 1023;
    int m = idx >> 10;
    int b = m >> 10, s = m & 1023, h = n >> 6, hd = n & 63;
    o[idx] = hin[(((size_t)(b * CH + h)) << 16) + (s << 6) + hd];
}

__global__ void colsum_k(const float* __restrict__ kpsi, float* __restrict__ ksum) {
    int bz = blockIdx.x;
    int d = threadIdx.x;
    const float* base = kpsi + (size_t)bz * CS * CKD + d;
    float s = 0.f;
    for (int l = 0; l < CS; l++) s += base[(size_t)l * CKD];
    ksum[bz * CKD + d] = s;
}

__global__ void perf_norm_k(float* __restrict__ num, const float* __restrict__ qphi,
                            const float* __restrict__ ksum) {
    int row = blockIdx.x;
    int bz = row / CS;
    int t = threadIdx.x;
    float p = qphi[(size_t)row * CKD + t] * ksum[bz * CKD + t];
    float den = brs(p) + 1e-8f;
    float inv = 1.f / den;
    if (t < CHD) num[(size_t)row * CHD + t] *= inv;
}

__global__ void convA(const float* __restrict__ s, __nv_bfloat16* __restrict__ h,
                      __nv_bfloat16* __restrict__ l, int n, float scale) {
    int i = blockIdx.x * 256 + threadIdx.x;
    if (i < n) {
        float v = s[i] * scale;
        split_st(h, l, i, v);
    }
}

// V heads [bh][s][hd] fp32 -> V^T [bh][hd][s] bf16 hi/lo
__global__ void vtrans_k(const float* __restrict__ v, __nv_bfloat16* __restrict__ th,
                         __nv_bfloat16* __restrict__ tl) {
    __shared__ float tt[32][33];
    int bh = blockIdx.z;
    int s0 = blockIdx.x * 32;
    int d0 = blockIdx.y * 32;
    const float* vp = v + (size_t)bh * 65536;
    for (int i = threadIdx.y; i < 32; i += 8)
        tt[i][threadIdx.x] = vp[(size_t)(s0 + i) * 64 + d0 + threadIdx.x];
    __syncthreads();
    for (int i = threadIdx.y; i < 32; i += 8) {
        float val = tt[threadIdx.x][i];
        size_t idx = (size_t)bh * 65536 + (size_t)(d0 + i) * 1024 + s0 + threadIdx.x;
        split_st(th, tl, idx, val);
    }
}

__global__ void convWT(const float* __restrict__ src, __nv_bfloat16* __restrict__ dh,
                       __nv_bfloat16* __restrict__ dl, int K, int N) {
    __shared__ float tt[32][33];
    int b = blockIdx.z;
    src += (size_t)b * K * N;
    dh += (size_t)b * K * N;
    dl += (size_t)b * K * N;
    int k0 = blockIdx.x * 32, n0 = blockIdx.y * 32;
    for (int i = threadIdx.y; i < 32; i += 8)
        tt[i][threadIdx.x] = src[(size_t)(k0 + i) * N + n0 + threadIdx.x];
    __syncthreads();
    for (int i = threadIdx.y; i < 32; i += 8) {
        float v = tt[threadIdx.x][i];
        size_t o = (size_t)(n0 + i) * K + k0 + threadIdx.x;
        split_st(dh, dl, o, v);
    }
}

static float* symaddr(const void* s) {
    void* p = 0;
    cudaGetSymbolAddress(&p, s);
    return (float*)p;
}
static __nv_bfloat16* symb(const void* s) {
    void* p = 0;
    cudaGetSymbolAddress(&p, s);
    return (__nv_bfloat16*)p;
}

static void tgl(int epi, int outm, const __nv_bfloat16* Ah, const __nv_bfloat16* Al,
                const __nv_bfloat16* Bh, const __nv_bfloat16* Bl, const float* bias,
                float* C, __nv_bfloat16* Ch, __nv_bfloat16* Cl,
                int M, int N, int K, int bsA, int bsB, int bsC, int bsBias, int batch,
                float alpha, const float* p1, const float* p2, int i1, int j2) {
    dim3 g((N + 127) / 128, M / 128, batch);
    tg_k<<<g, 256, TG_SMEM>>>(epi, outm, Ah, Al, Bh, Bl, bias, C, Ch, Cl, M, N, K,
                              bsA, bsB, bsC, bsBias, alpha, p1, p2, i1, j2);
}

extern "C" void kernel_launch(void* const* d_in, const int* in_sizes, int n_in,
                              void* d_out, int out_size) {
    const float* x = (const float*)d_in[0];
    const float* w_qkvo = (const float*)d_in[1];
    const float* b_qkvo = (const float*)d_in[2];
    const float* sp_w = (const float*)d_in[3];
    const float* sp_b = (const float*)d_in[4];
    const float* phi_w = (const float*)d_in[5];
    const float* phi_b = (const float*)d_in[6];
    const float* psi_w = (const float*)d_in[7];
    const float* psi_b = (const float*)d_in[8];
    const float* conv_dw = (const float*)d_in[9];
    const float* conv_pw = (const float*)d_in[10];
    const float* fus_w = (const float*)d_in[11];
    const float* fus_b = (const float*)d_in[12];
    const float* sub_w1 = (const float*)d_in[13];
    const float* sub_b1 = (const float*)d_in[14];
    const float* sub_g = (const float*)d_in[15];
    const float* sub_be = (const float*)d_in[16];
    const float* sub_w2 = (const float*)d_in[17];
    const float* sub_b2 = (const float*)d_in[18];
    const float* r1_w1 = (const float*)d_in[19];
    const float* r1_b1 = (const float*)d_in[20];
    const float* r1_g = (const float*)d_in[21];
    const float* r1_be = (const float*)d_in[22];
    const float* r1_w2 = (const float*)d_in[23];
    const float* r1_b2 = (const float*)d_in[24];
    const float* r2_w1 = (const float*)d_in[25];
    const float* r2_b1 = (const float*)d_in[26];
    const float* r2_g = (const float*)d_in[27];
    const float* r2_be = (const float*)d_in[28];
    const float* r2_w2 = (const float*)d_in[29];
    const float* r2_b2 = (const float*)d_in[30];
    float* out = (float*)d_out;

    cudaFuncSetAttribute(tg_k, cudaFuncAttributeMaxDynamicSharedMemorySize, TG_SMEM);

    float* q = symaddr(g_qkv);
    float* k = q + 2097152;
    float* v = q + 4194304;
    float* scores = symaddr(g_scores);
    float* attn = symaddr(g_attn);
    float* mrg = symaddr(g_merge);
    float* eo = symaddr(g_eo);
    float* ao = symaddr(g_ao);
    float* xc = symaddr(g_xc);
    float* cnv = symaddr(g_conv);
    float* t1 = symaddr(g_t1);
    float* qphi = symaddr(g_qphi);
    float* kpsi = symaddr(g_kpsi);
    float* kv = symaddr(g_kv);
    float* ksum = symaddr(g_ksum);
    float* h1 = symaddr(g_h1);
    float* h2 = symaddr(g_h2);
    float* p1 = symaddr(g_p1);
    float* p2 = symaddr(g_p2);
    float* imp = symaddr(g_imp);
    float* msk = symaddr(g_mask);
    __nv_bfloat16* xbh = symb(xb_h);
    __nv_bfloat16* xbl = symb(xb_l);
    __nv_bfloat16* qhh = symb(qh_h);
    __nv_bfloat16* qhl = symb(qh_l);
    __nv_bfloat16* khh = symb(kh_h);
    __nv_bfloat16* khl = symb(kh_l);
    __nv_bfloat16* cvh = symb(cv_h);
    __nv_bfloat16* cvl = symb(cv_l);
    __nv_bfloat16* xch = symb(xc_h);
    __nv_bfloat16* xcl = symb(xc_l);
    __nv_bfloat16* aoh = symb(ao_h);
    __nv_bfloat16* aol = symb(ao_l);
    __nv_bfloat16* mgh = symb(mg_h);
    __nv_bfloat16* mgl = symb(mg_l);
    __nv_bfloat16* eoh = symb(eo_h);
    __nv_bfloat16* eol = symb(eo_l);
    __nv_bfloat16* t1h = symb(t1_h);
    __nv_bfloat16* t1l = symb(t1_l);
    __nv_bfloat16* wqh = symb(wq_h);
    __nv_bfloat16* wql = symb(wq_l);
    __nv_bfloat16* s1h = symb(s1_h);
    __nv_bfloat16* s1l = symb(s1_l);
    __nv_bfloat16* s2h = symb(s2_h);
    __nv_bfloat16* s2l = symb(s2_l);
    __nv_bfloat16* fwh = symb(fw_h);
    __nv_bfloat16* fwl = symb(fw_l);
    __nv_bfloat16* cwh = symb(cw_h);
    __nv_bfloat16* cwl = symb(cw_l);
    __nv_bfloat16* r1h = symb(r1_h);
    __nv_bfloat16* r1l = symb(r1_l);
    __nv_bfloat16* r2h = symb(r2_h);
    __nv_bfloat16* r2l = symb(r2_l);
    __nv_bfloat16* phh = symb(ph_h);
    __nv_bfloat16* phl = symb(ph_l);
    __nv_bfloat16* psh = symb(ps_h);
    __nv_bfloat16* psl = symb(ps_l);
    __nv_bfloat16* vth = symb(vt_h);
    __nv_bfloat16* vtl = symb(vt_l);
    __nv_bfloat16* pbh = symb(pb_h);
    __nv_bfloat16* pbl = symb(pb_l);
    const float* NP = (const float*)0;
    float* NF = (float*)0;
    __nv_bfloat16* NB = (__nv_bfloat16*)0;

    dim3 tb(32, 8);
    convWT<<<dim3(32, 32, 16), tb>>>(w_qkvo, wqh, wql, 1024, 1024);
    convWT<<<dim3(32, 32, 8), tb>>>(sub_w1, s1h, s1l, 1024, 1024);
    convWT<<<dim3(32, 32, 8), tb>>>(sub_w2, s2h, s2l, 1024, 1024);
    convWT<<<dim3(32, 32, 2), tb>>>(fus_w, fwh, fwl, 1024, 1024);
    convWT<<<dim3(32, 32, 1), tb>>>(conv_pw, cwh, cwl, 1024, 1024);
    convWT<<<dim3(32, 16, 1), tb>>>(r1_w1, r1h, r1l, 1024, 512);
    convWT<<<dim3(32, 8, 4), tb>>>(r2_w1, r2h, r2l, 1024, 256);
    convWT<<<dim3(2, 8, 1), tb>>>(phi_w, phh, phl, 64, 256);
    convWT<<<dim3(2, 8, 1), tb>>>(psi_w, psh, psl, 64, 256);
    convA<<<8192, 256>>>(x, xbh, xbl, CM * CD, 1.f);

    zero_k<<<8192, 256>>>(out, CM * CD);

    tgl(0, 0, xbh, xbl, r1h, r1l, r1_b1, h1, NB, NB, CM, 512, CD, 0, 0, 0, 0, 1, 1.f,
        NP, NP, 0, 0);
    ln_k<1><<<CM, 256>>>(h1, r1_g, r1_be, 512, CM, 0);
    router_k<<<CM, 128>>>(h1, r1_w2, r1_b2, p1, 512, 4);

    gemv_k<<<CM, 256>>>(x, sp_w, sp_b, imp);
    topk_mask_k<<<CB, 1024>>>(imp, msk);

    for (int i = 0; i < 4; i++) {
        const float* bb = b_qkvo + (size_t)i * 4 * CD;
        tgl(0, 1, xbh, xbl, wqh + (size_t)i * 4194304, wql + (size_t)i * 4194304, bb, q,
            NB, NB, CM, CD, CD, 0, 1048576, 2097152, CD, 3, 1.f, NP, NP, 0, 0);
        const __nv_bfloat16* woh = wqh + (size_t)(i * 4 + 3) * 1048576;
        const __nv_bfloat16* wol = wql + (size_t)(i * 4 + 3) * 1048576;

        if (i == 1) {
            convA<<<8192, 256>>>(q, qhh, qhl, 2097152, 1.f);
            convA<<<8192, 256>>>(k, khh, khl, 2097152, 1.f);
            tgl(1, 0, qhh, qhl, phh, phl, phi_b, qphi, NB, NB, CBH * CS, CKD, CHD,
                0, 0, 0, 0, 1, 1.f, NP, NP, 0, 0);
            tgl(1, 0, khh, khl, psh, psl, psi_b, kpsi, NB, NB, CBH * CS, CKD, CHD,
                0, 0, 0, 0, 1, 1.f, NP, NP, 0, 0);
            gemm_k<64, 64, 16, 4, 4><<<dim3(1, 4, CBH), 256>>>(
                kpsi, v, kv, CKD, CHD, CS, 1, CKD, CHD, 1,
                CS * CKD, CS * CHD, CKD * CHD, 1.f);
            colsum_k<<<CBH, 256>>>(kpsi, ksum);
            gemm_k<64, 64, 16, 4, 4><<<dim3(1, 16, CBH), 256>>>(
                qphi, kv, attn, CS, CHD, CKD, CKD, 1, CHD, 1,
                CS * CKD, CKD * CHD, CS * CHD, 1.f);
            perf_norm_k<<<CBH * CS, 256>>>(attn, qphi, ksum);
            merge_k<<<8192, 256>>>(attn, mrg);
            convA<<<8192, 256>>>(mrg, mgh, mgl, CM * CD, 1.f);
            tgl(0, 0, mgh, mgl, woh, wol, bb + 3 * CD, eo, NB, NB, CM, CD, CD,
                0, 0, 0, 0, 1, 1.f, NP, NP, 0, 0);
        } else {
            convA<<<8192, 256>>>(q, qhh, qhl, 2097152, 0.125f);
            convA<<<8192, 256>>>(k, khh, khl, 2097152, 1.f);
            vtrans_k<<<dim3(32, 2, CBH), tb>>>(v, vth, vtl);
            tgl(0, 0, qhh, qhl, khh, khl, NP, scores, NB, NB, CS, CS, CHD,
                65536, 65536, 1048576, 0, CBH, 1.f, NP, NP, 0, 0);
            softmax_k<<<CBH * CS, 256>>>(scores, (i == 0) ? msk : NP, pbh, pbl);
            tgl(0, 6, pbh, pbl, vth, vtl, NP, NF, mgh, mgl, CS, CHD, CS,
                1048576, 65536, 0, 0, CBH, 1.f, NP, NP, 0, 0);
            if (i == 3) {
                dwconv_k<<<8192, 256>>>(x, conv_dw, cnv);
                convA<<<8192, 256>>>(cnv, cvh, cvl, CM * CD, 1.f);
                tgl(2, 0, cvh, cvl, cwh, cwl, NP, xc, NB, NB, CM, CD, CD,
                    0, 0, 0, 0, 1, 1.f, NP, NP, 0, 0);
                tgl(0, 0, mgh, mgl, woh, wol, bb + 3 * CD, ao, NB, NB, CM, CD, CD,
                    0, 0, 0, 0, 1, 1.f, NP, NP, 0, 0);
                convA<<<8192, 256>>>(ao, aoh, aol, CM * CD, 1.f);
                convA<<<8192, 256>>>(xc, xch, xcl, CM * CD, 1.f);
                tgl(0, 0, aoh, aol, fwh, fwl, fus_b, eo, NB, NB, CM, CD, CD,
                    0, 0, 0, 0, 1, 1.f, NP, NP, 0, 0);
                tgl(0, 2, xch, xcl, fwh + 1048576, fwl + 1048576, NP, eo, NB, NB,
                    CM, CD, CD, 0, 0, 0, 0, 1, 1.f, NP, NP, 0, 0);
            } else {
                tgl(0, 0, mgh, mgl, woh, wol, bb + 3 * CD, eo, NB, NB, CM, CD, CD,
                    0, 0, 0, 0, 1, 1.f, NP, NP, 0, 0);
            }
        }
        convA<<<8192, 256>>>(eo, eoh, eol, CM * CD, 1.f);

        tgl(0, 0, eoh, eol, r2h + (size_t)i * 262144, r2l + (size_t)i * 262144,
            r2_b1 + i * 256, h2, NB, NB, CM, 256, CD, 0, 0, 0, 0, 1, 1.f, NP, NP, 0, 0);
        ln_k<1><<<CM, 256>>>(h2, r2_g + i * 256, r2_be + i * 256, 256, CM, 0);
        router_k<<<CM, 128>>>(h2, r2_w2 + (size_t)i * 512, r2_b2 + i * 2, p2, 256, 2);

        tgl(0, 0, eoh, eol, s1h + (size_t)i * 2097152, s1l + (size_t)i * 2097152,
            sub_b1 + (size_t)i * 2 * CD, t1, NB, NB, CM, CD, CD, 0, 1048576, 2097152,
            CD, 2, 1.f, NP, NP, 0, 0);
        ln_k<2><<<2 * CM, 256>>>(t1, sub_g + (size_t)i * 2 * CD, sub_be + (size_t)i * 2 * CD,
                                 CD, CM, CD);
        convA<<<16384, 256>>>(t1, t1h, t1l, 2 * CM * CD, 1.f);
        for (int j = 0; j < 2; j++) {
            tgl(0, 3, t1h + (size_t)j * 2097152, t1l + (size_t)j * 2097152,
                s2h + (size_t)(i * 2 + j) * 1048576, s2l + (size_t)(i * 2 + j) * 1048576,
                sub_b2 + (size_t)(i * 2 + j) * CD, out, NB, NB, CM, CD, CD,
                0, 0, 0, 0, 1, 1.f, p1, p2, i, j);
        }
    }
}

// round 13
// speedup vs baseline: 1.2900x; 1.0264x over previous
#include <cuda_runtime.h>
#include <cuda_bf16.h>
#include <math.h>
#include <stdint.h>
#include <cstdint>

#define CB 2
#define CS 1024
#define CD 1024
#define CH 16
#define CHD 64
#define CKD 256
#define CTOPK 10
#define CM 2048
#define CBH 32

__device__ float g_qkv[6291456];
__device__ float g_scores[33554432];
__device__ float g_attn[2097152];
__device__ float g_merge[2097152];
__device__ float g_eo[2097152];
__device__ float g_ao[2097152];
__device__ float g_xc[2097152];
__device__ float g_conv[2097152];
__device__ float g_t1[4194304];
__device__ float g_qphi[8388608];
__device__ float g_kpsi[8388608];
__device__ float g_kv[524288];
__device__ float g_ksum[8192];
__device__ float g_h1[1048576];
__device__ float g_h2[524288];
__device__ float g_p1[8192];
__device__ float g_p2[4096];
__device__ float g_imp[2048];
__device__ float g_mask[2048];

__device__ __nv_bfloat16 xb_h[2097152], xb_l[2097152];
__device__ __nv_bfloat16 qh_h[2097152], qh_l[2097152];
__device__ __nv_bfloat16 kh_h[2097152], kh_l[2097152];
__device__ __nv_bfloat16 cv_h[2097152], cv_l[2097152];
__device__ __nv_bfloat16 xc_h[2097152], xc_l[2097152];
__device__ __nv_bfloat16 ao_h[2097152], ao_l[2097152];
__device__ __nv_bfloat16 mg_h[2097152], mg_l[2097152];
__device__ __nv_bfloat16 eo_h[2097152], eo_l[2097152];
__device__ __nv_bfloat16 t1_h[4194304], t1_l[4194304];
__device__ __nv_bfloat16 wq_h[16777216], wq_l[16777216];
__device__ __nv_bfloat16 s1_h[8388608], s1_l[8388608];
__device__ __nv_bfloat16 s2_h[8388608], s2_l[8388608];
__device__ __nv_bfloat16 fw_h[2097152], fw_l[2097152];
__device__ __nv_bfloat16 cw_h[1048576], cw_l[1048576];
__device__ __nv_bfloat16 r1_h[524288], r1_l[524288];
__device__ __nv_bfloat16 r2_h[1048576], r2_l[1048576];
__device__ __nv_bfloat16 ph_h[16384], ph_l[16384];
__device__ __nv_bfloat16 ps_h[16384], ps_l[16384];
__device__ __nv_bfloat16 vt_h[2097152], vt_l[2097152];
__device__ __nv_bfloat16 pb_h[33554432], pb_l[33554432];

__device__ __forceinline__ float gelu_f(float v) {
    float c = 0.7978845608028654f * (v + 0.044715f * v * v * v);
    return 0.5f * v * (1.f + tanhf(c));
}

__device__ __forceinline__ float brs(float v) {
    __shared__ float sh[32];
    __syncthreads();
    int lane = threadIdx.x & 31;
    int wd = threadIdx.x >> 5;
#pragma unroll
    for (int o = 16; o > 0; o >>= 1) v += __shfl_xor_sync(0xffffffffu, v, o);
    if (lane == 0) sh[wd] = v;
    __syncthreads();
    int nw = (blockDim.x + 31) >> 5;
    v = (threadIdx.x < nw) ? sh[threadIdx.x] : 0.f;
    if (wd == 0) {
#pragma unroll
        for (int o = 16; o > 0; o >>= 1) v += __shfl_xor_sync(0xffffffffu, v, o);
        if (lane == 0) sh[0] = v;
    }
    __syncthreads();
    return sh[0];
}

__device__ __forceinline__ float brm(float v) {
    __shared__ float sh[32];
    __syncthreads();
    int lane = threadIdx.x & 31;
    int wd = threadIdx.x >> 5;
#pragma unroll
    for (int o = 16; o > 0; o >>= 1) v = fmaxf(v, __shfl_xor_sync(0xffffffffu, v, o));
    if (lane == 0) sh[wd] = v;
    __syncthreads();
    int nw = (blockDim.x + 31) >> 5;
    v = (threadIdx.x < nw) ? sh[threadIdx.x] : -3.4e38f;
    if (wd == 0) {
#pragma unroll
        for (int o = 16; o > 0; o >>= 1) v = fmaxf(v, __shfl_xor_sync(0xffffffffu, v, o));
        if (lane == 0) sh[0] = v;
    }
    __syncthreads();
    return sh[0];
}

__device__ __forceinline__ void mma16816(float* d, const uint32_t* a, const uint32_t* b) {
    asm volatile(
        "mma.sync.aligned.m16n8k16.row.col.f32.bf16.bf16.f32 "
        "{%0, %1, %2, %3}, {%4, %5, %6, %7}, {%8, %9}, {%0, %1, %2, %3};"
        : "+f"(d[0]), "+f"(d[1]), "+f"(d[2]), "+f"(d[3])
        : "r"(a[0]), "r"(a[1]), "r"(a[2]), "r"(a[3]), "r"(b[0]), "r"(b[1]));
}

__device__ __forceinline__ void ldsm4(uint32_t* r, uint32_t a) {
    asm volatile(
        "ldmatrix.sync.aligned.m8n8.x4.shared.b16 {%0, %1, %2, %3}, [%4];"
        : "=r"(r[0]), "=r"(r[1]), "=r"(r[2]), "=r"(r[3])
        : "r"(a));
}

__device__ __forceinline__ uint32_t s2u(const void* p) {
    uint32_t a;
    asm("{ .reg .u64 t; cvta.to.shared.u64 t, %1; cvt.u32.u64 %0, t; }" : "=r"(a) : "l"(p));
    return a;
}

__device__ __forceinline__ void split_st(__nv_bfloat16* h, __nv_bfloat16* l, size_t idx,
                                         float v) {
    __nv_bfloat16 a = __float2bfloat16(v);
    h[idx] = a;
    l[idx] = __float2bfloat16(v - __bfloat162float(a));
}

#define SROW 56
#define TILE_B 14336
#define BUF_B 57344
#define TG_SMEM 114688

__device__ __forceinline__ void tg_issue(const __nv_bfloat16* A0, const __nv_bfloat16* A1,
                                         const __nv_bfloat16* B0, const __nv_bfloat16* B1,
                                         int m0, int n0, int K, int M, int N, int ch,
                                         uint32_t sbase, int tid) {
    const __nv_bfloat16* srcs[4] = {A0, A1, B0, B1};
    uint32_t dbase = sbase + (uint32_t)(ch & 1) * BUF_B;
#pragma unroll
    for (int t = 0; t < 4; t++) {
        const __nv_bfloat16* src = srcs[t];
        int r0 = (t < 2) ? m0 : n0;
        int lim = (t < 2) ? M : N;
#pragma unroll
        for (int it = 0; it < 2; it++) {
            int u = tid + it * 256;
            int row = u >> 2;
            int c = u & 3;
            int gr = r0 + row;
            if (gr >= lim) gr = lim - 1;
            const void* gp = src + (size_t)gr * K + ch * 32 + c * 8;
            uint32_t dst = dbase + (uint32_t)(t * TILE_B + row * 112 + c * 16);
            asm volatile("cp.async.cg.shared.global [%0], [%1], 16;"
                         :: "r"(dst), "l"(gp) : "memory");
        }
    }
    asm volatile("cp.async.commit_group;" ::: "memory");
}

// tensor GEMM via mma.sync + ldmatrix, cp.async double-buffered.
// C[M,N] = epi(alpha*(Ah+Al)@(Bh+Bl)^T + bias). A:[M,K] rm, B:[N,K] rm.
// epi: 0 none, 1 elu+1, 2 gelu.
// outm: 0 store, 1 heads-scatter, 2 +=, 3 rowscale-accum, 6 bf16-split merged.
__global__ void __launch_bounds__(256, 1) tg_k(
    int epi, int outm,
    const __nv_bfloat16* __restrict__ Ah, const __nv_bfloat16* __restrict__ Al,
    const __nv_bfloat16* __restrict__ Bh, const __nv_bfloat16* __restrict__ Bl,
    const float* __restrict__ bias, float* __restrict__ C,
    __nv_bfloat16* __restrict__ Ch, __nv_bfloat16* __restrict__ Cl,
    int M, int N, int K, int bsA, int bsB, int bsC, int bsBias, float alpha,
    const float* __restrict__ p1, const float* __restrict__ p2, int i1, int j2) {
    extern __shared__ char sm[];
    uint32_t sbase = s2u(sm);

    const int tid = threadIdx.x;
    const int lane = tid & 31;
    const int w = tid >> 5;
    const int g = lane >> 2;
    const int tc = lane & 3;
    const int wm = w >> 2;
    const int wn = w & 3;
    const int quad = lane >> 3;
    const int lrow = lane & 7;
    const int bz = blockIdx.z;
    const int m0 = blockIdx.y * 128;
    const int n0 = blockIdx.x * 128;

    const __nv_bfloat16* A0 = Ah + (size_t)bz * bsA;
    const __nv_bfloat16* A1 = Al + (size_t)bz * bsA;
    const __nv_bfloat16* B0 = Bh + (size_t)bz * bsB;
    const __nv_bfloat16* B1 = Bl + (size_t)bz * bsB;
    const float* bp = bias;
    if (bp) bp += (size_t)bz * bsBias;
    float* Cp = C ? C + (size_t)bz * bsC : (float*)0;

    // per-lane ldmatrix address offsets (bytes, within a tile)
    const uint32_t aoff =
        (uint32_t)((wm * 64 + lrow + ((quad & 1) << 3)) * 112 + ((quad >> 1) << 4));
    const uint32_t boff =
        (uint32_t)((wn * 32 + ((quad >> 1) << 3) + lrow) * 112 + ((quad & 1) << 4));

    float acc[4][4][4];
#pragma unroll
    for (int a = 0; a < 4; a++)
#pragma unroll
        for (int b = 0; b < 4; b++)
#pragma unroll
            for (int e = 0; e < 4; e++) acc[a][b][e] = 0.f;

    const int nch = K >> 5;
    tg_issue(A0, A1, B0, B1, m0, n0, K, M, N, 0, sbase, tid);

    for (int ch = 0; ch < nch; ch++) {
        if (ch + 1 < nch) {
            tg_issue(A0, A1, B0, B1, m0, n0, K, M, N, ch + 1, sbase, tid);
            asm volatile("cp.async.wait_group 1;" ::: "memory");
        } else {
            asm volatile("cp.async.wait_group 0;" ::: "memory");
        }
        __syncthreads();

        uint32_t buf = sbase + (uint32_t)(ch & 1) * BUF_B;
        uint32_t abase = buf + aoff;
        uint32_t bbase = buf + 2u * TILE_B + boff;

#pragma unroll
        for (int ks = 0; ks < 2; ks++) {
            uint32_t kso = (uint32_t)(ks * 32);
            uint32_t fAh[4][4], fAl[4][4], fBh[4][2], fBl[4][2];
#pragma unroll
            for (int mt = 0; mt < 4; mt++) {
                ldsm4(fAh[mt], abase + (uint32_t)(mt * 1792) + kso);
                ldsm4(fAl[mt], abase + TILE_B + (uint32_t)(mt * 1792) + kso);
            }
#pragma unroll
            for (int np = 0; np < 2; np++) {
                uint32_t tb[4];
                ldsm4(tb, bbase + (uint32_t)(np * 1792) + kso);
                fBh[np * 2][0] = tb[0];
                fBh[np * 2][1] = tb[1];
                fBh[np * 2 + 1][0] = tb[2];
                fBh[np * 2 + 1][1] = tb[3];
                ldsm4(tb, bbase + TILE_B + (uint32_t)(np * 1792) + kso);
                fBl[np * 2][0] = tb[0];
                fBl[np * 2][1] = tb[1];
                fBl[np * 2 + 1][0] = tb[2];
                fBl[np * 2 + 1][1] = tb[3];
            }
#pragma unroll
            for (int mt = 0; mt < 4; mt++)
#pragma unroll
                for (int nt = 0; nt < 4; nt++) {
                    mma16816(acc[mt][nt], fAh[mt], fBh[nt]);
                    mma16816(acc[mt][nt], fAh[mt], fBl[nt]);
                    mma16816(acc[mt][nt], fAl[mt], fBh[nt]);
                }
        }
        __syncthreads();
    }

#pragma unroll
    for (int mt = 0; mt < 4; mt++) {
#pragma unroll
        for (int eh = 0; eh < 2; eh++) {
            int row = m0 + wm * 64 + mt * 16 + g + eh * 8;
            float rs = 1.f;
            if (outm == 3) rs = p1[row * 4 + i1] * p2[row * 2 + j2];
#pragma unroll
            for (int nt = 0; nt < 4; nt++) {
#pragma unroll
                for (int ec = 0; ec < 2; ec++) {
                    int col = n0 + wn * 32 + nt * 8 + tc * 2 + ec;
                    if (col >= N) continue;
                    float v = acc[mt][nt][eh * 2 + ec] * alpha;
                    if (bp) v += bp[col];
                    if (epi == 1) v = (v > 0.f) ? (v + 1.f) : expf(v);
                    else if (epi == 2) v = gelu_f(v);
                    if (outm == 1) {
                        int b = row >> 10;
                        int s = row & 1023;
                        int h = col >> 6;
                        int hd = col & 63;
                        Cp[(((size_t)(b * CH + h)) << 16) + (s << 6) + hd] = v;
                    } else if (outm == 6) {
                        size_t idx = ((size_t)((bz >> 4) * 1024 + row)) * 1024 +
                                     (size_t)((bz & 15) * 64 + col);
                        split_st(Ch, Cl, idx, v);
                    } else {
                        size_t ci = (size_t)row * N + col;
                        if (outm == 0) Cp[ci] = v;
                        else if (outm == 2) Cp[ci] += v;
                        else Cp[ci] += rs * v;
                    }
                }
            }
        }
    }
}

// FFMA GEMM (performer only)
template <int BM, int BN, int BK, int TM, int TN>
__global__ void __launch_bounds__((BM / TM) * (BN / TN))
gemm_k(const float* __restrict__ A, const float* __restrict__ Bm, float* __restrict__ C,
       int M, int N, int K, int sam, int sak, int sbk, int sbn,
       int bsA, int bsB, int bsC, float alpha) {
    constexpr int RM = BM / TM, RN = BN / TN, NT = RM * RN;
    const int bz = blockIdx.z;
    A += (size_t)bz * bsA;
    Bm += (size_t)bz * bsB;
    C += (size_t)bz * bsC;
    const int m0 = blockIdx.y * BM, n0 = blockIdx.x * BN;
    __shared__ float As[BK][BM + 4];
    __shared__ float Bs[BK][BN + 4];
    const int tid = threadIdx.x, tx = tid % RN, ty = tid / RN;
    float acc[TM][TN];
#pragma unroll
    for (int i = 0; i < TM; i++)
#pragma unroll
        for (int j = 0; j < TN; j++) acc[i][j] = 0.f;
    for (int k0 = 0; k0 < K; k0 += BK) {
#pragma unroll
        for (int idx = tid; idx < BM * BK; idx += NT) {
            int mm = idx / BK, kk = idx % BK;
            As[kk][mm] = A[(size_t)(m0 + mm) * sam + (size_t)(k0 + kk) * sak];
        }
#pragma unroll
        for (int idx = tid; idx < BK * BN; idx += NT) {
            int kk = idx / BN, nn = idx % BN;
            Bs[kk][nn] = Bm[(size_t)(k0 + kk) * sbk + (size_t)(n0 + nn) * sbn];
        }
        __syncthreads();
#pragma unroll
        for (int kk = 0; kk < BK; ++kk) {
            float ra[TM], rb[TN];
#pragma unroll
            for (int i = 0; i < TM; i++) ra[i] = As[kk][ty + i * RM];
#pragma unroll
            for (int j = 0; j < TN; j++) rb[j] = Bs[kk][tx + j * RN];
#pragma unroll
            for (int i = 0; i < TM; i++)
#pragma unroll
                for (int j = 0; j < TN; j++) acc[i][j] = fmaf(ra[i], rb[j], acc[i][j]);
        }
        __syncthreads();
    }
#pragma unroll
    for (int i = 0; i < TM; i++)
#pragma unroll
        for (int j = 0; j < TN; j++)
            C[(size_t)(m0 + ty + i * RM) * N + n0 + tx + j * RN] = acc[i][j] * alpha;
}

__global__ void zero_k(float* p, int n) {
    int i = blockIdx.x * blockDim.x + threadIdx.x;
    if (i < n) p[i] = 0.f;
}

template <int ACT>
__global__ void ln_k(float* __restrict__ y, const float* __restrict__ g,
                     const float* __restrict__ be, int N, int rpg, int pstride) {
    int row = blockIdx.x;
    int grp = row / rpg;
    const float* gp = g + (size_t)grp * pstride;
    const float* bpp = be + (size_t)grp * pstride;
    float* yr = y + (size_t)row * N;
    float s = 0.f, q = 0.f;
    for (int c = threadIdx.x; c < N; c += blockDim.x) {
        float v = yr[c];
        s += v;
        q += v * v;
    }
    s = brs(s);
    q = brs(q);
    float mean = s / N;
    float inv = rsqrtf(q / N - mean * mean + 1e-5f);
    for (int c = threadIdx.x; c < N; c += blockDim.x) {
        float v = (yr[c] - mean) * inv * gp[c] + bpp[c];
        if (ACT == 1) v = fmaxf(v, 0.f);
        if (ACT == 2) v = gelu_f(v);
        yr[c] = v;
    }
}

// softmax over S cols; writes P as bf16 hi/lo
__global__ void softmax_k(const float* __restrict__ sc, const float* __restrict__ mask,
                          __nv_bfloat16* __restrict__ ph, __nv_bfloat16* __restrict__ pl) {
    int row = blockIdx.x;
    int b = row / (CH * CS);
    const float* r = sc + (size_t)row * CS;
    int t = threadIdx.x;
    float v[4];
    float mx = -3.4e38f;
#pragma unroll
    for (int i = 0; i < 4; i++) {
        int c = t + i * 256;
        float xv = r[c];
        if (mask) xv *= mask[b * CS + c];
        v[i] = xv;
        mx = fmaxf(mx, xv);
    }
    mx = brm(mx);
    float s = 0.f;
#pragma unroll
    for (int i = 0; i < 4; i++) {
        v[i] = __expf(v[i] - mx);
        s += v[i];
    }
    s = brs(s);
    float inv = 1.f / s;
#pragma unroll
    for (int i = 0; i < 4; i++) {
        size_t idx = (size_t)row * CS + t + i * 256;
        split_st(ph, pl, idx, v[i] * inv);
    }
}

__global__ void router_k(const float* __restrict__ h, const float* __restrict__ w,
                         const float* __restrict__ bias, float* __restrict__ probs,
                         int K, int NOUT) {
    __shared__ float red[512];
    int row = blockIdx.x, t = threadIdx.x;
    const float* hr = h + (size_t)row * K;
    float part[4] = {0.f, 0.f, 0.f, 0.f};
    for (int k = t; k < K; k += 128) {
        float hv = hr[k];
        for (int o = 0; o < NOUT; o++) part[o] += hv * w[k * NOUT + o];
    }
    for (int o = 0; o < 4; o++) red[t * 4 + o] = part[o];
    __syncthreads();
    for (int s = 64; s > 0; s >>= 1) {
        if (t < s)
            for (int o = 0; o < 4; o++) red[t * 4 + o] += red[(t + s) * 4 + o];
        __syncthreads();
    }
    if (t == 0) {
        float lg[4];
        float mx = -3.4e38f;
        for (int o = 0; o < NOUT; o++) {
            lg[o] = red[o] + bias[o];
            mx = fmaxf(mx, lg[o]);
        }
        float s = 0.f;
        for (int o = 0; o < NOUT; o++) {
            lg[o] = expf(lg[o] - mx);
            s += lg[o];
        }
        for (int o = 0; o < NOUT; o++) probs[row * NOUT + o] = lg[o] / s;
    }
}

__global__ void gemv_k(const float* __restrict__ x, const float* __restrict__ w,
                       const float* __restrict__ b, float* __restrict__ out) {
    int row = blockIdx.x;
    const float* xr = x + (size_t)row * CD;
    float s = 0.f;
    for (int k = threadIdx.x; k < CD; k += blockDim.x) s += xr[k] * w[k];
    s = brs(s);
    if (threadIdx.x == 0) out[row] = s + b[0];
}

__global__ void topk_mask_k(const float* __restrict__ imp, float* __restrict__ mask) {
    __shared__ float vals[1024];
    __shared__ float rv[1024];
    __shared__ int ri[1024];
    int b = blockIdx.x, t = threadIdx.x;
    vals[t] = imp[b * CS + t];
    mask[b * CS + t] = 0.f;
    __syncthreads();
    for (int it = 0; it < CTOPK; it++) {
        rv[t] = vals[t];
        ri[t] = t;
        __syncthreads();
        for (int s = 512; s > 0; s >>= 1) {
            if (t < s) {
                if (rv[t + s] > rv[t] || (rv[t + s] == rv[t] && ri[t + s] < ri[t])) {
                    rv[t] = rv[t + s];
                    ri[t] = ri[t + s];
                }
            }
            __syncthreads();
        }
        if (t == 0) {
            mask[b * CS + ri[0]] = 1.f;
            vals[ri[0]] = -3.4e38f;
        }
        __syncthreads();
    }
}

__global__ void dwconv_k(const float* __restrict__ x, const float* __restrict__ dw,
                         float* __restrict__ o) {
    int idx = blockIdx.x * blockDim.x + threadIdx.x;
    if (idx >= CM * CD) return;
    int d = idx & (CD - 1);
    int s = (idx >> 10) & (CS - 1);
    float acc = x[idx] * dw[CD + d];
    if (s > 0) acc += x[idx - CD] * dw[d];
    if (s < CS - 1) acc += x[idx + CD] * dw[2 * CD + d];
    o[idx] = acc;
}

__global__ void merge_k(const float* __restrict__ hin, float* __restrict__ o) {
    int idx = blockIdx.x * blockDim.x + threadIdx.x;
    if (idx >= CM * CD) return;
    int n = idx & 1023;
    int m = idx >> 10;
    int b = m >> 10, s = m & 1023, h = n >> 6, hd = n & 63;
    o[idx] = hin[(((size_t)(b * CH + h)) << 16) + (s << 6) + hd];
}

__global__ void colsum_k(const float* __restrict__ kpsi, float* __restrict__ ksum) {
    int bz = blockIdx.x;
    int d = threadIdx.x;
    const float* base = kpsi + (size_t)bz * CS * CKD + d;
    float s = 0.f;
    for (int l = 0; l < CS; l++) s += base[(size_t)l * CKD];
    ksum[bz * CKD + d] = s;
}

__global__ void perf_norm_k(float* __restrict__ num, const float* __restrict__ qphi,
                            const float* __restrict__ ksum) {
    int row = blockIdx.x;
    int bz = row / CS;
    int t = threadIdx.x;
    float p = qphi[(size_t)row * CKD + t] * ksum[bz * CKD + t];
    float den = brs(p) + 1e-8f;
    float inv = 1.f / den;
    if (t < CHD) num[(size_t)row * CHD + t] *= inv;
}

__global__ void convA(const float* __restrict__ s, __nv_bfloat16* __restrict__ h,
                      __nv_bfloat16* __restrict__ l, int n, float scale) {
    int i = blockIdx.x * 256 + threadIdx.x;
    if (i < n) {
        float v = s[i] * scale;
        split_st(h, l, i, v);
    }
}

// V heads [bh][s][hd] fp32 -> V^T [bh][hd][s] bf16 hi/lo
__global__ void vtrans_k(const float* __restrict__ v, __nv_bfloat16* __restrict__ th,
                         __nv_bfloat16* __restrict__ tl) {
    __shared__ float tt[32][33];
    int bh = blockIdx.z;
    int s0 = blockIdx.x * 32;
    int d0 = blockIdx.y * 32;
    const float* vp = v + (size_t)bh * 65536;
    for (int i = threadIdx.y; i < 32; i += 8)
        tt[i][threadIdx.x] = vp[(size_t)(s0 + i) * 64 + d0 + threadIdx.x];
    __syncthreads();
    for (int i = threadIdx.y; i < 32; i += 8) {
        float val = tt[threadIdx.x][i];
        size_t idx = (size_t)bh * 65536 + (size_t)(d0 + i) * 1024 + s0 + threadIdx.x;
        split_st(th, tl, idx, val);
    }
}

__global__ void convWT(const float* __restrict__ src, __nv_bfloat16* __restrict__ dh,
                       __nv_bfloat16* __restrict__ dl, int K, int N) {
    __shared__ float tt[32][33];
    int b = blockIdx.z;
    src += (size_t)b * K * N;
    dh += (size_t)b * K * N;
    dl += (size_t)b * K * N;
    int k0 = blockIdx.x * 32, n0 = blockIdx.y * 32;
    for (int i = threadIdx.y; i < 32; i += 8)
        tt[i][threadIdx.x] = src[(size_t)(k0 + i) * N + n0 + threadIdx.x];
    __syncthreads();
    for (int i = threadIdx.y; i < 32; i += 8) {
        float v = tt[threadIdx.x][i];
        size_t o = (size_t)(n0 + i) * K + k0 + threadIdx.x;
        split_st(dh, dl, o, v);
    }
}

static float* symaddr(const void* s) {
    void* p = 0;
    cudaGetSymbolAddress(&p, s);
    return (float*)p;
}
static __nv_bfloat16* symb(const void* s) {
    void* p = 0;
    cudaGetSymbolAddress(&p, s);
    return (__nv_bfloat16*)p;
}

static void tgl(int epi, int outm, const __nv_bfloat16* Ah, const __nv_bfloat16* Al,
                const __nv_bfloat16* Bh, const __nv_bfloat16* Bl, const float* bias,
                float* C, __nv_bfloat16* Ch, __nv_bfloat16* Cl,
                int M, int N, int K, int bsA, int bsB, int bsC, int bsBias, int batch,
                float alpha, const float* p1, const float* p2, int i1, int j2) {
    dim3 g((N + 127) / 128, M / 128, batch);
    tg_k<<<g, 256, TG_SMEM>>>(epi, outm, Ah, Al, Bh, Bl, bias, C, Ch, Cl, M, N, K,
                              bsA, bsB, bsC, bsBias, alpha, p1, p2, i1, j2);
}

extern "C" void kernel_launch(void* const* d_in, const int* in_sizes, int n_in,
                              void* d_out, int out_size) {
    const float* x = (const float*)d_in[0];
    const float* w_qkvo = (const float*)d_in[1];
    const float* b_qkvo = (const float*)d_in[2];
    const float* sp_w = (const float*)d_in[3];
    const float* sp_b = (const float*)d_in[4];
    const float* phi_w = (const float*)d_in[5];
    const float* phi_b = (const float*)d_in[6];
    const float* psi_w = (const float*)d_in[7];
    const float* psi_b = (const float*)d_in[8];
    const float* conv_dw = (const float*)d_in[9];
    const float* conv_pw = (const float*)d_in[10];
    const float* fus_w = (const float*)d_in[11];
    const float* fus_b = (const float*)d_in[12];
    const float* sub_w1 = (const float*)d_in[13];
    const float* sub_b1 = (const float*)d_in[14];
    const float* sub_g = (const float*)d_in[15];
    const float* sub_be = (const float*)d_in[16];
    const float* sub_w2 = (const float*)d_in[17];
    const float* sub_b2 = (const float*)d_in[18];
    const float* r1_w1 = (const float*)d_in[19];
    const float* r1_b1 = (const float*)d_in[20];
    const float* r1_g = (const float*)d_in[21];
    const float* r1_be = (const float*)d_in[22];
    const float* r1_w2 = (const float*)d_in[23];
    const float* r1_b2 = (const float*)d_in[24];
    const float* r2_w1 = (const float*)d_in[25];
    const float* r2_b1 = (const float*)d_in[26];
    const float* r2_g = (const float*)d_in[27];
    const float* r2_be = (const float*)d_in[28];
    const float* r2_w2 = (const float*)d_in[29];
    const float* r2_b2 = (const float*)d_in[30];
    float* out = (float*)d_out;

    cudaFuncSetAttribute(tg_k, cudaFuncAttributeMaxDynamicSharedMemorySize, TG_SMEM);

    float* q = symaddr(g_qkv);
    float* k = q + 2097152;
    float* v = q + 4194304;
    float* scores = symaddr(g_scores);
    float* attn = symaddr(g_attn);
    float* mrg = symaddr(g_merge);
    float* eo = symaddr(g_eo);
    float* ao = symaddr(g_ao);
    float* xc = symaddr(g_xc);
    float* cnv = symaddr(g_conv);
    float* t1 = symaddr(g_t1);
    float* qphi = symaddr(g_qphi);
    float* kpsi = symaddr(g_kpsi);
    float* kv = symaddr(g_kv);
    float* ksum = symaddr(g_ksum);
    float* h1 = symaddr(g_h1);
    float* h2 = symaddr(g_h2);
    float* p1 = symaddr(g_p1);
    float* p2 = symaddr(g_p2);
    float* imp = symaddr(g_imp);
    float* msk = symaddr(g_mask);
    __nv_bfloat16* xbh = symb(xb_h);
    __nv_bfloat16* xbl = symb(xb_l);
    __nv_bfloat16* qhh = symb(qh_h);
    __nv_bfloat16* qhl = symb(qh_l);
    __nv_bfloat16* khh = symb(kh_h);
    __nv_bfloat16* khl = symb(kh_l);
    __nv_bfloat16* cvh = symb(cv_h);
    __nv_bfloat16* cvl = symb(cv_l);
    __nv_bfloat16* xch = symb(xc_h);
    __nv_bfloat16* xcl = symb(xc_l);
    __nv_bfloat16* aoh = symb(ao_h);
    __nv_bfloat16* aol = symb(ao_l);
    __nv_bfloat16* mgh = symb(mg_h);
    __nv_bfloat16* mgl = symb(mg_l);
    __nv_bfloat16* eoh = symb(eo_h);
    __nv_bfloat16* eol = symb(eo_l);
    __nv_bfloat16* t1h = symb(t1_h);
    __nv_bfloat16* t1l = symb(t1_l);
    __nv_bfloat16* wqh = symb(wq_h);
    __nv_bfloat16* wql = symb(wq_l);
    __nv_bfloat16* s1h = symb(s1_h);
    __nv_bfloat16* s1l = symb(s1_l);
    __nv_bfloat16* s2h = symb(s2_h);
    __nv_bfloat16* s2l = symb(s2_l);
    __nv_bfloat16* fwh = symb(fw_h);
    __nv_bfloat16* fwl = symb(fw_l);
    __nv_bfloat16* cwh = symb(cw_h);
    __nv_bfloat16* cwl = symb(cw_l);
    __nv_bfloat16* r1h = symb(r1_h);
    __nv_bfloat16* r1l = symb(r1_l);
    __nv_bfloat16* r2h = symb(r2_h);
    __nv_bfloat16* r2l = symb(r2_l);
    __nv_bfloat16* phh = symb(ph_h);
    __nv_bfloat16* phl = symb(ph_l);
    __nv_bfloat16* psh = symb(ps_h);
    __nv_bfloat16* psl = symb(ps_l);
    __nv_bfloat16* vth = symb(vt_h);
    __nv_bfloat16* vtl = symb(vt_l);
    __nv_bfloat16* pbh = symb(pb_h);
    __nv_bfloat16* pbl = symb(pb_l);
    const float* NP = (const float*)0;
    float* NF = (float*)0;
    __nv_bfloat16* NB = (__nv_bfloat16*)0;

    dim3 tb(32, 8);
    // prologue ordered so launch #6 is the first tg_k (ncu -s 5 captures it)
    convWT<<<dim3(32, 16, 1), tb>>>(r1_w1, r1h, r1l, 1024, 512);
    convA<<<8192, 256>>>(x, xbh, xbl, CM * CD, 1.f);
    zero_k<<<8192, 256>>>(out, CM * CD);
    gemv_k<<<CM, 256>>>(x, sp_w, sp_b, imp);
    topk_mask_k<<<CB, 1024>>>(imp, msk);

    tgl(0, 0, xbh, xbl, r1h, r1l, r1_b1, h1, NB, NB, CM, 512, CD, 0, 0, 0, 0, 1, 1.f,
        NP, NP, 0, 0);
    ln_k<1><<<CM, 256>>>(h1, r1_g, r1_be, 512, CM, 0);
    router_k<<<CM, 128>>>(h1, r1_w2, r1_b2, p1, 512, 4);

    convWT<<<dim3(32, 32, 16), tb>>>(w_qkvo, wqh, wql, 1024, 1024);
    convWT<<<dim3(32, 32, 8), tb>>>(sub_w1, s1h, s1l, 1024, 1024);
    convWT<<<dim3(32, 32, 8), tb>>>(sub_w2, s2h, s2l, 1024, 1024);
    convWT<<<dim3(32, 32, 2), tb>>>(fus_w, fwh, fwl, 1024, 1024);
    convWT<<<dim3(32, 32, 1), tb>>>(conv_pw, cwh, cwl, 1024, 1024);
    convWT<<<dim3(32, 8, 4), tb>>>(r2_w1, r2h, r2l, 1024, 256);
    convWT<<<dim3(2, 8, 1), tb>>>(phi_w, phh, phl, 64, 256);
    convWT<<<dim3(2, 8, 1), tb>>>(psi_w, psh, psl, 64, 256);

    for (int i = 0; i < 4; i++) {
        const float* bb = b_qkvo + (size_t)i * 4 * CD;
        tgl(0, 1, xbh, xbl, wqh + (size_t)i * 4194304, wql + (size_t)i * 4194304, bb, q,
            NB, NB, CM, CD, CD, 0, 1048576, 2097152, CD, 3, 1.f, NP, NP, 0, 0);
        const __nv_bfloat16* woh = wqh + (size_t)(i * 4 + 3) * 1048576;
        const __nv_bfloat16* wol = wql + (size_t)(i * 4 + 3) * 1048576;

        if (i == 1) {
            convA<<<8192, 256>>>(q, qhh, qhl, 2097152, 1.f);
            convA<<<8192, 256>>>(k, khh, khl, 2097152, 1.f);
            tgl(1, 0, qhh, qhl, phh, phl, phi_b, qphi, NB, NB, CBH * CS, CKD, CHD,
                0, 0, 0, 0, 1, 1.f, NP, NP, 0, 0);
            tgl(1, 0, khh, khl, psh, psl, psi_b, kpsi, NB, NB, CBH * CS, CKD, CHD,
                0, 0, 0, 0, 1, 1.f, NP, NP, 0, 0);
            gemm_k<64, 64, 16, 4, 4><<<dim3(1, 4, CBH), 256>>>(
                kpsi, v, kv, CKD, CHD, CS, 1, CKD, CHD, 1,
                CS * CKD, CS * CHD, CKD * CHD, 1.f);
            colsum_k<<<CBH, 256>>>(kpsi, ksum);
            gemm_k<64, 64, 16, 4, 4><<<dim3(1, 16, CBH), 256>>>(
                qphi, kv, attn, CS, CHD, CKD, CKD, 1, CHD, 1,
                CS * CKD, CKD * CHD, CS * CHD, 1.f);
            perf_norm_k<<<CBH * CS, 256>>>(attn, qphi, ksum);
            merge_k<<<8192, 256>>>(attn, mrg);
            convA<<<8192, 256>>>(mrg, mgh, mgl, CM * CD, 1.f);
            tgl(0, 0, mgh, mgl, woh, wol, bb + 3 * CD, eo, NB, NB, CM, CD, CD,
                0, 0, 0, 0, 1, 1.f, NP, NP, 0, 0);
        } else {
            convA<<<8192, 256>>>(q, qhh, qhl, 2097152, 0.125f);
            convA<<<8192, 256>>>(k, khh, khl, 2097152, 1.f);
            vtrans_k<<<dim3(32, 2, CBH), tb>>>(v, vth, vtl);
            tgl(0, 0, qhh, qhl, khh, khl, NP, scores, NB, NB, CS, CS, CHD,
                65536, 65536, 1048576, 0, CBH, 1.f, NP, NP, 0, 0);
            softmax_k<<<CBH * CS, 256>>>(scores, (i == 0) ? msk : NP, pbh, pbl);
            tgl(0, 6, pbh, pbl, vth, vtl, NP, NF, mgh, mgl, CS, CHD, CS,
                1048576, 65536, 0, 0, CBH, 1.f, NP, NP, 0, 0);
            if (i == 3) {
                dwconv_k<<<8192, 256>>>(x, conv_dw, cnv);
                convA<<<8192, 256>>>(cnv, cvh, cvl, CM * CD, 1.f);
                tgl(2, 0, cvh, cvl, cwh, cwl, NP, xc, NB, NB, CM, CD, CD,
                    0, 0, 0, 0, 1, 1.f, NP, NP, 0, 0);
                tgl(0, 0, mgh, mgl, woh, wol, bb + 3 * CD, ao, NB, NB, CM, CD, CD,
                    0, 0, 0, 0, 1, 1.f, NP, NP, 0, 0);
                convA<<<8192, 256>>>(ao, aoh, aol, CM * CD, 1.f);
                convA<<<8192, 256>>>(xc, xch, xcl, CM * CD, 1.f);
                tgl(0, 0, aoh, aol, fwh, fwl, fus_b, eo, NB, NB, CM, CD, CD,
                    0, 0, 0, 0, 1, 1.f, NP, NP, 0, 0);
                tgl(0, 2, xch, xcl, fwh + 1048576, fwl + 1048576, NP, eo, NB, NB,
                    CM, CD, CD, 0, 0, 0, 0, 1, 1.f, NP, NP, 0, 0);
            } else {
                tgl(0, 0, mgh, mgl, woh, wol, bb + 3 * CD, eo, NB, NB, CM, CD, CD,
                    0, 0, 0, 0, 1, 1.f, NP, NP, 0, 0);
            }
        }
        convA<<<8192, 256>>>(eo, eoh, eol, CM * CD, 1.f);

        tgl(0, 0, eoh, eol, r2h + (size_t)i * 262144, r2l + (size_t)i * 262144,
            r2_b1 + i * 256, h2, NB, NB, CM, 256, CD, 0, 0, 0, 0, 1, 1.f, NP, NP, 0, 0);
        ln_k<1><<<CM, 256>>>(h2, r2_g + i * 256, r2_be + i * 256, 256, CM, 0);
        router_k<<<CM, 128>>>(h2, r2_w2 + (size_t)i * 512, r2_b2 + i * 2, p2, 256, 2);

        tgl(0, 0, eoh, eol, s1h + (size_t)i * 2097152, s1l + (size_t)i * 2097152,
            sub_b1 + (size_t)i * 2 * CD, t1, NB, NB, CM, CD, CD, 0, 1048576, 2097152,
            CD, 2, 1.f, NP, NP, 0, 0);
        ln_k<2><<<2 * CM, 256>>>(t1, sub_g + (size_t)i * 2 * CD, sub_be + (size_t)i * 2 * CD,
                                 CD, CM, CD);
        convA<<<16384, 256>>>(t1, t1h, t1l, 2 * CM * CD, 1.f);
        for (int j = 0; j < 2; j++) {
            tgl(0, 3, t1h + (size_t)j * 2097152, t1l + (size_t)j * 2097152,
                s2h + (size_t)(i * 2 + j) * 1048576, s2l + (size_t)(i * 2 + j) * 1048576,
                sub_b2 + (size_t)(i * 2 + j) * CD, out, NB, NB, CM, CD, CD,
                0, 0, 0, 0, 1, 1.f, p1, p2, i, j);
        }
    }
}

// round 14
// speedup vs baseline: 1.3305x; 1.0314x over previous
#include <cuda_runtime.h>
#include <cuda_bf16.h>
#include <math.h>
#include <stdint.h>
#include <cstdint>

#define CB 2
#define CS 1024
#define CD 1024
#define CH 16
#define CHD 64
#define CKD 256
#define CTOPK 10
#define CM 2048
#define CBH 32

__device__ float g_qkv[6291456];
__device__ float g_scores[33554432];
__device__ float g_attn[2097152];
__device__ float g_merge[2097152];
__device__ float g_eo[2097152];
__device__ float g_ao[2097152];
__device__ float g_xc[2097152];
__device__ float g_conv[2097152];
__device__ float g_t1[4194304];
__device__ float g_qphi[8388608];
__device__ float g_kpsi[8388608];
__device__ float g_kv[524288];
__device__ float g_ksum[8192];
__device__ float g_h1[1048576];
__device__ float g_h2[524288];
__device__ float g_p1[8192];
__device__ float g_p2[4096];
__device__ float g_imp[2048];
__device__ float g_mask[2048];

__device__ __nv_bfloat16 xb_h[2097152], xb_l[2097152];
__device__ __nv_bfloat16 qh_h[2097152], qh_l[2097152];
__device__ __nv_bfloat16 kh_h[2097152], kh_l[2097152];
__device__ __nv_bfloat16 cv_h[2097152], cv_l[2097152];
__device__ __nv_bfloat16 xc_h[2097152], xc_l[2097152];
__device__ __nv_bfloat16 ao_h[2097152], ao_l[2097152];
__device__ __nv_bfloat16 mg_h[2097152], mg_l[2097152];
__device__ __nv_bfloat16 eo_h[2097152], eo_l[2097152];
__device__ __nv_bfloat16 t1_h[4194304], t1_l[4194304];
__device__ __nv_bfloat16 wq_h[16777216], wq_l[16777216];
__device__ __nv_bfloat16 s1_h[8388608], s1_l[8388608];
__device__ __nv_bfloat16 s2_h[8388608], s2_l[8388608];
__device__ __nv_bfloat16 fw_h[2097152], fw_l[2097152];
__device__ __nv_bfloat16 cw_h[1048576], cw_l[1048576];
__device__ __nv_bfloat16 r1_h[524288], r1_l[524288];
__device__ __nv_bfloat16 r2_h[1048576], r2_l[1048576];
__device__ __nv_bfloat16 ph_h[16384], ph_l[16384];
__device__ __nv_bfloat16 ps_h[16384], ps_l[16384];
__device__ __nv_bfloat16 vt_h[2097152], vt_l[2097152];
__device__ __nv_bfloat16 pb_h[33554432], pb_l[33554432];

__device__ __forceinline__ float gelu_f(float v) {
    float c = 0.7978845608028654f * (v + 0.044715f * v * v * v);
    return 0.5f * v * (1.f + tanhf(c));
}

__device__ __forceinline__ float brs(float v) {
    __shared__ float sh[32];
    __syncthreads();
    int lane = threadIdx.x & 31;
    int wd = threadIdx.x >> 5;
#pragma unroll
    for (int o = 16; o > 0; o >>= 1) v += __shfl_xor_sync(0xffffffffu, v, o);
    if (lane == 0) sh[wd] = v;
    __syncthreads();
    int nw = (blockDim.x + 31) >> 5;
    v = (threadIdx.x < nw) ? sh[threadIdx.x] : 0.f;
    if (wd == 0) {
#pragma unroll
        for (int o = 16; o > 0; o >>= 1) v += __shfl_xor_sync(0xffffffffu, v, o);
        if (lane == 0) sh[0] = v;
    }
    __syncthreads();
    return sh[0];
}

__device__ __forceinline__ float brm(float v) {
    __shared__ float sh[32];
    __syncthreads();
    int lane = threadIdx.x & 31;
    int wd = threadIdx.x >> 5;
#pragma unroll
    for (int o = 16; o > 0; o >>= 1) v = fmaxf(v, __shfl_xor_sync(0xffffffffu, v, o));
    if (lane == 0) sh[wd] = v;
    __syncthreads();
    int nw = (blockDim.x + 31) >> 5;
    v = (threadIdx.x < nw) ? sh[threadIdx.x] : -3.4e38f;
    if (wd == 0) {
#pragma unroll
        for (int o = 16; o > 0; o >>= 1) v = fmaxf(v, __shfl_xor_sync(0xffffffffu, v, o));
        if (lane == 0) sh[0] = v;
    }
    __syncthreads();
    return sh[0];
}

__device__ __forceinline__ void mma16816(float* d, const uint32_t* a, const uint32_t* b) {
    asm volatile(
        "mma.sync.aligned.m16n8k16.row.col.f32.bf16.bf16.f32 "
        "{%0, %1, %2, %3}, {%4, %5, %6, %7}, {%8, %9}, {%0, %1, %2, %3};"
        : "+f"(d[0]), "+f"(d[1]), "+f"(d[2]), "+f"(d[3])
        : "r"(a[0]), "r"(a[1]), "r"(a[2]), "r"(a[3]), "r"(b[0]), "r"(b[1]));
}

__device__ __forceinline__ void ldsm4(uint32_t* r, uint32_t a) {
    asm volatile(
        "ldmatrix.sync.aligned.m8n8.x4.shared.b16 {%0, %1, %2, %3}, [%4];"
        : "=r"(r[0]), "=r"(r[1]), "=r"(r[2]), "=r"(r[3])
        : "r"(a));
}

__device__ __forceinline__ uint32_t s2u(const void* p) {
    uint32_t a;
    asm("{ .reg .u64 t; cvta.to.shared.u64 t, %1; cvt.u32.u64 %0, t; }" : "=r"(a) : "l"(p));
    return a;
}

__device__ __forceinline__ void split_st(__nv_bfloat16* h, __nv_bfloat16* l, size_t idx,
                                         float v) {
    __nv_bfloat16 a = __float2bfloat16(v);
    h[idx] = a;
    l[idx] = __float2bfloat16(v - __bfloat162float(a));
}

#define SROW 56
#define TILE_B 14336
#define BUF_B 57344
#define TG_SMEM 114688

__device__ __forceinline__ void tg_issue(const __nv_bfloat16* A0, const __nv_bfloat16* A1,
                                         const __nv_bfloat16* B0, const __nv_bfloat16* B1,
                                         int m0, int n0, int K, int M, int N, int ch,
                                         uint32_t sbase, int tid) {
    const __nv_bfloat16* srcs[4] = {A0, A1, B0, B1};
    uint32_t dbase = sbase + (uint32_t)(ch & 1) * BUF_B;
#pragma unroll
    for (int t = 0; t < 4; t++) {
        const __nv_bfloat16* src = srcs[t];
        int r0 = (t < 2) ? m0 : n0;
        int lim = (t < 2) ? M : N;
#pragma unroll
        for (int it = 0; it < 2; it++) {
            int u = tid + it * 256;
            int row = u >> 2;
            int c = u & 3;
            int gr = r0 + row;
            if (gr >= lim) gr = lim - 1;
            const void* gp = src + (size_t)gr * K + ch * 32 + c * 8;
            uint32_t dst = dbase + (uint32_t)(t * TILE_B + row * 112 + c * 16);
            asm volatile("cp.async.cg.shared.global [%0], [%1], 16;"
                         :: "r"(dst), "l"(gp) : "memory");
        }
    }
    asm volatile("cp.async.commit_group;" ::: "memory");
}

// tensor GEMM via mma.sync + ldmatrix, cp.async double-buffered (tile 128x128).
__global__ void __launch_bounds__(256, 1) tg_k(
    int epi, int outm,
    const __nv_bfloat16* __restrict__ Ah, const __nv_bfloat16* __restrict__ Al,
    const __nv_bfloat16* __restrict__ Bh, const __nv_bfloat16* __restrict__ Bl,
    const float* __restrict__ bias, float* __restrict__ C,
    __nv_bfloat16* __restrict__ Ch, __nv_bfloat16* __restrict__ Cl,
    int M, int N, int K, int bsA, int bsB, int bsC, int bsBias, float alpha,
    const float* __restrict__ p1, const float* __restrict__ p2, int i1, int j2) {
    extern __shared__ char sm[];
    uint32_t sbase = s2u(sm);

    const int tid = threadIdx.x;
    const int lane = tid & 31;
    const int w = tid >> 5;
    const int g = lane >> 2;
    const int tc = lane & 3;
    const int wm = w >> 2;
    const int wn = w & 3;
    const int quad = lane >> 3;
    const int lrow = lane & 7;
    const int bz = blockIdx.z;
    const int m0 = blockIdx.y * 128;
    const int n0 = blockIdx.x * 128;

    const __nv_bfloat16* A0 = Ah + (size_t)bz * bsA;
    const __nv_bfloat16* A1 = Al + (size_t)bz * bsA;
    const __nv_bfloat16* B0 = Bh + (size_t)bz * bsB;
    const __nv_bfloat16* B1 = Bl + (size_t)bz * bsB;
    const float* bp = bias;
    if (bp) bp += (size_t)bz * bsBias;
    float* Cp = C ? C + (size_t)bz * bsC : (float*)0;

    const uint32_t aoff =
        (uint32_t)((wm * 64 + lrow + ((quad & 1) << 3)) * 112 + ((quad >> 1) << 4));
    const uint32_t boff =
        (uint32_t)((wn * 32 + ((quad >> 1) << 3) + lrow) * 112 + ((quad & 1) << 4));

    float acc[4][4][4];
#pragma unroll
    for (int a = 0; a < 4; a++)
#pragma unroll
        for (int b = 0; b < 4; b++)
#pragma unroll
            for (int e = 0; e < 4; e++) acc[a][b][e] = 0.f;

    const int nch = K >> 5;
    tg_issue(A0, A1, B0, B1, m0, n0, K, M, N, 0, sbase, tid);

    for (int ch = 0; ch < nch; ch++) {
        if (ch + 1 < nch) {
            tg_issue(A0, A1, B0, B1, m0, n0, K, M, N, ch + 1, sbase, tid);
            asm volatile("cp.async.wait_group 1;" ::: "memory");
        } else {
            asm volatile("cp.async.wait_group 0;" ::: "memory");
        }
        __syncthreads();

        uint32_t buf = sbase + (uint32_t)(ch & 1) * BUF_B;
        uint32_t abase = buf + aoff;
        uint32_t bbase = buf + 2u * TILE_B + boff;

#pragma unroll
        for (int ks = 0; ks < 2; ks++) {
            uint32_t kso = (uint32_t)(ks * 32);
            uint32_t fAh[4][4], fAl[4][4], fBh[4][2], fBl[4][2];
#pragma unroll
            for (int mt = 0; mt < 4; mt++) {
                ldsm4(fAh[mt], abase + (uint32_t)(mt * 1792) + kso);
                ldsm4(fAl[mt], abase + TILE_B + (uint32_t)(mt * 1792) + kso);
            }
#pragma unroll
            for (int np = 0; np < 2; np++) {
                uint32_t tb[4];
                ldsm4(tb, bbase + (uint32_t)(np * 1792) + kso);
                fBh[np * 2][0] = tb[0];
                fBh[np * 2][1] = tb[1];
                fBh[np * 2 + 1][0] = tb[2];
                fBh[np * 2 + 1][1] = tb[3];
                ldsm4(tb, bbase + TILE_B + (uint32_t)(np * 1792) + kso);
                fBl[np * 2][0] = tb[0];
                fBl[np * 2][1] = tb[1];
                fBl[np * 2 + 1][0] = tb[2];
                fBl[np * 2 + 1][1] = tb[3];
            }
#pragma unroll
            for (int mt = 0; mt < 4; mt++)
#pragma unroll
                for (int nt = 0; nt < 4; nt++) {
                    mma16816(acc[mt][nt], fAh[mt], fBh[nt]);
                    mma16816(acc[mt][nt], fAh[mt], fBl[nt]);
                    mma16816(acc[mt][nt], fAl[mt], fBh[nt]);
                }
        }
        __syncthreads();
    }

#pragma unroll
    for (int mt = 0; mt < 4; mt++) {
#pragma unroll
        for (int eh = 0; eh < 2; eh++) {
            int row = m0 + wm * 64 + mt * 16 + g + eh * 8;
            float rs = 1.f;
            if (outm == 3) rs = p1[row * 4 + i1] * p2[row * 2 + j2];
#pragma unroll
            for (int nt = 0; nt < 4; nt++) {
#pragma unroll
                for (int ec = 0; ec < 2; ec++) {
                    int col = n0 + wn * 32 + nt * 8 + tc * 2 + ec;
                    if (col >= N) continue;
                    float v = acc[mt][nt][eh * 2 + ec] * alpha;
                    if (bp) v += bp[col];
                    if (epi == 1) v = (v > 0.f) ? (v + 1.f) : expf(v);
                    else if (epi == 2) v = gelu_f(v);
                    if (outm == 1) {
                        int b = row >> 10;
                        int s = row & 1023;
                        int h = col >> 6;
                        int hd = col & 63;
                        Cp[(((size_t)(b * CH + h)) << 16) + (s << 6) + hd] = v;
                    } else {
                        size_t ci = (size_t)row * N + col;
                        if (outm == 0) Cp[ci] = v;
                        else if (outm == 2) Cp[ci] += v;
                        else Cp[ci] += rs * v;
                    }
                }
            }
        }
    }
}

// N=64 specialized GEMM (tile 128x64, warps 4x2, 2 CTAs/SM).
// Writes bf16-split merged layout (PV attention): out[(bz>>4)*1024+row][ (bz&15)*64 + col ]
#define T64A 14336
#define T64B 7168
#define B64 43008
#define TG64_SMEM 86016

__device__ __forceinline__ void tg64_issue(const __nv_bfloat16* A0, const __nv_bfloat16* A1,
                                           const __nv_bfloat16* B0, const __nv_bfloat16* B1,
                                           int m0, int K, int ch, uint32_t sbase, int tid) {
    uint32_t dbase = sbase + (uint32_t)(ch & 1) * B64;
#pragma unroll
    for (int it = 0; it < 2; it++) {
        int u = tid + it * 256;
        int row = u >> 2;
        int c = u & 3;
        const void* ga = A0 + (size_t)(m0 + row) * K + ch * 32 + c * 8;
        asm volatile("cp.async.cg.shared.global [%0], [%1], 16;"
                     :: "r"(dbase + (uint32_t)(row * 112 + c * 16)), "l"(ga) : "memory");
        const void* gb = A1 + (size_t)(m0 + row) * K + ch * 32 + c * 8;
        asm volatile("cp.async.cg.shared.global [%0], [%1], 16;"
                     :: "r"(dbase + T64A + (uint32_t)(row * 112 + c * 16)), "l"(gb)
                     : "memory");
    }
    {
        int row = tid >> 2;
        int c = tid & 3;
        const void* gb0 = B0 + (size_t)row * K + ch * 32 + c * 8;
        asm volatile("cp.async.cg.shared.global [%0], [%1], 16;"
                     :: "r"(dbase + 2u * T64A + (uint32_t)(row * 112 + c * 16)), "l"(gb0)
                     : "memory");
        const void* gb1 = B1 + (size_t)row * K + ch * 32 + c * 8;
        asm volatile("cp.async.cg.shared.global [%0], [%1], 16;"
                     :: "r"(dbase + 2u * T64A + T64B + (uint32_t)(row * 112 + c * 16)),
                        "l"(gb1)
                     : "memory");
    }
    asm volatile("cp.async.commit_group;" ::: "memory");
}

__global__ void __launch_bounds__(256, 2) tg64_k(
    const __nv_bfloat16* __restrict__ Ah, const __nv_bfloat16* __restrict__ Al,
    const __nv_bfloat16* __restrict__ Bh, const __nv_bfloat16* __restrict__ Bl,
    __nv_bfloat16* __restrict__ Ch, __nv_bfloat16* __restrict__ Cl,
    int M, int K, int bsA, int bsB) {
    extern __shared__ char sm[];
    uint32_t sbase = s2u(sm);

    const int tid = threadIdx.x;
    const int lane = tid & 31;
    const int w = tid >> 5;
    const int g = lane >> 2;
    const int tc = lane & 3;
    const int wm = w >> 1;   // 0..3
    const int wn = w & 1;    // 0..1
    const int quad = lane >> 3;
    const int lrow = lane & 7;
    const int bz = blockIdx.z;
    const int m0 = blockIdx.y * 128;

    const __nv_bfloat16* A0 = Ah + (size_t)bz * bsA;
    const __nv_bfloat16* A1 = Al + (size_t)bz * bsA;
    const __nv_bfloat16* B0 = Bh + (size_t)bz * bsB;
    const __nv_bfloat16* B1 = Bl + (size_t)bz * bsB;

    const uint32_t aoff =
        (uint32_t)((wm * 32 + lrow + ((quad & 1) << 3)) * 112 + ((quad >> 1) << 4));
    const uint32_t boff =
        (uint32_t)((wn * 32 + ((quad >> 1) << 3) + lrow) * 112 + ((quad & 1) << 4));

    float acc[2][4][4];
#pragma unroll
    for (int a = 0; a < 2; a++)
#pragma unroll
        for (int b = 0; b < 4; b++)
#pragma unroll
            for (int e = 0; e < 4; e++) acc[a][b][e] = 0.f;

    const int nch = K >> 5;
    tg64_issue(A0, A1, B0, B1, m0, K, 0, sbase, tid);

    for (int ch = 0; ch < nch; ch++) {
        if (ch + 1 < nch) {
            tg64_issue(A0, A1, B0, B1, m0, K, ch + 1, sbase, tid);
            asm volatile("cp.async.wait_group 1;" ::: "memory");
        } else {
            asm volatile("cp.async.wait_group 0;" ::: "memory");
        }
        __syncthreads();

        uint32_t buf = sbase + (uint32_t)(ch & 1) * B64;
        uint32_t abase = buf + aoff;
        uint32_t bbase = buf + 2u * T64A + boff;

#pragma unroll
        for (int ks = 0; ks < 2; ks++) {
            uint32_t kso = (uint32_t)(ks * 32);
            uint32_t fAh[2][4], fAl[2][4], fBh[4][2], fBl[4][2];
#pragma unroll
            for (int mt = 0; mt < 2; mt++) {
                ldsm4(fAh[mt], abase + (uint32_t)(mt * 1792) + kso);
                ldsm4(fAl[mt], abase + T64A + (uint32_t)(mt * 1792) + kso);
            }
#pragma unroll
            for (int np = 0; np < 2; np++) {
                uint32_t tb[4];
                ldsm4(tb, bbase + (uint32_t)(np * 1792) + kso);
                fBh[np * 2][0] = tb[0];
                fBh[np * 2][1] = tb[1];
                fBh[np * 2 + 1][0] = tb[2];
                fBh[np * 2 + 1][1] = tb[3];
                ldsm4(tb, bbase + T64B + (uint32_t)(np * 1792) + kso);
                fBl[np * 2][0] = tb[0];
                fBl[np * 2][1] = tb[1];
                fBl[np * 2 + 1][0] = tb[2];
                fBl[np * 2 + 1][1] = tb[3];
            }
#pragma unroll
            for (int mt = 0; mt < 2; mt++)
#pragma unroll
                for (int nt = 0; nt < 4; nt++) {
                    mma16816(acc[mt][nt], fAh[mt], fBh[nt]);
                    mma16816(acc[mt][nt], fAh[mt], fBl[nt]);
                    mma16816(acc[mt][nt], fAl[mt], fBh[nt]);
                }
        }
        __syncthreads();
    }

#pragma unroll
    for (int mt = 0; mt < 2; mt++) {
#pragma unroll
        for (int eh = 0; eh < 2; eh++) {
            int row = m0 + wm * 32 + mt * 16 + g + eh * 8;
#pragma unroll
            for (int nt = 0; nt < 4; nt++) {
#pragma unroll
                for (int ec = 0; ec < 2; ec++) {
                    int col = wn * 32 + nt * 8 + tc * 2 + ec;
                    float v = acc[mt][nt][eh * 2 + ec];
                    size_t idx = ((size_t)((bz >> 4) * 1024 + row)) * 1024 +
                                 (size_t)((bz & 15) * 64 + col);
                    split_st(Ch, Cl, idx, v);
                }
            }
        }
    }
}

// FFMA GEMM (performer only)
template <int BM, int BN, int BK, int TM, int TN>
__global__ void __launch_bounds__((BM / TM) * (BN / TN))
gemm_k(const float* __restrict__ A, const float* __restrict__ Bm, float* __restrict__ C,
       int M, int N, int K, int sam, int sak, int sbk, int sbn,
       int bsA, int bsB, int bsC, float alpha) {
    constexpr int RM = BM / TM, RN = BN / TN, NT = RM * RN;
    const int bz = blockIdx.z;
    A += (size_t)bz * bsA;
    Bm += (size_t)bz * bsB;
    C += (size_t)bz * bsC;
    const int m0 = blockIdx.y * BM, n0 = blockIdx.x * BN;
    __shared__ float As[BK][BM + 4];
    __shared__ float Bs[BK][BN + 4];
    const int tid = threadIdx.x, tx = tid % RN, ty = tid / RN;
    float acc[TM][TN];
#pragma unroll
    for (int i = 0; i < TM; i++)
#pragma unroll
        for (int j = 0; j < TN; j++) acc[i][j] = 0.f;
    for (int k0 = 0; k0 < K; k0 += BK) {
#pragma unroll
        for (int idx = tid; idx < BM * BK; idx += NT) {
            int mm = idx / BK, kk = idx % BK;
            As[kk][mm] = A[(size_t)(m0 + mm) * sam + (size_t)(k0 + kk) * sak];
        }
#pragma unroll
        for (int idx = tid; idx < BK * BN; idx += NT) {
            int kk = idx / BN, nn = idx % BN;
            Bs[kk][nn] = Bm[(size_t)(k0 + kk) * sbk + (size_t)(n0 + nn) * sbn];
        }
        __syncthreads();
#pragma unroll
        for (int kk = 0; kk < BK; ++kk) {
            float ra[TM], rb[TN];
#pragma unroll
            for (int i = 0; i < TM; i++) ra[i] = As[kk][ty + i * RM];
#pragma unroll
            for (int j = 0; j < TN; j++) rb[j] = Bs[kk][tx + j * RN];
#pragma unroll
            for (int i = 0; i < TM; i++)
#pragma unroll
                for (int j = 0; j < TN; j++) acc[i][j] = fmaf(ra[i], rb[j], acc[i][j]);
        }
        __syncthreads();
    }
#pragma unroll
    for (int i = 0; i < TM; i++)
#pragma unroll
        for (int j = 0; j < TN; j++)
            C[(size_t)(m0 + ty + i * RM) * N + n0 + tx + j * RN] = acc[i][j] * alpha;
}

__global__ void zero_k(float* p, int n) {
    int i = blockIdx.x * blockDim.x + threadIdx.x;
    if (i < n) p[i] = 0.f;
}

template <int ACT>
__global__ void ln_k(float* __restrict__ y, const float* __restrict__ g,
                     const float* __restrict__ be, int N, int rpg, int pstride) {
    int row = blockIdx.x;
    int grp = row / rpg;
    const float* gp = g + (size_t)grp * pstride;
    const float* bpp = be + (size_t)grp * pstride;
    float* yr = y + (size_t)row * N;
    float s = 0.f, q = 0.f;
    for (int c = threadIdx.x; c < N; c += blockDim.x) {
        float v = yr[c];
        s += v;
        q += v * v;
    }
    s = brs(s);
    q = brs(q);
    float mean = s / N;
    float inv = rsqrtf(q / N - mean * mean + 1e-5f);
    for (int c = threadIdx.x; c < N; c += blockDim.x) {
        float v = (yr[c] - mean) * inv * gp[c] + bpp[c];
        if (ACT == 1) v = fmaxf(v, 0.f);
        if (ACT == 2) v = gelu_f(v);
        yr[c] = v;
    }
}

__global__ void softmax_k(const float* __restrict__ sc, const float* __restrict__ mask,
                          __nv_bfloat16* __restrict__ ph, __nv_bfloat16* __restrict__ pl) {
    int row = blockIdx.x;
    int b = row / (CH * CS);
    const float* r = sc + (size_t)row * CS;
    int t = threadIdx.x;
    float v[4];
    float mx = -3.4e38f;
#pragma unroll
    for (int i = 0; i < 4; i++) {
        int c = t + i * 256;
        float xv = r[c];
        if (mask) xv *= mask[b * CS + c];
        v[i] = xv;
        mx = fmaxf(mx, xv);
    }
    mx = brm(mx);
    float s = 0.f;
#pragma unroll
    for (int i = 0; i < 4; i++) {
        v[i] = __expf(v[i] - mx);
        s += v[i];
    }
    s = brs(s);
    float inv = 1.f / s;
#pragma unroll
    for (int i = 0; i < 4; i++) {
        size_t idx = (size_t)row * CS + t + i * 256;
        split_st(ph, pl, idx, v[i] * inv);
    }
}

__global__ void router_k(const float* __restrict__ h, const float* __restrict__ w,
                         const float* __restrict__ bias, float* __restrict__ probs,
                         int K, int NOUT) {
    __shared__ float red[512];
    int row = blockIdx.x, t = threadIdx.x;
    const float* hr = h + (size_t)row * K;
    float part[4] = {0.f, 0.f, 0.f, 0.f};
    for (int k = t; k < K; k += 128) {
        float hv = hr[k];
        for (int o = 0; o < NOUT; o++) part[o] += hv * w[k * NOUT + o];
    }
    for (int o = 0; o < 4; o++) red[t * 4 + o] = part[o];
    __syncthreads();
    for (int s = 64; s > 0; s >>= 1) {
        if (t < s)
            for (int o = 0; o < 4; o++) red[t * 4 + o] += red[(t + s) * 4 + o];
        __syncthreads();
    }
    if (t == 0) {
        float lg[4];
        float mx = -3.4e38f;
        for (int o = 0; o < NOUT; o++) {
            lg[o] = red[o] + bias[o];
            mx = fmaxf(mx, lg[o]);
        }
        float s = 0.f;
        for (int o = 0; o < NOUT; o++) {
            lg[o] = expf(lg[o] - mx);
            s += lg[o];
        }
        for (int o = 0; o < NOUT; o++) probs[row * NOUT + o] = lg[o] / s;
    }
}

__global__ void gemv_k(const float* __restrict__ x, const float* __restrict__ w,
                       const float* __restrict__ b, float* __restrict__ out) {
    int row = blockIdx.x;
    const float* xr = x + (size_t)row * CD;
    float s = 0.f;
    for (int k = threadIdx.x; k < CD; k += blockDim.x) s += xr[k] * w[k];
    s = brs(s);
    if (threadIdx.x == 0) out[row] = s + b[0];
}

__global__ void topk_mask_k(const float* __restrict__ imp, float* __restrict__ mask) {
    __shared__ float vals[1024];
    __shared__ float rv[1024];
    __shared__ int ri[1024];
    int b = blockIdx.x, t = threadIdx.x;
    vals[t] = imp[b * CS + t];
    mask[b * CS + t] = 0.f;
    __syncthreads();
    for (int it = 0; it < CTOPK; it++) {
        rv[t] = vals[t];
        ri[t] = t;
        __syncthreads();
        for (int s = 512; s > 0; s >>= 1) {
            if (t < s) {
                if (rv[t + s] > rv[t] || (rv[t + s] == rv[t] && ri[t + s] < ri[t])) {
                    rv[t] = rv[t + s];
                    ri[t] = ri[t + s];
                }
            }
            __syncthreads();
        }
        if (t == 0) {
            mask[b * CS + ri[0]] = 1.f;
            vals[ri[0]] = -3.4e38f;
        }
        __syncthreads();
    }
}

__global__ void dwconv_k(const float* __restrict__ x, const float* __restrict__ dw,
                         float* __restrict__ o) {
    int idx = blockIdx.x * blockDim.x + threadIdx.x;
    if (idx >= CM * CD) return;
    int d = idx & (CD - 1);
    int s = (idx >> 10) & (CS - 1);
    float acc = x[idx] * dw[CD + d];
    if (s > 0) acc += x[idx - CD] * dw[d];
    if (s < CS - 1) acc += x[idx + CD] * dw[2 * CD + d];
    o[idx] = acc;
}

__global__ void merge_k(const float* __restrict__ hin, float* __restrict__ o) {
    int idx = blockIdx.x * blockDim.x + threadIdx.x;
    if (idx >= CM * CD) return;
    int n = idx & 1023;
    int m = idx >> 10;
    int b = m >> 10, s = m & 1023, h = n >> 6, hd = n & 63;
    o[idx] = hin[(((size_t)(b * CH + h)) << 16) + (s << 6) + hd];
}

__global__ void colsum_k(const float* __restrict__ kpsi, float* __restrict__ ksum) {
    int bz = blockIdx.x;
    int d = threadIdx.x;
    const float* base = kpsi + (size_t)bz * CS * CKD + d;
    float s = 0.f;
    for (int l = 0; l < CS; l++) s += base[(size_t)l * CKD];
    ksum[bz * CKD + d] = s;
}

__global__ void perf_norm_k(float* __restrict__ num, const float* __restrict__ qphi,
                            const float* __restrict__ ksum) {
    int row = blockIdx.x;
    int bz = row / CS;
    int t = threadIdx.x;
    float p = qphi[(size_t)row * CKD + t] * ksum[bz * CKD + t];
    float den = brs(p) + 1e-8f;
    float inv = 1.f / den;
    if (t < CHD) num[(size_t)row * CHD + t] *= inv;
}

__global__ void convA(const float* __restrict__ s, __nv_bfloat16* __restrict__ h,
                      __nv_bfloat16* __restrict__ l, int n, float scale) {
    int i = blockIdx.x * 256 + threadIdx.x;
    if (i < n) {
        float v = s[i] * scale;
        split_st(h, l, i, v);
    }
}

__global__ void vtrans_k(const float* __restrict__ v, __nv_bfloat16* __restrict__ th,
                         __nv_bfloat16* __restrict__ tl) {
    __shared__ float tt[32][33];
    int bh = blockIdx.z;
    int s0 = blockIdx.x * 32;
    int d0 = blockIdx.y * 32;
    const float* vp = v + (size_t)bh * 65536;
    for (int i = threadIdx.y; i < 32; i += 8)
        tt[i][threadIdx.x] = vp[(size_t)(s0 + i) * 64 + d0 + threadIdx.x];
    __syncthreads();
    for (int i = threadIdx.y; i < 32; i += 8) {
        float val = tt[threadIdx.x][i];
        size_t idx = (size_t)bh * 65536 + (size_t)(d0 + i) * 1024 + s0 + threadIdx.x;
        split_st(th, tl, idx, val);
    }
}

__global__ void convWT(const float* __restrict__ src, __nv_bfloat16* __restrict__ dh,
                       __nv_bfloat16* __restrict__ dl, int K, int N) {
    __shared__ float tt[32][33];
    int b = blockIdx.z;
    src += (size_t)b * K * N;
    dh += (size_t)b * K * N;
    dl += (size_t)b * K * N;
    int k0 = blockIdx.x * 32, n0 = blockIdx.y * 32;
    for (int i = threadIdx.y; i < 32; i += 8)
        tt[i][threadIdx.x] = src[(size_t)(k0 + i) * N + n0 + threadIdx.x];
    __syncthreads();
    for (int i = threadIdx.y; i < 32; i += 8) {
        float v = tt[threadIdx.x][i];
        size_t o = (size_t)(n0 + i) * K + k0 + threadIdx.x;
        split_st(dh, dl, o, v);
    }
}

static float* symaddr(const void* s) {
    void* p = 0;
    cudaGetSymbolAddress(&p, s);
    return (float*)p;
}
static __nv_bfloat16* symb(const void* s) {
    void* p = 0;
    cudaGetSymbolAddress(&p, s);
    return (__nv_bfloat16*)p;
}

static void tgl(int epi, int outm, const __nv_bfloat16* Ah, const __nv_bfloat16* Al,
                const __nv_bfloat16* Bh, const __nv_bfloat16* Bl, const float* bias,
                float* C, __nv_bfloat16* Ch, __nv_bfloat16* Cl,
                int M, int N, int K, int bsA, int bsB, int bsC, int bsBias, int batch,
                float alpha, const float* p1, const float* p2, int i1, int j2) {
    dim3 g((N + 127) / 128, M / 128, batch);
    tg_k<<<g, 256, TG_SMEM>>>(epi, outm, Ah, Al, Bh, Bl, bias, C, Ch, Cl, M, N, K,
                              bsA, bsB, bsC, bsBias, alpha, p1, p2, i1, j2);
}

extern "C" void kernel_launch(void* const* d_in, const int* in_sizes, int n_in,
                              void* d_out, int out_size) {
    const float* x = (const float*)d_in[0];
    const float* w_qkvo = (const float*)d_in[1];
    const float* b_qkvo = (const float*)d_in[2];
    const float* sp_w = (const float*)d_in[3];
    const float* sp_b = (const float*)d_in[4];
    const float* phi_w = (const float*)d_in[5];
    const float* phi_b = (const float*)d_in[6];
    const float* psi_w = (const float*)d_in[7];
    const float* psi_b = (const float*)d_in[8];
    const float* conv_dw = (const float*)d_in[9];
    const float* conv_pw = (const float*)d_in[10];
    const float* fus_w = (const float*)d_in[11];
    const float* fus_b = (const float*)d_in[12];
    const float* sub_w1 = (const float*)d_in[13];
    const float* sub_b1 = (const float*)d_in[14];
    const float* sub_g = (const float*)d_in[15];
    const float* sub_be = (const float*)d_in[16];
    const float* sub_w2 = (const float*)d_in[17];
    const float* sub_b2 = (const float*)d_in[18];
    const float* r1_w1 = (const float*)d_in[19];
    const float* r1_b1 = (const float*)d_in[20];
    const float* r1_g = (const float*)d_in[21];
    const float* r1_be = (const float*)d_in[22];
    const float* r1_w2 = (const float*)d_in[23];
    const float* r1_b2 = (const float*)d_in[24];
    const float* r2_w1 = (const float*)d_in[25];
    const float* r2_b1 = (const float*)d_in[26];
    const float* r2_g = (const float*)d_in[27];
    const float* r2_be = (const float*)d_in[28];
    const float* r2_w2 = (const float*)d_in[29];
    const float* r2_b2 = (const float*)d_in[30];
    float* out = (float*)d_out;

    cudaFuncSetAttribute(tg_k, cudaFuncAttributeMaxDynamicSharedMemorySize, TG_SMEM);
    cudaFuncSetAttribute(tg64_k, cudaFuncAttributeMaxDynamicSharedMemorySize, TG64_SMEM);

    float* q = symaddr(g_qkv);
    float* k = q + 2097152;
    float* v = q + 4194304;
    float* scores = symaddr(g_scores);
    float* attn = symaddr(g_attn);
    float* mrg = symaddr(g_merge);
    float* eo = symaddr(g_eo);
    float* ao = symaddr(g_ao);
    float* xc = symaddr(g_xc);
    float* cnv = symaddr(g_conv);
    float* t1 = symaddr(g_t1);
    float* qphi = symaddr(g_qphi);
    float* kpsi = symaddr(g_kpsi);
    float* kv = symaddr(g_kv);
    float* ksum = symaddr(g_ksum);
    float* h1 = symaddr(g_h1);
    float* h2 = symaddr(g_h2);
    float* p1 = symaddr(g_p1);
    float* p2 = symaddr(g_p2);
    float* imp = symaddr(g_imp);
    float* msk = symaddr(g_mask);
    __nv_bfloat16* xbh = symb(xb_h);
    __nv_bfloat16* xbl = symb(xb_l);
    __nv_bfloat16* qhh = symb(qh_h);
    __nv_bfloat16* qhl = symb(qh_l);
    __nv_bfloat16* khh = symb(kh_h);
    __nv_bfloat16* khl = symb(kh_l);
    __nv_bfloat16* cvh = symb(cv_h);
    __nv_bfloat16* cvl = symb(cv_l);
    __nv_bfloat16* xch = symb(xc_h);
    __nv_bfloat16* xcl = symb(xc_l);
    __nv_bfloat16* aoh = symb(ao_h);
    __nv_bfloat16* aol = symb(ao_l);
    __nv_bfloat16* mgh = symb(mg_h);
    __nv_bfloat16* mgl = symb(mg_l);
    __nv_bfloat16* eoh = symb(eo_h);
    __nv_bfloat16* eol = symb(eo_l);
    __nv_bfloat16* t1h = symb(t1_h);
    __nv_bfloat16* t1l = symb(t1_l);
    __nv_bfloat16* wqh = symb(wq_h);
    __nv_bfloat16* wql = symb(wq_l);
    __nv_bfloat16* s1h = symb(s1_h);
    __nv_bfloat16* s1l = symb(s1_l);
    __nv_bfloat16* s2h = symb(s2_h);
    __nv_bfloat16* s2l = symb(s2_l);
    __nv_bfloat16* fwh = symb(fw_h);
    __nv_bfloat16* fwl = symb(fw_l);
    __nv_bfloat16* cwh = symb(cw_h);
    __nv_bfloat16* cwl = symb(cw_l);
    __nv_bfloat16* r1h = symb(r1_h);
    __nv_bfloat16* r1l = symb(r1_l);
    __nv_bfloat16* r2h = symb(r2_h);
    __nv_bfloat16* r2l = symb(r2_l);
    __nv_bfloat16* phh = symb(ph_h);
    __nv_bfloat16* phl = symb(ph_l);
    __nv_bfloat16* psh = symb(ps_h);
    __nv_bfloat16* psl = symb(ps_l);
    __nv_bfloat16* vth = symb(vt_h);
    __nv_bfloat16* vtl = symb(vt_l);
    __nv_bfloat16* pbh = symb(pb_h);
    __nv_bfloat16* pbl = symb(pb_l);
    const float* NP = (const float*)0;
    float* NF = (float*)0;
    __nv_bfloat16* NB = (__nv_bfloat16*)0;

    dim3 tb(32, 8);
    convWT<<<dim3(32, 16, 1), tb>>>(r1_w1, r1h, r1l, 1024, 512);
    convA<<<8192, 256>>>(x, xbh, xbl, CM * CD, 1.f);
    zero_k<<<8192, 256>>>(out, CM * CD);
    gemv_k<<<CM, 256>>>(x, sp_w, sp_b, imp);
    topk_mask_k<<<CB, 1024>>>(imp, msk);

    tgl(0, 0, xbh, xbl, r1h, r1l, r1_b1, h1, NB, NB, CM, 512, CD, 0, 0, 0, 0, 1, 1.f,
        NP, NP, 0, 0);
    ln_k<1><<<CM, 256>>>(h1, r1_g, r1_be, 512, CM, 0);
    router_k<<<CM, 128>>>(h1, r1_w2, r1_b2, p1, 512, 4);

    convWT<<<dim3(32, 32, 16), tb>>>(w_qkvo, wqh, wql, 1024, 1024);
    convWT<<<dim3(32, 32, 8), tb>>>(sub_w1, s1h, s1l, 1024, 1024);
    convWT<<<dim3(32, 32, 8), tb>>>(sub_w2, s2h, s2l, 1024, 1024);
    convWT<<<dim3(32, 32, 2), tb>>>(fus_w, fwh, fwl, 1024, 1024);
    convWT<<<dim3(32, 32, 1), tb>>>(conv_pw, cwh, cwl, 1024, 1024);
    convWT<<<dim3(32, 8, 4), tb>>>(r2_w1, r2h, r2l, 1024, 256);
    convWT<<<dim3(2, 8, 1), tb>>>(phi_w, phh, phl, 64, 256);
    convWT<<<dim3(2, 8, 1), tb>>>(psi_w, psh, psl, 64, 256);

    for (int i = 0; i < 4; i++) {
        const float* bb = b_qkvo + (size_t)i * 4 * CD;
        tgl(0, 1, xbh, xbl, wqh + (size_t)i * 4194304, wql + (size_t)i * 4194304, bb, q,
            NB, NB, CM, CD, CD, 0, 1048576, 2097152, CD, 3, 1.f, NP, NP, 0, 0);
        const __nv_bfloat16* woh = wqh + (size_t)(i * 4 + 3) * 1048576;
        const __nv_bfloat16* wol = wql + (size_t)(i * 4 + 3) * 1048576;

        if (i == 1) {
            convA<<<8192, 256>>>(q, qhh, qhl, 2097152, 1.f);
            convA<<<8192, 256>>>(k, khh, khl, 2097152, 1.f);
            tgl(1, 0, qhh, qhl, phh, phl, phi_b, qphi, NB, NB, CBH * CS, CKD, CHD,
                0, 0, 0, 0, 1, 1.f, NP, NP, 0, 0);
            tgl(1, 0, khh, khl, psh, psl, psi_b, kpsi, NB, NB, CBH * CS, CKD, CHD,
                0, 0, 0, 0, 1, 1.f, NP, NP, 0, 0);
            gemm_k<64, 64, 16, 4, 4><<<dim3(1, 4, CBH), 256>>>(
                kpsi, v, kv, CKD, CHD, CS, 1, CKD, CHD, 1,
                CS * CKD, CS * CHD, CKD * CHD, 1.f);
            colsum_k<<<CBH, 256>>>(kpsi, ksum);
            gemm_k<64, 64, 16, 4, 4><<<dim3(1, 16, CBH), 256>>>(
                qphi, kv, attn, CS, CHD, CKD, CKD, 1, CHD, 1,
                CS * CKD, CKD * CHD, CS * CHD, 1.f);
            perf_norm_k<<<CBH * CS, 256>>>(attn, qphi, ksum);
            merge_k<<<8192, 256>>>(attn, mrg);
            convA<<<8192, 256>>>(mrg, mgh, mgl, CM * CD, 1.f);
            tgl(0, 0, mgh, mgl, woh, wol, bb + 3 * CD, eo, NB, NB, CM, CD, CD,
                0, 0, 0, 0, 1, 1.f, NP, NP, 0, 0);
        } else {
            convA<<<8192, 256>>>(q, qhh, qhl, 2097152, 0.125f);
            convA<<<8192, 256>>>(k, khh, khl, 2097152, 1.f);
            vtrans_k<<<dim3(32, 2, CBH), tb>>>(v, vth, vtl);
            tgl(0, 0, qhh, qhl, khh, khl, NP, scores, NB, NB, CS, CS, CHD,
                65536, 65536, 1048576, 0, CBH, 1.f, NP, NP, 0, 0);
            softmax_k<<<CBH * CS, 256>>>(scores, (i == 0) ? msk : NP, pbh, pbl);
            tg64_k<<<dim3(1, 8, CBH), 256, TG64_SMEM>>>(
                pbh, pbl, vth, vtl, mgh, mgl, CS, CS, 1048576, 65536);
            if (i == 3) {
                dwconv_k<<<8192, 256>>>(x, conv_dw, cnv);
                convA<<<8192, 256>>>(cnv, cvh, cvl, CM * CD, 1.f);
                tgl(2, 0, cvh, cvl, cwh, cwl, NP, xc, NB, NB, CM, CD, CD,
                    0, 0, 0, 0, 1, 1.f, NP, NP, 0, 0);
                tgl(0, 0, mgh, mgl, woh, wol, bb + 3 * CD, ao, NB, NB, CM, CD, CD,
                    0, 0, 0, 0, 1, 1.f, NP, NP, 0, 0);
                convA<<<8192, 256>>>(ao, aoh, aol, CM * CD, 1.f);
                convA<<<8192, 256>>>(xc, xch, xcl, CM * CD, 1.f);
                tgl(0, 0, aoh, aol, fwh, fwl, fus_b, eo, NB, NB, CM, CD, CD,
                    0, 0, 0, 0, 1, 1.f, NP, NP, 0, 0);
                tgl(0, 2, xch, xcl, fwh + 1048576, fwl + 1048576, NP, eo, NB, NB,
                    CM, CD, CD, 0, 0, 0, 0, 1, 1.f, NP, NP, 0, 0);
            } else {
                tgl(0, 0, mgh, mgl, woh, wol, bb + 3 * CD, eo, NB, NB, CM, CD, CD,
                    0, 0, 0, 0, 1, 1.f, NP, NP, 0, 0);
            }
        }
        convA<<<8192, 256>>>(eo, eoh, eol, CM * CD, 1.f);

        tgl(0, 0, eoh, eol, r2h + (size_t)i * 262144, r2l + (size_t)i * 262144,
            r2_b1 + i * 256, h2, NB, NB, CM, 256, CD, 0, 0, 0, 0, 1, 1.f, NP, NP, 0, 0);
        ln_k<1><<<CM, 256>>>(h2, r2_g + i * 256, r2_be + i * 256, 256, CM, 0);
        router_k<<<CM, 128>>>(h2, r2_w2 + (size_t)i * 512, r2_b2 + i * 2, p2, 256, 2);

        tgl(0, 0, eoh, eol, s1h + (size_t)i * 2097152, s1l + (size_t)i * 2097152,
            sub_b1 + (size_t)i * 2 * CD, t1, NB, NB, CM, CD, CD, 0, 1048576, 2097152,
            CD, 2, 1.f, NP, NP, 0, 0);
        ln_k<2><<<2 * CM, 256>>>(t1, sub_g + (size_t)i * 2 * CD, sub_be + (size_t)i * 2 * CD,
                                 CD, CM, CD);
        convA<<<16384, 256>>>(t1, t1h, t1l, 2 * CM * CD, 1.f);
        for (int j = 0; j < 2; j++) {
            tgl(0, 3, t1h + (size_t)j * 2097152, t1l + (size_t)j * 2097152,
                s2h + (size_t)(i * 2 + j) * 1048576, s2l + (size_t)(i * 2 + j) * 1048576,
                sub_b2 + (size_t)(i * 2 + j) * CD, out, NB, NB, CM, CD, CD,
                0, 0, 0, 0, 1, 1.f, p1, p2, i, j);
        }
    }
}

// round 15
// speedup vs baseline: 1.4258x; 1.0716x over previous
#include <cuda_runtime.h>
#include <cuda_bf16.h>
#include <math.h>
#include <stdint.h>
#include <cstdint>

#define CB 2
#define CS 1024
#define CD 1024
#define CH 16
#define CHD 64
#define CKD 256
#define CTOPK 10
#define CM 2048
#define CBH 32

__device__ float g_qkv[6291456];
__device__ float g_scores[33554432];
__device__ float g_attn[2097152];
__device__ float g_merge[2097152];
__device__ float g_eo[2097152];
__device__ float g_ao[2097152];
__device__ float g_xc[2097152];
__device__ float g_conv[2097152];
__device__ float g_t1[4194304];
__device__ float g_qphi[8388608];
__device__ float g_kpsi[8388608];
__device__ float g_kv[524288];
__device__ float g_ksum[8192];
__device__ float g_h1[1048576];
__device__ float g_h2[524288];
__device__ float g_p1[8192];
__device__ float g_p2[4096];
__device__ float g_imp[2048];
__device__ float g_mask[2048];

__device__ __nv_bfloat16 xb_h[2097152], xb_l[2097152];
__device__ __nv_bfloat16 qh_h[2097152], qh_l[2097152];
__device__ __nv_bfloat16 kh_h[2097152], kh_l[2097152];
__device__ __nv_bfloat16 cv_h[2097152], cv_l[2097152];
__device__ __nv_bfloat16 xc_h[2097152], xc_l[2097152];
__device__ __nv_bfloat16 ao_h[2097152], ao_l[2097152];
__device__ __nv_bfloat16 mg_h[2097152], mg_l[2097152];
__device__ __nv_bfloat16 eo_h[2097152], eo_l[2097152];
__device__ __nv_bfloat16 t1_h[4194304], t1_l[4194304];
__device__ __nv_bfloat16 wq_h[16777216], wq_l[16777216];
__device__ __nv_bfloat16 s1_h[8388608], s1_l[8388608];
__device__ __nv_bfloat16 s2_h[8388608], s2_l[8388608];
__device__ __nv_bfloat16 fw_h[2097152], fw_l[2097152];
__device__ __nv_bfloat16 cw_h[1048576], cw_l[1048576];
__device__ __nv_bfloat16 r1_h[524288], r1_l[524288];
__device__ __nv_bfloat16 r2_h[1048576], r2_l[1048576];
__device__ __nv_bfloat16 ph_h[16384], ph_l[16384];
__device__ __nv_bfloat16 ps_h[16384], ps_l[16384];
__device__ __nv_bfloat16 vt_h[2097152], vt_l[2097152];
__device__ __nv_bfloat16 pb_h[33554432], pb_l[33554432];

__device__ __forceinline__ float gelu_f(float v) {
    float c = 0.7978845608028654f * (v + 0.044715f * v * v * v);
    return 0.5f * v * (1.f + tanhf(c));
}

__device__ __forceinline__ float brs(float v) {
    __shared__ float sh[32];
    __syncthreads();
    int lane = threadIdx.x & 31;
    int wd = threadIdx.x >> 5;
#pragma unroll
    for (int o = 16; o > 0; o >>= 1) v += __shfl_xor_sync(0xffffffffu, v, o);
    if (lane == 0) sh[wd] = v;
    __syncthreads();
    int nw = (blockDim.x + 31) >> 5;
    v = (threadIdx.x < nw) ? sh[threadIdx.x] : 0.f;
    if (wd == 0) {
#pragma unroll
        for (int o = 16; o > 0; o >>= 1) v += __shfl_xor_sync(0xffffffffu, v, o);
        if (lane == 0) sh[0] = v;
    }
    __syncthreads();
    return sh[0];
}

__device__ __forceinline__ float brm(float v) {
    __shared__ float sh[32];
    __syncthreads();
    int lane = threadIdx.x & 31;
    int wd = threadIdx.x >> 5;
#pragma unroll
    for (int o = 16; o > 0; o >>= 1) v = fmaxf(v, __shfl_xor_sync(0xffffffffu, v, o));
    if (lane == 0) sh[wd] = v;
    __syncthreads();
    int nw = (blockDim.x + 31) >> 5;
    v = (threadIdx.x < nw) ? sh[threadIdx.x] : -3.4e38f;
    if (wd == 0) {
#pragma unroll
        for (int o = 16; o > 0; o >>= 1) v = fmaxf(v, __shfl_xor_sync(0xffffffffu, v, o));
        if (lane == 0) sh[0] = v;
    }
    __syncthreads();
    return sh[0];
}

__device__ __forceinline__ void mma16816(float* d, const uint32_t* a, const uint32_t* b) {
    asm volatile(
        "mma.sync.aligned.m16n8k16.row.col.f32.bf16.bf16.f32 "
        "{%0, %1, %2, %3}, {%4, %5, %6, %7}, {%8, %9}, {%0, %1, %2, %3};"
        : "+f"(d[0]), "+f"(d[1]), "+f"(d[2]), "+f"(d[3])
        : "r"(a[0]), "r"(a[1]), "r"(a[2]), "r"(a[3]), "r"(b[0]), "r"(b[1]));
}

__device__ __forceinline__ void ldsm4(uint32_t* r, uint32_t a) {
    asm volatile(
        "ldmatrix.sync.aligned.m8n8.x4.shared.b16 {%0, %1, %2, %3}, [%4];"
        : "=r"(r[0]), "=r"(r[1]), "=r"(r[2]), "=r"(r[3])
        : "r"(a));
}

__device__ __forceinline__ uint32_t s2u(const void* p) {
    uint32_t a;
    asm("{ .reg .u64 t; cvta.to.shared.u64 t, %1; cvt.u32.u64 %0, t; }" : "=r"(a) : "l"(p));
    return a;
}

__device__ __forceinline__ void split_st(__nv_bfloat16* h, __nv_bfloat16* l, size_t idx,
                                         float v) {
    __nv_bfloat16 a = __float2bfloat16(v);
    h[idx] = a;
    l[idx] = __float2bfloat16(v - __bfloat162float(a));
}

// ---- tg_k: KC=64 chunk, row stride 144 B ----
#define TROW 144
#define TILE_B 18432
#define BUF_B 73728
#define TG_SMEM 147456

__device__ __forceinline__ void tg_issue(const __nv_bfloat16* A0, const __nv_bfloat16* A1,
                                         const __nv_bfloat16* B0, const __nv_bfloat16* B1,
                                         int m0, int n0, int K, int M, int N, int ch,
                                         uint32_t sbase, int tid) {
    const __nv_bfloat16* srcs[4] = {A0, A1, B0, B1};
    uint32_t dbase = sbase + (uint32_t)(ch & 1) * BUF_B;
#pragma unroll
    for (int t = 0; t < 4; t++) {
        const __nv_bfloat16* src = srcs[t];
        int r0 = (t < 2) ? m0 : n0;
        int lim = (t < 2) ? M : N;
#pragma unroll
        for (int it = 0; it < 4; it++) {
            int u = tid + it * 256;
            int row = u >> 3;
            int c = u & 7;
            int gr = r0 + row;
            if (gr >= lim) gr = lim - 1;
            const void* gp = src + (size_t)gr * K + ch * 64 + c * 8;
            uint32_t dst = dbase + (uint32_t)(t * TILE_B + row * TROW + c * 16);
            asm volatile("cp.async.cg.shared.global [%0], [%1], 16;"
                         :: "r"(dst), "l"(gp) : "memory");
        }
    }
    asm volatile("cp.async.commit_group;" ::: "memory");
}

// tensor GEMM via mma.sync + ldmatrix, cp.async double-buffered (tile 128x128, KC=64).
__global__ void __launch_bounds__(256, 1) tg_k(
    int epi, int outm,
    const __nv_bfloat16* __restrict__ Ah, const __nv_bfloat16* __restrict__ Al,
    const __nv_bfloat16* __restrict__ Bh, const __nv_bfloat16* __restrict__ Bl,
    const float* __restrict__ bias, float* __restrict__ C,
    __nv_bfloat16* __restrict__ Ch, __nv_bfloat16* __restrict__ Cl,
    int M, int N, int K, int bsA, int bsB, int bsC, int bsBias, float alpha,
    const float* __restrict__ p1, const float* __restrict__ p2, int i1, int j2) {
    extern __shared__ char sm[];
    uint32_t sbase = s2u(sm);

    const int tid = threadIdx.x;
    const int lane = tid & 31;
    const int w = tid >> 5;
    const int g = lane >> 2;
    const int tc = lane & 3;
    const int wm = w >> 2;
    const int wn = w & 3;
    const int quad = lane >> 3;
    const int lrow = lane & 7;
    const int bz = blockIdx.z;
    const int m0 = blockIdx.y * 128;
    const int n0 = blockIdx.x * 128;

    const __nv_bfloat16* A0 = Ah + (size_t)bz * bsA;
    const __nv_bfloat16* A1 = Al + (size_t)bz * bsA;
    const __nv_bfloat16* B0 = Bh + (size_t)bz * bsB;
    const __nv_bfloat16* B1 = Bl + (size_t)bz * bsB;
    const float* bp = bias;
    if (bp) bp += (size_t)bz * bsBias;
    float* Cp = C ? C + (size_t)bz * bsC : (float*)0;

    const uint32_t aoff =
        (uint32_t)((wm * 64 + lrow + ((quad & 1) << 3)) * TROW + ((quad >> 1) << 4));
    const uint32_t boff =
        (uint32_t)((wn * 32 + ((quad >> 1) << 3) + lrow) * TROW + ((quad & 1) << 4));

    float acc[4][4][4];
#pragma unroll
    for (int a = 0; a < 4; a++)
#pragma unroll
        for (int b = 0; b < 4; b++)
#pragma unroll
            for (int e = 0; e < 4; e++) acc[a][b][e] = 0.f;

    const int nch = K >> 6;
    tg_issue(A0, A1, B0, B1, m0, n0, K, M, N, 0, sbase, tid);

    for (int ch = 0; ch < nch; ch++) {
        if (ch + 1 < nch) {
            tg_issue(A0, A1, B0, B1, m0, n0, K, M, N, ch + 1, sbase, tid);
            asm volatile("cp.async.wait_group 1;" ::: "memory");
        } else {
            asm volatile("cp.async.wait_group 0;" ::: "memory");
        }
        __syncthreads();

        uint32_t buf = sbase + (uint32_t)(ch & 1) * BUF_B;
        uint32_t abase = buf + aoff;
        uint32_t bbase = buf + 2u * TILE_B + boff;

#pragma unroll
        for (int ks = 0; ks < 4; ks++) {
            uint32_t kso = (uint32_t)(ks * 32);
            uint32_t fAh[4][4], fAl[4][4], fBh[4][2], fBl[4][2];
#pragma unroll
            for (int mt = 0; mt < 4; mt++) {
                ldsm4(fAh[mt], abase + (uint32_t)(mt * 16 * TROW) + kso);
                ldsm4(fAl[mt], abase + TILE_B + (uint32_t)(mt * 16 * TROW) + kso);
            }
#pragma unroll
            for (int np = 0; np < 2; np++) {
                uint32_t tb[4];
                ldsm4(tb, bbase + (uint32_t)(np * 16 * TROW) + kso);
                fBh[np * 2][0] = tb[0];
                fBh[np * 2][1] = tb[1];
                fBh[np * 2 + 1][0] = tb[2];
                fBh[np * 2 + 1][1] = tb[3];
                ldsm4(tb, bbase + TILE_B + (uint32_t)(np * 16 * TROW) + kso);
                fBl[np * 2][0] = tb[0];
                fBl[np * 2][1] = tb[1];
                fBl[np * 2 + 1][0] = tb[2];
                fBl[np * 2 + 1][1] = tb[3];
            }
#pragma unroll
            for (int mt = 0; mt < 4; mt++)
#pragma unroll
                for (int nt = 0; nt < 4; nt++) {
                    mma16816(acc[mt][nt], fAh[mt], fBh[nt]);
                    mma16816(acc[mt][nt], fAh[mt], fBl[nt]);
                    mma16816(acc[mt][nt], fAl[mt], fBh[nt]);
                }
        }
        __syncthreads();
    }

#pragma unroll
    for (int mt = 0; mt < 4; mt++) {
#pragma unroll
        for (int eh = 0; eh < 2; eh++) {
            int row = m0 + wm * 64 + mt * 16 + g + eh * 8;
            float rs = 1.f;
            if (outm == 3) rs = p1[row * 4 + i1] * p2[row * 2 + j2];
#pragma unroll
            for (int nt = 0; nt < 4; nt++) {
#pragma unroll
                for (int ec = 0; ec < 2; ec++) {
                    int col = n0 + wn * 32 + nt * 8 + tc * 2 + ec;
                    if (col >= N) continue;
                    float v = acc[mt][nt][eh * 2 + ec] * alpha;
                    if (bp) v += bp[col];
                    if (epi == 1) v = (v > 0.f) ? (v + 1.f) : expf(v);
                    else if (epi == 2) v = gelu_f(v);
                    if (outm == 1) {
                        int b = row >> 10;
                        int s = row & 1023;
                        int h = col >> 6;
                        int hd = col & 63;
                        Cp[(((size_t)(b * CH + h)) << 16) + (s << 6) + hd] = v;
                    } else {
                        size_t ci = (size_t)row * N + col;
                        if (outm == 0) Cp[ci] = v;
                        else if (outm == 2) Cp[ci] += v;
                        else Cp[ci] += rs * v;
                    }
                }
            }
        }
    }
}

// N=64 specialized GEMM (tile 128x64, warps 4x2, 2 CTAs/SM), KC=32 (unchanged from R14).
#define T64A 14336
#define T64B 7168
#define B64 43008
#define TG64_SMEM 86016

__device__ __forceinline__ void tg64_issue(const __nv_bfloat16* A0, const __nv_bfloat16* A1,
                                           const __nv_bfloat16* B0, const __nv_bfloat16* B1,
                                           int m0, int K, int ch, uint32_t sbase, int tid) {
    uint32_t dbase = sbase + (uint32_t)(ch & 1) * B64;
#pragma unroll
    for (int it = 0; it < 2; it++) {
        int u = tid + it * 256;
        int row = u >> 2;
        int c = u & 3;
        const void* ga = A0 + (size_t)(m0 + row) * K + ch * 32 + c * 8;
        asm volatile("cp.async.cg.shared.global [%0], [%1], 16;"
                     :: "r"(dbase + (uint32_t)(row * 112 + c * 16)), "l"(ga) : "memory");
        const void* gb = A1 + (size_t)(m0 + row) * K + ch * 32 + c * 8;
        asm volatile("cp.async.cg.shared.global [%0], [%1], 16;"
                     :: "r"(dbase + T64A + (uint32_t)(row * 112 + c * 16)), "l"(gb)
                     : "memory");
    }
    {
        int row = tid >> 2;
        int c = tid & 3;
        const void* gb0 = B0 + (size_t)row * K + ch * 32 + c * 8;
        asm volatile("cp.async.cg.shared.global [%0], [%1], 16;"
                     :: "r"(dbase + 2u * T64A + (uint32_t)(row * 112 + c * 16)), "l"(gb0)
                     : "memory");
        const void* gb1 = B1 + (size_t)row * K + ch * 32 + c * 8;
        asm volatile("cp.async.cg.shared.global [%0], [%1], 16;"
                     :: "r"(dbase + 2u * T64A + T64B + (uint32_t)(row * 112 + c * 16)),
                        "l"(gb1)
                     : "memory");
    }
    asm volatile("cp.async.commit_group;" ::: "memory");
}

__global__ void __launch_bounds__(256, 2) tg64_k(
    const __nv_bfloat16* __restrict__ Ah, const __nv_bfloat16* __restrict__ Al,
    const __nv_bfloat16* __restrict__ Bh, const __nv_bfloat16* __restrict__ Bl,
    __nv_bfloat16* __restrict__ Ch, __nv_bfloat16* __restrict__ Cl,
    int M, int K, int bsA, int bsB) {
    extern __shared__ char sm[];
    uint32_t sbase = s2u(sm);

    const int tid = threadIdx.x;
    const int lane = tid & 31;
    const int w = tid >> 5;
    const int g = lane >> 2;
    const int tc = lane & 3;
    const int wm = w >> 1;
    const int wn = w & 1;
    const int quad = lane >> 3;
    const int lrow = lane & 7;
    const int bz = blockIdx.z;
    const int m0 = blockIdx.y * 128;

    const __nv_bfloat16* A0 = Ah + (size_t)bz * bsA;
    const __nv_bfloat16* A1 = Al + (size_t)bz * bsA;
    const __nv_bfloat16* B0 = Bh + (size_t)bz * bsB;
    const __nv_bfloat16* B1 = Bl + (size_t)bz * bsB;

    const uint32_t aoff =
        (uint32_t)((wm * 32 + lrow + ((quad & 1) << 3)) * 112 + ((quad >> 1) << 4));
    const uint32_t boff =
        (uint32_t)((wn * 32 + ((quad >> 1) << 3) + lrow) * 112 + ((quad & 1) << 4));

    float acc[2][4][4];
#pragma unroll
    for (int a = 0; a < 2; a++)
#pragma unroll
        for (int b = 0; b < 4; b++)
#pragma unroll
            for (int e = 0; e < 4; e++) acc[a][b][e] = 0.f;

    const int nch = K >> 5;
    tg64_issue(A0, A1, B0, B1, m0, K, 0, sbase, tid);

    for (int ch = 0; ch < nch; ch++) {
        if (ch + 1 < nch) {
            tg64_issue(A0, A1, B0, B1, m0, K, ch + 1, sbase, tid);
            asm volatile("cp.async.wait_group 1;" ::: "memory");
        } else {
            asm volatile("cp.async.wait_group 0;" ::: "memory");
        }
        __syncthreads();

        uint32_t buf = sbase + (uint32_t)(ch & 1) * B64;
        uint32_t abase = buf + aoff;
        uint32_t bbase = buf + 2u * T64A + boff;

#pragma unroll
        for (int ks = 0; ks < 2; ks++) {
            uint32_t kso = (uint32_t)(ks * 32);
            uint32_t fAh[2][4], fAl[2][4], fBh[4][2], fBl[4][2];
#pragma unroll
            for (int mt = 0; mt < 2; mt++) {
                ldsm4(fAh[mt], abase + (uint32_t)(mt * 1792) + kso);
                ldsm4(fAl[mt], abase + T64A + (uint32_t)(mt * 1792) + kso);
            }
#pragma unroll
            for (int np = 0; np < 2; np++) {
                uint32_t tb[4];
                ldsm4(tb, bbase + (uint32_t)(np * 1792) + kso);
                fBh[np * 2][0] = tb[0];
                fBh[np * 2][1] = tb[1];
                fBh[np * 2 + 1][0] = tb[2];
                fBh[np * 2 + 1][1] = tb[3];
                ldsm4(tb, bbase + T64B + (uint32_t)(np * 1792) + kso);
                fBl[np * 2][0] = tb[0];
                fBl[np * 2][1] = tb[1];
                fBl[np * 2 + 1][0] = tb[2];
                fBl[np * 2 + 1][1] = tb[3];
            }
#pragma unroll
            for (int mt = 0; mt < 2; mt++)
#pragma unroll
                for (int nt = 0; nt < 4; nt++) {
                    mma16816(acc[mt][nt], fAh[mt], fBh[nt]);
                    mma16816(acc[mt][nt], fAh[mt], fBl[nt]);
                    mma16816(acc[mt][nt], fAl[mt], fBh[nt]);
                }
        }
        __syncthreads();
    }

#pragma unroll
    for (int mt = 0; mt < 2; mt++) {
#pragma unroll
        for (int eh = 0; eh < 2; eh++) {
            int row = m0 + wm * 32 + mt * 16 + g + eh * 8;
#pragma unroll
            for (int nt = 0; nt < 4; nt++) {
#pragma unroll
                for (int ec = 0; ec < 2; ec++) {
                    int col = wn * 32 + nt * 8 + tc * 2 + ec;
                    float v = acc[mt][nt][eh * 2 + ec];
                    size_t idx = ((size_t)((bz >> 4) * 1024 + row)) * 1024 +
                                 (size_t)((bz & 15) * 64 + col);
                    split_st(Ch, Cl, idx, v);
                }
            }
        }
    }
}

// FFMA GEMM (performer only)
template <int BM, int BN, int BK, int TM, int TN>
__global__ void __launch_bounds__((BM / TM) * (BN / TN))
gemm_k(const float* __restrict__ A, const float* __restrict__ Bm, float* __restrict__ C,
       int M, int N, int K, int sam, int sak, int sbk, int sbn,
       int bsA, int bsB, int bsC, float alpha) {
    constexpr int RM = BM / TM, RN = BN / TN, NT = RM * RN;
    const int bz = blockIdx.z;
    A += (size_t)bz * bsA;
    Bm += (size_t)bz * bsB;
    C += (size_t)bz * bsC;
    const int m0 = blockIdx.y * BM, n0 = blockIdx.x * BN;
    __shared__ float As[BK][BM + 4];
    __shared__ float Bs[BK][BN + 4];
    const int tid = threadIdx.x, tx = tid % RN, ty = tid / RN;
    float acc[TM][TN];
#pragma unroll
    for (int i = 0; i < TM; i++)
#pragma unroll
        for (int j = 0; j < TN; j++) acc[i][j] = 0.f;
    for (int k0 = 0; k0 < K; k0 += BK) {
#pragma unroll
        for (int idx = tid; idx < BM * BK; idx += NT) {
            int mm = idx / BK, kk = idx % BK;
            As[kk][mm] = A[(size_t)(m0 + mm) * sam + (size_t)(k0 + kk) * sak];
        }
#pragma unroll
        for (int idx = tid; idx < BK * BN; idx += NT) {
            int kk = idx / BN, nn = idx % BN;
            Bs[kk][nn] = Bm[(size_t)(k0 + kk) * sbk + (size_t)(n0 + nn) * sbn];
        }
        __syncthreads();
#pragma unroll
        for (int kk = 0; kk < BK; ++kk) {
            float ra[TM], rb[TN];
#pragma unroll
            for (int i = 0; i < TM; i++) ra[i] = As[kk][ty + i * RM];
#pragma unroll
            for (int j = 0; j < TN; j++) rb[j] = Bs[kk][tx + j * RN];
#pragma unroll
            for (int i = 0; i < TM; i++)
#pragma unroll
                for (int j = 0; j < TN; j++) acc[i][j] = fmaf(ra[i], rb[j], acc[i][j]);
        }
        __syncthreads();
    }
#pragma unroll
    for (int i = 0; i < TM; i++)
#pragma unroll
        for (int j = 0; j < TN; j++)
            C[(size_t)(m0 + ty + i * RM) * N + n0 + tx + j * RN] = acc[i][j] * alpha;
}

__global__ void zero_k(float* p, int n) {
    int i = blockIdx.x * blockDim.x + threadIdx.x;
    if (i < n) p[i] = 0.f;
}

template <int ACT>
__global__ void ln_k(float* __restrict__ y, const float* __restrict__ g,
                     const float* __restrict__ be, int N, int rpg, int pstride) {
    int row = blockIdx.x;
    int grp = row / rpg;
    const float* gp = g + (size_t)grp * pstride;
    const float* bpp = be + (size_t)grp * pstride;
    float* yr = y + (size_t)row * N;
    float s = 0.f, q = 0.f;
    for (int c = threadIdx.x; c < N; c += blockDim.x) {
        float v = yr[c];
        s += v;
        q += v * v;
    }
    s = brs(s);
    q = brs(q);
    float mean = s / N;
    float inv = rsqrtf(q / N - mean * mean + 1e-5f);
    for (int c = threadIdx.x; c < N; c += blockDim.x) {
        float v = (yr[c] - mean) * inv * gp[c] + bpp[c];
        if (ACT == 1) v = fmaxf(v, 0.f);
        if (ACT == 2) v = gelu_f(v);
        yr[c] = v;
    }
}

__global__ void softmax_k(const float* __restrict__ sc, const float* __restrict__ mask,
                          __nv_bfloat16* __restrict__ ph, __nv_bfloat16* __restrict__ pl) {
    int row = blockIdx.x;
    int b = row / (CH * CS);
    const float* r = sc + (size_t)row * CS;
    int t = threadIdx.x;
    float v[4];
    float mx = -3.4e38f;
#pragma unroll
    for (int i = 0; i < 4; i++) {
        int c = t + i * 256;
        float xv = r[c];
        if (mask) xv *= mask[b * CS + c];
        v[i] = xv;
        mx = fmaxf(mx, xv);
    }
    mx = brm(mx);
    float s = 0.f;
#pragma unroll
    for (int i = 0; i < 4; i++) {
        v[i] = __expf(v[i] - mx);
        s += v[i];
    }
    s = brs(s);
    float inv = 1.f / s;
#pragma unroll
    for (int i = 0; i < 4; i++) {
        size_t idx = (size_t)row * CS + t + i * 256;
        split_st(ph, pl, idx, v[i] * inv);
    }
}

__global__ void router_k(const float* __restrict__ h, const float* __restrict__ w,
                         const float* __restrict__ bias, float* __restrict__ probs,
                         int K, int NOUT) {
    __shared__ float red[512];
    int row = blockIdx.x, t = threadIdx.x;
    const float* hr = h + (size_t)row * K;
    float part[4] = {0.f, 0.f, 0.f, 0.f};
    for (int k = t; k < K; k += 128) {
        float hv = hr[k];
        for (int o = 0; o < NOUT; o++) part[o] += hv * w[k * NOUT + o];
    }
    for (int o = 0; o < 4; o++) red[t * 4 + o] = part[o];
    __syncthreads();
    for (int s = 64; s > 0; s >>= 1) {
        if (t < s)
            for (int o = 0; o < 4; o++) red[t * 4 + o] += red[(t + s) * 4 + o];
        __syncthreads();
    }
    if (t == 0) {
        float lg[4];
        float mx = -3.4e38f;
        for (int o = 0; o < NOUT; o++) {
            lg[o] = red[o] + bias[o];
            mx = fmaxf(mx, lg[o]);
        }
        float s = 0.f;
        for (int o = 0; o < NOUT; o++) {
            lg[o] = expf(lg[o] - mx);
            s += lg[o];
        }
        for (int o = 0; o < NOUT; o++) probs[row * NOUT + o] = lg[o] / s;
    }
}

__global__ void gemv_k(const float* __restrict__ x, const float* __restrict__ w,
                       const float* __restrict__ b, float* __restrict__ out) {
    int row = blockIdx.x;
    const float* xr = x + (size_t)row * CD;
    float s = 0.f;
    for (int k = threadIdx.x; k < CD; k += blockDim.x) s += xr[k] * w[k];
    s = brs(s);
    if (threadIdx.x == 0) out[row] = s + b[0];
}

__global__ void topk_mask_k(const float* __restrict__ imp, float* __restrict__ mask) {
    __shared__ float vals[1024];
    __shared__ float rv[1024];
    __shared__ int ri[1024];
    int b = blockIdx.x, t = threadIdx.x;
    vals[t] = imp[b * CS + t];
    mask[b * CS + t] = 0.f;
    __syncthreads();
    for (int it = 0; it < CTOPK; it++) {
        rv[t] = vals[t];
        ri[t] = t;
        __syncthreads();
        for (int s = 512; s > 0; s >>= 1) {
            if (t < s) {
                if (rv[t + s] > rv[t] || (rv[t + s] == rv[t] && ri[t + s] < ri[t])) {
                    rv[t] = rv[t + s];
                    ri[t] = ri[t + s];
                }
            }
            __syncthreads();
        }
        if (t == 0) {
            mask[b * CS + ri[0]] = 1.f;
            vals[ri[0]] = -3.4e38f;
        }
        __syncthreads();
    }
}

__global__ void dwconv_k(const float* __restrict__ x, const float* __restrict__ dw,
                         float* __restrict__ o) {
    int idx = blockIdx.x * blockDim.x + threadIdx.x;
    if (idx >= CM * CD) return;
    int d = idx & (CD - 1);
    int s = (idx >> 10) & (CS - 1);
    float acc = x[idx] * dw[CD + d];
    if (s > 0) acc += x[idx - CD] * dw[d];
    if (s < CS - 1) acc += x[idx + CD] * dw[2 * CD + d];
    o[idx] = acc;
}

__global__ void merge_k(const float* __restrict__ hin, float* __restrict__ o) {
    int idx = blockIdx.x * blockDim.x + threadIdx.x;
    if (idx >= CM * CD) return;
    int n = idx & 1023;
    int m = idx >> 10;
    int b = m >> 10, s = m & 1023, h = n >> 6, hd = n & 63;
    o[idx] = hin[(((size_t)(b * CH + h)) << 16) + (s << 6) + hd];
}

__global__ void colsum_k(const float* __restrict__ kpsi, float* __restrict__ ksum) {
    int bz = blockIdx.x;
    int d = threadIdx.x;
    const float* base = kpsi + (size_t)bz * CS * CKD + d;
    float s = 0.f;
    for (int l = 0; l < CS; l++) s += base[(size_t)l * CKD];
    ksum[bz * CKD + d] = s;
}

__global__ void perf_norm_k(float* __restrict__ num, const float* __restrict__ qphi,
                            const float* __restrict__ ksum) {
    int row = blockIdx.x;
    int bz = row / CS;
    int t = threadIdx.x;
    float p = qphi[(size_t)row * CKD + t] * ksum[bz * CKD + t];
    float den = brs(p) + 1e-8f;
    float inv = 1.f / den;
    if (t < CHD) num[(size_t)row * CHD + t] *= inv;
}

__global__ void convA(const float* __restrict__ s, __nv_bfloat16* __restrict__ h,
                      __nv_bfloat16* __restrict__ l, int n, float scale) {
    int i = blockIdx.x * 256 + threadIdx.x;
    if (i < n) {
        float v = s[i] * scale;
        split_st(h, l, i, v);
    }
}

__global__ void vtrans_k(const float* __restrict__ v, __nv_bfloat16* __restrict__ th,
                         __nv_bfloat16* __restrict__ tl) {
    __shared__ float tt[32][33];
    int bh = blockIdx.z;
    int s0 = blockIdx.x * 32;
    int d0 = blockIdx.y * 32;
    const float* vp = v + (size_t)bh * 65536;
    for (int i = threadIdx.y; i < 32; i += 8)
        tt[i][threadIdx.x] = vp[(size_t)(s0 + i) * 64 + d0 + threadIdx.x];
    __syncthreads();
    for (int i = threadIdx.y; i < 32; i += 8) {
        float val = tt[threadIdx.x][i];
        size_t idx = (size_t)bh * 65536 + (size_t)(d0 + i) * 1024 + s0 + threadIdx.x;
        split_st(th, tl, idx, val);
    }
}

__global__ void convWT(const float* __restrict__ src, __nv_bfloat16* __restrict__ dh,
                       __nv_bfloat16* __restrict__ dl, int K, int N) {
    __shared__ float tt[32][33];
    int b = blockIdx.z;
    src += (size_t)b * K * N;
    dh += (size_t)b * K * N;
    dl += (size_t)b * K * N;
    int k0 = blockIdx.x * 32, n0 = blockIdx.y * 32;
    for (int i = threadIdx.y; i < 32; i += 8)
        tt[i][threadIdx.x] = src[(size_t)(k0 + i) * N + n0 + threadIdx.x];
    __syncthreads();
    for (int i = threadIdx.y; i < 32; i += 8) {
        float v = tt[threadIdx.x][i];
        size_t o = (size_t)(n0 + i) * K + k0 + threadIdx.x;
        split_st(dh, dl, o, v);
    }
}

static float* symaddr(const void* s) {
    void* p = 0;
    cudaGetSymbolAddress(&p, s);
    return (float*)p;
}
static __nv_bfloat16* symb(const void* s) {
    void* p = 0;
    cudaGetSymbolAddress(&p, s);
    return (__nv_bfloat16*)p;
}

static void tgl(int epi, int outm, const __nv_bfloat16* Ah, const __nv_bfloat16* Al,
                const __nv_bfloat16* Bh, const __nv_bfloat16* Bl, const float* bias,
                float* C, __nv_bfloat16* Ch, __nv_bfloat16* Cl,
                int M, int N, int K, int bsA, int bsB, int bsC, int bsBias, int batch,
                float alpha, const float* p1, const float* p2, int i1, int j2) {
    dim3 g((N + 127) / 128, M / 128, batch);
    tg_k<<<g, 256, TG_SMEM>>>(epi, outm, Ah, Al, Bh, Bl, bias, C, Ch, Cl, M, N, K,
                              bsA, bsB, bsC, bsBias, alpha, p1, p2, i1, j2);
}

extern "C" void kernel_launch(void* const* d_in, const int* in_sizes, int n_in,
                              void* d_out, int out_size) {
    const float* x = (const float*)d_in[0];
    const float* w_qkvo = (const float*)d_in[1];
    const float* b_qkvo = (const float*)d_in[2];
    const float* sp_w = (const float*)d_in[3];
    const float* sp_b = (const float*)d_in[4];
    const float* phi_w = (const float*)d_in[5];
    const float* phi_b = (const float*)d_in[6];
    const float* psi_w = (const float*)d_in[7];
    const float* psi_b = (const float*)d_in[8];
    const float* conv_dw = (const float*)d_in[9];
    const float* conv_pw = (const float*)d_in[10];
    const float* fus_w = (const float*)d_in[11];
    const float* fus_b = (const float*)d_in[12];
    const float* sub_w1 = (const float*)d_in[13];
    const float* sub_b1 = (const float*)d_in[14];
    const float* sub_g = (const float*)d_in[15];
    const float* sub_be = (const float*)d_in[16];
    const float* sub_w2 = (const float*)d_in[17];
    const float* sub_b2 = (const float*)d_in[18];
    const float* r1_w1 = (const float*)d_in[19];
    const float* r1_b1 = (const float*)d_in[20];
    const float* r1_g = (const float*)d_in[21];
    const float* r1_be = (const float*)d_in[22];
    const float* r1_w2 = (const float*)d_in[23];
    const float* r1_b2 = (const float*)d_in[24];
    const float* r2_w1 = (const float*)d_in[25];
    const float* r2_b1 = (const float*)d_in[26];
    const float* r2_g = (const float*)d_in[27];
    const float* r2_be = (const float*)d_in[28];
    const float* r2_w2 = (const float*)d_in[29];
    const float* r2_b2 = (const float*)d_in[30];
    float* out = (float*)d_out;

    cudaFuncSetAttribute(tg_k, cudaFuncAttributeMaxDynamicSharedMemorySize, TG_SMEM);
    cudaFuncSetAttribute(tg64_k, cudaFuncAttributeMaxDynamicSharedMemorySize, TG64_SMEM);

    float* q = symaddr(g_qkv);
    float* k = q + 2097152;
    float* v = q + 4194304;
    float* scores = symaddr(g_scores);
    float* attn = symaddr(g_attn);
    float* mrg = symaddr(g_merge);
    float* eo = symaddr(g_eo);
    float* ao = symaddr(g_ao);
    float* xc = symaddr(g_xc);
    float* cnv = symaddr(g_conv);
    float* t1 = symaddr(g_t1);
    float* qphi = symaddr(g_qphi);
    float* kpsi = symaddr(g_kpsi);
    float* kv = symaddr(g_kv);
    float* ksum = symaddr(g_ksum);
    float* h1 = symaddr(g_h1);
    float* h2 = symaddr(g_h2);
    float* p1 = symaddr(g_p1);
    float* p2 = symaddr(g_p2);
    float* imp = symaddr(g_imp);
    float* msk = symaddr(g_mask);
    __nv_bfloat16* xbh = symb(xb_h);
    __nv_bfloat16* xbl = symb(xb_l);
    __nv_bfloat16* qhh = symb(qh_h);
    __nv_bfloat16* qhl = symb(qh_l);
    __nv_bfloat16* khh = symb(kh_h);
    __nv_bfloat16* khl = symb(kh_l);
    __nv_bfloat16* cvh = symb(cv_h);
    __nv_bfloat16* cvl = symb(cv_l);
    __nv_bfloat16* xch = symb(xc_h);
    __nv_bfloat16* xcl = symb(xc_l);
    __nv_bfloat16* aoh = symb(ao_h);
    __nv_bfloat16* aol = symb(ao_l);
    __nv_bfloat16* mgh = symb(mg_h);
    __nv_bfloat16* mgl = symb(mg_l);
    __nv_bfloat16* eoh = symb(eo_h);
    __nv_bfloat16* eol = symb(eo_l);
    __nv_bfloat16* t1h = symb(t1_h);
    __nv_bfloat16* t1l = symb(t1_l);
    __nv_bfloat16* wqh = symb(wq_h);
    __nv_bfloat16* wql = symb(wq_l);
    __nv_bfloat16* s1h = symb(s1_h);
    __nv_bfloat16* s1l = symb(s1_l);
    __nv_bfloat16* s2h = symb(s2_h);
    __nv_bfloat16* s2l = symb(s2_l);
    __nv_bfloat16* fwh = symb(fw_h);
    __nv_bfloat16* fwl = symb(fw_l);
    __nv_bfloat16* cwh = symb(cw_h);
    __nv_bfloat16* cwl = symb(cw_l);
    __nv_bfloat16* r1h = symb(r1_h);
    __nv_bfloat16* r1l = symb(r1_l);
    __nv_bfloat16* r2h = symb(r2_h);
    __nv_bfloat16* r2l = symb(r2_l);
    __nv_bfloat16* phh = symb(ph_h);
    __nv_bfloat16* phl = symb(ph_l);
    __nv_bfloat16* psh = symb(ps_h);
    __nv_bfloat16* psl = symb(ps_l);
    __nv_bfloat16* vth = symb(vt_h);
    __nv_bfloat16* vtl = symb(vt_l);
    __nv_bfloat16* pbh = symb(pb_h);
    __nv_bfloat16* pbl = symb(pb_l);
    const float* NP = (const float*)0;
    float* NF = (float*)0;
    __nv_bfloat16* NB = (__nv_bfloat16*)0;

    dim3 tb(32, 8);
    convWT<<<dim3(32, 16, 1), tb>>>(r1_w1, r1h, r1l, 1024, 512);
    convA<<<8192, 256>>>(x, xbh, xbl, CM * CD, 1.f);
    zero_k<<<8192, 256>>>(out, CM * CD);
    gemv_k<<<CM, 256>>>(x, sp_w, sp_b, imp);
    topk_mask_k<<<CB, 1024>>>(imp, msk);

    tgl(0, 0, xbh, xbl, r1h, r1l, r1_b1, h1, NB, NB, CM, 512, CD, 0, 0, 0, 0, 1, 1.f,
        NP, NP, 0, 0);
    ln_k<1><<<CM, 256>>>(h1, r1_g, r1_be, 512, CM, 0);
    router_k<<<CM, 128>>>(h1, r1_w2, r1_b2, p1, 512, 4);

    convWT<<<dim3(32, 32, 16), tb>>>(w_qkvo, wqh, wql, 1024, 1024);
    convWT<<<dim3(32, 32, 8), tb>>>(sub_w1, s1h, s1l, 1024, 1024);
    convWT<<<dim3(32, 32, 8), tb>>>(sub_w2, s2h, s2l, 1024, 1024);
    convWT<<<dim3(32, 32, 2), tb>>>(fus_w, fwh, fwl, 1024, 1024);
    convWT<<<dim3(32, 32, 1), tb>>>(conv_pw, cwh, cwl, 1024, 1024);
    convWT<<<dim3(32, 8, 4), tb>>>(r2_w1, r2h, r2l, 1024, 256);
    convWT<<<dim3(2, 8, 1), tb>>>(phi_w, phh, phl, 64, 256);
    convWT<<<dim3(2, 8, 1), tb>>>(psi_w, psh, psl, 64, 256);

    for (int i = 0; i < 4; i++) {
        const float* bb = b_qkvo + (size_t)i * 4 * CD;
        tgl(0, 1, xbh, xbl, wqh + (size_t)i * 4194304, wql + (size_t)i * 4194304, bb, q,
            NB, NB, CM, CD, CD, 0, 1048576, 2097152, CD, 3, 1.f, NP, NP, 0, 0);
        const __nv_bfloat16* woh = wqh + (size_t)(i * 4 + 3) * 1048576;
        const __nv_bfloat16* wol = wql + (size_t)(i * 4 + 3) * 1048576;

        if (i == 1) {
            convA<<<8192, 256>>>(q, qhh, qhl, 2097152, 1.f);
            convA<<<8192, 256>>>(k, khh, khl, 2097152, 1.f);
            tgl(1, 0, qhh, qhl, phh, phl, phi_b, qphi, NB, NB, CBH * CS, CKD, CHD,
                0, 0, 0, 0, 1, 1.f, NP, NP, 0, 0);
            tgl(1, 0, khh, khl, psh, psl, psi_b, kpsi, NB, NB, CBH * CS, CKD, CHD,
                0, 0, 0, 0, 1, 1.f, NP, NP, 0, 0);
            gemm_k<64, 64, 16, 4, 4><<<dim3(1, 4, CBH), 256>>>(
                kpsi, v, kv, CKD, CHD, CS, 1, CKD, CHD, 1,
                CS * CKD, CS * CHD, CKD * CHD, 1.f);
            colsum_k<<<CBH, 256>>>(kpsi, ksum);
            gemm_k<64, 64, 16, 4, 4><<<dim3(1, 16, CBH), 256>>>(
                qphi, kv, attn, CS, CHD, CKD, CKD, 1, CHD, 1,
                CS * CKD, CKD * CHD, CS * CHD, 1.f);
            perf_norm_k<<<CBH * CS, 256>>>(attn, qphi, ksum);
            merge_k<<<8192, 256>>>(attn, mrg);
            convA<<<8192, 256>>>(mrg, mgh, mgl, CM * CD, 1.f);
            tgl(0, 0, mgh, mgl, woh, wol, bb + 3 * CD, eo, NB, NB, CM, CD, CD,
                0, 0, 0, 0, 1, 1.f, NP, NP, 0, 0);
        } else {
            convA<<<8192, 256>>>(q, qhh, qhl, 2097152, 0.125f);
            convA<<<8192, 256>>>(k, khh, khl, 2097152, 1.f);
            vtrans_k<<<dim3(32, 2, CBH), tb>>>(v, vth, vtl);
            tgl(0, 0, qhh, qhl, khh, khl, NP, scores, NB, NB, CS, CS, CHD,
                65536, 65536, 1048576, 0, CBH, 1.f, NP, NP, 0, 0);
            softmax_k<<<CBH * CS, 256>>>(scores, (i == 0) ? msk : NP, pbh, pbl);
            tg64_k<<<dim3(1, 8, CBH), 256, TG64_SMEM>>>(
                pbh, pbl, vth, vtl, mgh, mgl, CS, CS, 1048576, 65536);
            if (i == 3) {
                dwconv_k<<<8192, 256>>>(x, conv_dw, cnv);
                convA<<<8192, 256>>>(cnv, cvh, cvl, CM * CD, 1.f);
                tgl(2, 0, cvh, cvl, cwh, cwl, NP, xc, NB, NB, CM, CD, CD,
                    0, 0, 0, 0, 1, 1.f, NP, NP, 0, 0);
                tgl(0, 0, mgh, mgl, woh, wol, bb + 3 * CD, ao, NB, NB, CM, CD, CD,
                    0, 0, 0, 0, 1, 1.f, NP, NP, 0, 0);
                convA<<<8192, 256>>>(ao, aoh, aol, CM * CD, 1.f);
                convA<<<8192, 256>>>(xc, xch, xcl, CM * CD, 1.f);
                tgl(0, 0, aoh, aol, fwh, fwl, fus_b, eo, NB, NB, CM, CD, CD,
                    0, 0, 0, 0, 1, 1.f, NP, NP, 0, 0);
                tgl(0, 2, xch, xcl, fwh + 1048576, fwl + 1048576, NP, eo, NB, NB,
                    CM, CD, CD, 0, 0, 0, 0, 1, 1.f, NP, NP, 0, 0);
            } else {
                tgl(0, 0, mgh, mgl, woh, wol, bb + 3 * CD, eo, NB, NB, CM, CD, CD,
                    0, 0, 0, 0, 1, 1.f, NP, NP, 0, 0);
            }
        }
        convA<<<8192, 256>>>(eo, eoh, eol, CM * CD, 1.f);

        tgl(0, 0, eoh, eol, r2h + (size_t)i * 262144, r2l + (size_t)i * 262144,
            r2_b1 + i * 256, h2, NB, NB, CM, 256, CD, 0, 0, 0, 0, 1, 1.f, NP, NP, 0, 0);
        ln_k<1><<<CM, 256>>>(h2, r2_g + i * 256, r2_be + i * 256, 256, CM, 0);
        router_k<<<CM, 128>>>(h2, r2_w2 + (size_t)i * 512, r2_b2 + i * 2, p2, 256, 2);

        tgl(0, 0, eoh, eol, s1h + (size_t)i * 2097152, s1l + (size_t)i * 2097152,
            sub_b1 + (size_t)i * 2 * CD, t1, NB, NB, CM, CD, CD, 0, 1048576, 2097152,
            CD, 2, 1.f, NP, NP, 0, 0);
        ln_k<2><<<2 * CM, 256>>>(t1, sub_g + (size_t)i * 2 * CD, sub_be + (size_t)i * 2 * CD,
                                 CD, CM, CD);
        convA<<<16384, 256>>>(t1, t1h, t1l, 2 * CM * CD, 1.f);
        for (int j = 0; j < 2; j++) {
            tgl(0, 3, t1h + (size_t)j * 2097152, t1l + (size_t)j * 2097152,
                s2h + (size_t)(i * 2 + j) * 1048576, s2l + (size_t)(i * 2 + j) * 1048576,
                sub_b2 + (size_t)(i * 2 + j) * CD, out, NB, NB, CM, CD, CD,
                0, 0, 0, 0, 1, 1.f, p1, p2, i, j);
        }
    }
}